// round 2
// baseline (speedup 1.0000x reference)
#include <cuda_runtime.h>
#include <math.h>

#define BB 2
#define NN 256
#define FF 64
#define HH 4
#define HIDN 64
#define CC 256
#define KF 50
#define NODES (BB*NN)
#define CUTF 5.0f
#define PI_F 3.14159265358979f

// -------- scratch (device globals; no runtime allocation) --------
__device__ float g_Ain[NODES*KF];     // h[u] @ W_in[0:64]     (u in role j)
__device__ float g_Bin[NODES*KF];     // h[u] @ W_in[64:128]   (u in role i)
__device__ float g_P[NODES*HIDN];     // h[u] @ W_o1[0:64]
__device__ float g_Q[NODES*HIDN];     // h[u] @ W_o1[64:128]
__device__ float g_he[(long)BB*NN*NN*HIDN];   // h_e_mtx  (32 MB)
__device__ float g_attl[(long)BB*NN*NN*HH];   // att logits (post-celu, diag masked)
__device__ float4 g_dx[(long)BB*NN*NN];       // (d, xhat.x, xhat.y, xhat.z)
__device__ float g_hesum[NODES*CC];
__device__ float g_cn[NODES*CC];
__device__ float g_dv[NODES*4];

__device__ __forceinline__ float siluf(float v){ return v/(1.0f+expf(-v)); }

// -------- K1: per-node partial products --------
__global__ void k1_node(const float* __restrict__ h,
                        const float* __restrict__ W_in,
                        const float* __restrict__ W_o1)
{
    int node = blockIdx.x; int t = threadIdx.x;
    __shared__ float sh[FF];
    sh[t] = h[node*FF + t];
    __syncthreads();
    float p = 0.f, q = 0.f;
    #pragma unroll 8
    for (int k = 0; k < FF; k++){
        float hv = sh[k];
        p = fmaf(hv, W_o1[k*HIDN + t], p);
        q = fmaf(hv, W_o1[(FF+k)*HIDN + t], q);
    }
    g_P[node*HIDN + t] = p;
    g_Q[node*HIDN + t] = q;
    if (t < KF){
        float a = 0.f, bv = 0.f;
        #pragma unroll 8
        for (int k = 0; k < FF; k++){
            float hv = sh[k];
            a  = fmaf(hv, W_in[k*KF + t], a);
            bv = fmaf(hv, W_in[(FF+k)*KF + t], bv);
        }
        g_Ain[node*KF + t] = a;
        g_Bin[node*KF + t] = bv;
    }
}

// -------- K2: edge model (per pair), writes h_e_mtx, att logits, d/xhat --------
__global__ __launch_bounds__(256,1) void k2_edge(
    const float* __restrict__ x,
    const float* __restrict__ W_o1, const float* __restrict__ b_o1,
    const float* __restrict__ W_o2, const float* __restrict__ b_o2,
    const float* __restrict__ W_sem, const float* __restrict__ b_sem,
    const float* __restrict__ b_in, const float* __restrict__ means,
    const float* __restrict__ betas)
{
    int b  = blockIdx.z;
    int i0 = blockIdx.y*16, j0 = blockIdx.x*16;
    int t  = threadIdx.x;
    int ti = t >> 4, tj = t & 15;

    __shared__ __align__(16) float sA[16][KF+3];
    __shared__ __align__(16) float sB[16][KF+3];
    __shared__ __align__(16) float sP[16][68];
    __shared__ __align__(16) float sQ[16][68];
    __shared__ float sXi[16][3], sXj[16][3];
    __shared__ __align__(16) float sW1m[KF+1][HIDN];  // W_o1 rows 128..178
    __shared__ __align__(16) float sW2[HIDN][HIDN];
    __shared__ float sWs[HIDN][HH];
    __shared__ float sMean[KF], sBeta[KF], sBinV[KF];
    __shared__ __align__(16) float sBo1[HIDN];
    __shared__ __align__(16) float sBo2[HIDN];
    __shared__ float sBsem[HH];

    for (int idx = t; idx < 16*KF; idx += 256){
        int r = idx / KF, c = idx - r*KF;
        sA[r][c] = g_Ain[(b*NN + j0 + r)*KF + c];
        sB[r][c] = g_Bin[(b*NN + i0 + r)*KF + c];
    }
    for (int idx = t; idx < 16*HIDN; idx += 256){
        int r = idx >> 6, c = idx & 63;
        sP[r][c] = g_P[(b*NN + j0 + r)*HIDN + c];
        sQ[r][c] = g_Q[(b*NN + i0 + r)*HIDN + c];
    }
    if (t < 48){
        int r = t/3, c = t - r*3;
        sXi[r][c] = x[(b*NN + i0 + r)*3 + c];
        sXj[r][c] = x[(b*NN + j0 + r)*3 + c];
    }
    for (int idx = t; idx < (KF+1)*HIDN; idx += 256)
        sW1m[idx>>6][idx&63] = W_o1[(128 + (idx>>6))*HIDN + (idx&63)];
    for (int idx = t; idx < HIDN*HIDN; idx += 256)
        sW2[idx>>6][idx&63] = W_o2[idx];
    if (t < HIDN*HH) sWs[t>>2][t&3] = W_sem[t];
    if (t < KF){ sMean[t] = means[t]; sBeta[t] = betas[t]; sBinV[t] = b_in[t]; }
    if (t < HIDN){ sBo1[t] = b_o1[t]; sBo2[t] = b_o2[t]; }
    if (t < HH) sBsem[t] = b_sem[t];
    __syncthreads();

    int i = i0 + ti, j = j0 + tj;
    float dx = sXj[tj][0] - sXi[ti][0];
    float dy = sXj[tj][1] - sXi[ti][1];
    float dz = sXj[tj][2] - sXi[ti][2];
    float s2 = dx*dx + dy*dy + dz*dz;
    float d  = sqrtf(s2 + 1e-5f);
    float inv = 1.0f / (d + 1e-5f);
    long pair = ((long)(b*NN + i))*NN + j;
    g_dx[pair] = make_float4(d, dx*inv, dy*inv, dz*inv);

    float cutv = (d < CUTF) ? 0.5f*(cosf(d*(PI_F/CUTF)) + 1.0f) : 0.0f;
    float em = expf(-d);   // ALPHA = 1

    float pre[HIDN];
    {
        const float* wd = &sW1m[KF][0];
        #pragma unroll
        for (int f = 0; f < HIDN; f++)
            pre[f] = sP[tj][f] + sQ[ti][f] + sBo1[f] + d*wd[f];
    }
    for (int c = 0; c < KF; c++){
        float h1 = sA[tj][c] + sB[ti][c] + sBinV[c];
        float dm = em - sMean[c];
        float r  = cutv * expf(-sBeta[c]*dm*dm);
        float t2 = r * h1;
        const float4* w4 = (const float4*)&sW1m[c][0];
        #pragma unroll
        for (int q2 = 0; q2 < 16; q2++){
            float4 w = w4[q2];
            pre[4*q2+0] = fmaf(t2, w.x, pre[4*q2+0]);
            pre[4*q2+1] = fmaf(t2, w.y, pre[4*q2+1]);
            pre[4*q2+2] = fmaf(t2, w.z, pre[4*q2+2]);
            pre[4*q2+3] = fmaf(t2, w.w, pre[4*q2+3]);
        }
    }
    float he[HIDN];
    #pragma unroll
    for (int f = 0; f < HIDN; f++) he[f] = sBo2[f];
    #pragma unroll
    for (int k = 0; k < HIDN; k++){
        float a = pre[k];
        a = a / (1.0f + expf(-a));   // silu
        const float4* w4 = (const float4*)&sW2[k][0];
        #pragma unroll
        for (int q2 = 0; q2 < 16; q2++){
            float4 w = w4[q2];
            he[4*q2+0] = fmaf(a, w.x, he[4*q2+0]);
            he[4*q2+1] = fmaf(a, w.y, he[4*q2+1]);
            he[4*q2+2] = fmaf(a, w.z, he[4*q2+2]);
            he[4*q2+3] = fmaf(a, w.w, he[4*q2+3]);
        }
    }
    float4* o = (float4*)&g_he[pair*HIDN];
    #pragma unroll
    for (int q2 = 0; q2 < 16; q2++)
        o[q2] = make_float4(he[4*q2], he[4*q2+1], he[4*q2+2], he[4*q2+3]);

    float av[HH];
    #pragma unroll
    for (int hh = 0; hh < HH; hh++){
        float s = sBsem[hh];
        #pragma unroll
        for (int k = 0; k < HIDN; k++) s = fmaf(he[k], sWs[k][hh], s);
        s = (s > 0.f) ? s : 2.0f*expm1f(0.5f*s);   // celu alpha=2
        if (i == j) s -= 1e5f;
        av[hh] = s;
    }
    *(float4*)&g_attl[pair*HH] = make_float4(av[0], av[1], av[2], av[3]);
}

// -------- K3: per (b,i): softmax over j, h_e_att -> xmix GEMM -> reductions --------
__global__ __launch_bounds__(256) void k3_attn(const float* __restrict__ W_xmix,
                                               const float* __restrict__ W_vmix)
{
    int node = blockIdx.x;           // = b*NN + i
    int t = threadIdx.x;             // owns channel c = t
    __shared__ float4 sAtt[NN];
    __shared__ __align__(16) float sAm[32][CC];
    __shared__ float4 sXh[32];
    __shared__ float4 sRed[256];

    long base = ((long)node)*NN;

    // softmax over j (per head); diag already masked by -1e5
    float4 l = *(const float4*)&g_attl[(base + t)*HH];
    sRed[t] = l;
    __syncthreads();
    for (int s = 128; s; s >>= 1){
        if (t < s){
            float4 o2 = sRed[t+s]; float4 m = sRed[t];
            m.x = fmaxf(m.x,o2.x); m.y = fmaxf(m.y,o2.y);
            m.z = fmaxf(m.z,o2.z); m.w = fmaxf(m.w,o2.w);
            sRed[t] = m;
        }
        __syncthreads();
    }
    float4 mx = sRed[0];
    __syncthreads();
    float4 e = make_float4(expf(l.x-mx.x), expf(l.y-mx.y), expf(l.z-mx.z), expf(l.w-mx.w));
    sRed[t] = e;
    __syncthreads();
    for (int s = 128; s; s >>= 1){
        if (t < s){
            float4 o2 = sRed[t+s]; float4 m = sRed[t];
            m.x += o2.x; m.y += o2.y; m.z += o2.z; m.w += o2.w;
            sRed[t] = m;
        }
        __syncthreads();
    }
    float4 sm = sRed[0];
    __syncthreads();
    sAtt[t] = make_float4(e.x/sm.x, e.y/sm.y, e.z/sm.z, e.w/sm.w);
    __syncthreads();

    int f = t >> 2, hh = t & 3;
    float he_acc = 0.f, cs0 = 0.f, cs1 = 0.f, cs2 = 0.f;

    for (int jc = 0; jc < 8; jc++){
        int jb = jc*32;
        for (int jl = 0; jl < 32; jl++){
            int j = jb + jl;
            float vv = g_he[(base + j)*HIDN + f] * ((const float*)&sAtt[j])[hh];
            sAm[jl][t] = vv;
            he_acc += vv;
        }
        if (t < 32) sXh[t] = g_dx[base + jb + t];
        __syncthreads();

        float acc[32];
        #pragma unroll
        for (int jl = 0; jl < 32; jl++) acc[jl] = 0.f;
        for (int k = 0; k < CC; k += 4){
            float w0 = __ldg(&W_xmix[(k+0)*CC + t]);
            float w1 = __ldg(&W_xmix[(k+1)*CC + t]);
            float w2 = __ldg(&W_xmix[(k+2)*CC + t]);
            float w3 = __ldg(&W_xmix[(k+3)*CC + t]);
            #pragma unroll
            for (int jl = 0; jl < 32; jl++){
                float4 a = *(const float4*)&sAm[jl][k];
                float r = acc[jl];
                r = fmaf(a.x, w0, r); r = fmaf(a.y, w1, r);
                r = fmaf(a.z, w2, r); r = fmaf(a.w, w3, r);
                acc[jl] = r;
            }
        }
        #pragma unroll
        for (int jl = 0; jl < 32; jl++){
            float cf = tanhf(acc[jl]);
            float4 xh = sXh[jl];
            cs0 = fmaf(cf, xh.y, cs0);
            cs1 = fmaf(cf, xh.z, cs1);
            cs2 = fmaf(cf, xh.w, cs2);
        }
        __syncthreads();
    }

    const float invn = 1.0f/(float)NN;
    cs0 *= invn; cs1 *= invn; cs2 *= invn;
    g_hesum[node*CC + t] = he_acc;
    g_cn[node*CC + t] = cs0*cs0 + cs1*cs1 + cs2*cs2;

    float wv = W_vmix[t];
    sRed[t] = make_float4(cs0*wv, cs1*wv, cs2*wv, 0.f);
    __syncthreads();
    for (int s = 128; s; s >>= 1){
        if (t < s){
            float4 o2 = sRed[t+s]; float4 m = sRed[t];
            m.x += o2.x; m.y += o2.y; m.z += o2.z;
            sRed[t] = m;
        }
        __syncthreads();
    }
    if (t == 0){
        float4 r = sRed[0];
        g_dv[node*4+0] = r.x; g_dv[node*4+1] = r.y; g_dv[node*4+2] = r.z;
    }
}

// -------- K4: node MLPs + outputs --------
__global__ void k4_node(
    const float* __restrict__ h, const float* __restrict__ x, const float* __restrict__ v,
    const float* __restrict__ W_p1, const float* __restrict__ b_p1,
    const float* __restrict__ W_p2, const float* __restrict__ b_p2,
    const float* __restrict__ W_n1, const float* __restrict__ b_n1,
    const float* __restrict__ W_n2, const float* __restrict__ b_n2,
    const float* __restrict__ W_v1, const float* __restrict__ b_v1,
    const float* __restrict__ W_v2, float* __restrict__ out)
{
    int node = blockIdx.x; int t = threadIdx.x;
    __shared__ float sh[FF], she[CC], scn[CC], sb1[HIDN], sb2[HIDN], shn[HIDN];
    sh[t] = h[node*FF + t];
    for (int k = t; k < CC; k += HIDN){
        she[k] = g_hesum[node*CC + k];
        scn[k] = g_cn[node*CC + k];
    }
    __syncthreads();
    float a = b_p1[t];
    for (int k = 0; k < CC; k++) a = fmaf(scn[k], W_p1[k*HIDN + t], a);
    a = siluf(a); sb1[t] = a; __syncthreads();
    float hc = b_p2[t];
    for (int k = 0; k < HIDN; k++) hc = fmaf(sb1[k], W_p2[k*HIDN + t], hc);
    hc = siluf(hc); sb2[t] = hc; __syncthreads();
    float n1 = b_n1[t];
    for (int k = 0; k < FF; k++)   n1 = fmaf(sh[k],  W_n1[k*HIDN + t], n1);
    for (int k = 0; k < CC; k++)   n1 = fmaf(she[k], W_n1[(FF+k)*HIDN + t], n1);
    for (int k = 0; k < HIDN; k++) n1 = fmaf(sb2[k], W_n1[(FF+CC+k)*HIDN + t], n1);
    n1 = siluf(n1); sb1[t] = n1; __syncthreads();
    float hn = b_n2[t];
    for (int k = 0; k < HIDN; k++) hn = fmaf(sb1[k], W_n2[k*HIDN + t], hn);
    hn = sh[t] + siluf(hn);
    shn[t] = hn;
    out[node*FF + t] = hn;                  // h_new
    __syncthreads();
    float v1 = b_v1[t];
    for (int k = 0; k < HIDN; k++) v1 = fmaf(shn[k], W_v1[k*HIDN + t], v1);
    v1 = siluf(v1);
    sb1[t] = v1 * W_v2[t];
    __syncthreads();
    for (int s = 32; s; s >>= 1){
        if (t < s) sb1[t] += sb1[t+s];
        __syncthreads();
    }
    if (t < 3){
        float vs = 2.0f/(1.0f + expf(-sb1[0]));
        float vn = g_dv[node*4 + t] + vs * v[node*3 + t];
        out[NODES*FF + node*3 + t]            = x[node*3 + t] + vn;  // x_new
        out[NODES*FF + NODES*3 + node*3 + t]  = vn;                  // v_new
    }
}

extern "C" void kernel_launch(void* const* d_in, const int* in_sizes, int n_in,
                              void* d_out, int out_size)
{
    const float* h      = (const float*)d_in[0];
    const float* x      = (const float*)d_in[1];
    const float* v      = (const float*)d_in[2];
    const float* W_in   = (const float*)d_in[3];
    const float* b_in   = (const float*)d_in[4];
    const float* means  = (const float*)d_in[5];
    const float* betas  = (const float*)d_in[6];
    const float* W_o1   = (const float*)d_in[7];
    const float* b_o1   = (const float*)d_in[8];
    const float* W_o2   = (const float*)d_in[9];
    const float* b_o2   = (const float*)d_in[10];
    const float* W_sem  = (const float*)d_in[11];
    const float* b_sem  = (const float*)d_in[12];
    const float* W_xmix = (const float*)d_in[13];
    const float* W_p1   = (const float*)d_in[14];
    const float* b_p1   = (const float*)d_in[15];
    const float* W_p2   = (const float*)d_in[16];
    const float* b_p2   = (const float*)d_in[17];
    const float* W_n1   = (const float*)d_in[18];
    const float* b_n1   = (const float*)d_in[19];
    const float* W_n2   = (const float*)d_in[20];
    const float* b_n2   = (const float*)d_in[21];
    const float* W_v1   = (const float*)d_in[22];
    const float* b_v1   = (const float*)d_in[23];
    const float* W_v2   = (const float*)d_in[24];
    const float* W_vmix = (const float*)d_in[25];
    float* out = (float*)d_out;

    k1_node<<<NODES, 64>>>(h, W_in, W_o1);
    dim3 g2(NN/16, NN/16, BB);
    k2_edge<<<g2, 256>>>(x, W_o1, b_o1, W_o2, b_o2, W_sem, b_sem, b_in, means, betas);
    k3_attn<<<NODES, 256>>>(W_xmix, W_vmix);
    k4_node<<<NODES, 64>>>(h, x, v, W_p1, b_p1, W_p2, b_p2,
                           W_n1, b_n1, W_n2, b_n2, W_v1, b_v1, W_v2, out);
}

// round 4
// speedup vs baseline: 3.5319x; 3.5319x over previous
#include <cuda_runtime.h>
#include <math.h>

#define BB 2
#define NN 256
#define FF 64
#define HH 4
#define HIDN 64
#define CC 256
#define KF 50
#define NODES (BB*NN)
#define CUTF 5.0f
#define PI_F 3.14159265358979f

// -------- scratch (device globals; no runtime allocation) --------
__device__ float g_Ain[NODES*KF];
__device__ float g_Bin[NODES*KF];
__device__ float g_P[NODES*HIDN];
__device__ float g_Q[NODES*HIDN];
__device__ float g_he[(long)BB*NN*NN*HIDN];   // h_e_mtx (32 MB)
__device__ float g_attl[(long)BB*NN*NN*HH];   // att logits
__device__ float4 g_dx[(long)BB*NN*NN];       // (d, xhat)
__device__ float g_hesum[NODES*CC];
__device__ float g_cn[NODES*CC];
__device__ float g_dv[NODES*4];
// W_xmix^T bf16 pairs: g_Wt[c'*128 + cpair], low half = even c
__device__ unsigned int g_Wt[256*128];

__device__ __forceinline__ float siluf(float v){ return v/(1.0f+expf(-v)); }

__device__ __forceinline__ unsigned int pack_bf2(float lo, float hi){
    unsigned int r;
    asm("cvt.rn.bf16x2.f32 %0, %1, %2;" : "=r"(r) : "f"(hi), "f"(lo));
    return r;
}
__device__ __forceinline__ unsigned int smem_u32(const void* p){
    unsigned int a;
    asm("{ .reg .u64 t; cvta.to.shared.u64 t, %1; cvt.u32.u64 %0, t; }" : "=r"(a) : "l"(p));
    return a;
}
__device__ __forceinline__ float tanhfast(float x){
    float r; asm("tanh.approx.f32 %0, %1;" : "=f"(r) : "f"(x)); return r;
}
#define LDSM_X4(R, addr) \
    asm volatile("ldmatrix.sync.aligned.m8n8.x4.shared.b16 {%0,%1,%2,%3}, [%4];" \
        : "=r"((R)[0]),"=r"((R)[1]),"=r"((R)[2]),"=r"((R)[3]) : "r"(addr))
#define LDSM_X2(R, addr) \
    asm volatile("ldmatrix.sync.aligned.m8n8.x2.shared.b16 {%0,%1}, [%2];" \
        : "=r"((R)[0]),"=r"((R)[1]) : "r"(addr))
#define MMA16816(D, A, B0, B1) \
    asm volatile("mma.sync.aligned.m16n8k16.row.col.f32.bf16.bf16.f32 " \
        "{%0,%1,%2,%3}, {%4,%5,%6,%7}, {%8,%9}, {%0,%1,%2,%3};" \
        : "+f"((D)[0]),"+f"((D)[1]),"+f"((D)[2]),"+f"((D)[3]) \
        : "r"((A)[0]),"r"((A)[1]),"r"((A)[2]),"r"((A)[3]),"r"(B0),"r"(B1))

// -------- K0: build W_xmix^T bf16 pairs --------
__global__ void k0_wt(const float* __restrict__ W){
    int c1 = threadIdx.x;          // c'
    int cp = blockIdx.x;           // c pair
    float v0 = W[(2*cp  )*CC + c1];
    float v1 = W[(2*cp+1)*CC + c1];
    g_Wt[c1*128 + cp] = pack_bf2(v0, v1);
}

// -------- K1: per-node partial products --------
__global__ void k1_node(const float* __restrict__ h,
                        const float* __restrict__ W_in,
                        const float* __restrict__ W_o1)
{
    int node = blockIdx.x; int t = threadIdx.x;
    __shared__ float sh[FF];
    sh[t] = h[node*FF + t];
    __syncthreads();
    float p = 0.f, q = 0.f;
    #pragma unroll 8
    for (int k = 0; k < FF; k++){
        float hv = sh[k];
        p = fmaf(hv, W_o1[k*HIDN + t], p);
        q = fmaf(hv, W_o1[(FF+k)*HIDN + t], q);
    }
    g_P[node*HIDN + t] = p;
    g_Q[node*HIDN + t] = q;
    if (t < KF){
        float a = 0.f, bv = 0.f;
        #pragma unroll 8
        for (int k = 0; k < FF; k++){
            float hv = sh[k];
            a  = fmaf(hv, W_in[k*KF + t], a);
            bv = fmaf(hv, W_in[(FF+k)*KF + t], bv);
        }
        g_Ain[node*KF + t] = a;
        g_Bin[node*KF + t] = bv;
    }
}

// -------- K2: edge model --------
__global__ __launch_bounds__(256,1) void k2_edge(
    const float* __restrict__ x,
    const float* __restrict__ W_o1, const float* __restrict__ b_o1,
    const float* __restrict__ W_o2, const float* __restrict__ b_o2,
    const float* __restrict__ W_sem, const float* __restrict__ b_sem,
    const float* __restrict__ b_in, const float* __restrict__ means,
    const float* __restrict__ betas)
{
    int b  = blockIdx.z;
    int i0 = blockIdx.y*16, j0 = blockIdx.x*16;
    int t  = threadIdx.x;
    int ti = t >> 4, tj = t & 15;

    __shared__ __align__(16) float sA[16][KF+3];
    __shared__ __align__(16) float sB[16][KF+3];
    __shared__ __align__(16) float sP[16][68];
    __shared__ __align__(16) float sQ[16][68];
    __shared__ float sXi[16][3], sXj[16][3];
    __shared__ __align__(16) float sW1m[KF+1][HIDN];
    __shared__ __align__(16) float sW2[HIDN][HIDN];
    __shared__ float sWs[HIDN][HH];
    __shared__ float sMean[KF], sBeta[KF], sBinV[KF];
    __shared__ __align__(16) float sBo1[HIDN];
    __shared__ __align__(16) float sBo2[HIDN];
    __shared__ float sBsem[HH];

    for (int idx = t; idx < 16*KF; idx += 256){
        int r = idx / KF, c = idx - r*KF;
        sA[r][c] = g_Ain[(b*NN + j0 + r)*KF + c];
        sB[r][c] = g_Bin[(b*NN + i0 + r)*KF + c];
    }
    for (int idx = t; idx < 16*HIDN; idx += 256){
        int r = idx >> 6, c = idx & 63;
        sP[r][c] = g_P[(b*NN + j0 + r)*HIDN + c];
        sQ[r][c] = g_Q[(b*NN + i0 + r)*HIDN + c];
    }
    if (t < 48){
        int r = t/3, c = t - r*3;
        sXi[r][c] = x[(b*NN + i0 + r)*3 + c];
        sXj[r][c] = x[(b*NN + j0 + r)*3 + c];
    }
    for (int idx = t; idx < (KF+1)*HIDN; idx += 256)
        sW1m[idx>>6][idx&63] = W_o1[(128 + (idx>>6))*HIDN + (idx&63)];
    for (int idx = t; idx < HIDN*HIDN; idx += 256)
        sW2[idx>>6][idx&63] = W_o2[idx];
    if (t < HIDN*HH) sWs[t>>2][t&3] = W_sem[t];
    if (t < KF){ sMean[t] = means[t]; sBeta[t] = betas[t]; sBinV[t] = b_in[t]; }
    if (t < HIDN){ sBo1[t] = b_o1[t]; sBo2[t] = b_o2[t]; }
    if (t < HH) sBsem[t] = b_sem[t];
    __syncthreads();

    int i = i0 + ti, j = j0 + tj;
    float dx = sXj[tj][0] - sXi[ti][0];
    float dy = sXj[tj][1] - sXi[ti][1];
    float dz = sXj[tj][2] - sXi[ti][2];
    float s2 = dx*dx + dy*dy + dz*dz;
    float d  = sqrtf(s2 + 1e-5f);
    float inv = 1.0f / (d + 1e-5f);
    long pair = ((long)(b*NN + i))*NN + j;
    g_dx[pair] = make_float4(d, dx*inv, dy*inv, dz*inv);

    float cutv = (d < CUTF) ? 0.5f*(cosf(d*(PI_F/CUTF)) + 1.0f) : 0.0f;
    float em = expf(-d);

    float pre[HIDN];
    {
        const float* wd = &sW1m[KF][0];
        #pragma unroll
        for (int f = 0; f < HIDN; f++)
            pre[f] = sP[tj][f] + sQ[ti][f] + sBo1[f] + d*wd[f];
    }
    for (int c = 0; c < KF; c++){
        float h1 = sA[tj][c] + sB[ti][c] + sBinV[c];
        float dm = em - sMean[c];
        float r  = cutv * expf(-sBeta[c]*dm*dm);
        float t2 = r * h1;
        const float4* w4 = (const float4*)&sW1m[c][0];
        #pragma unroll
        for (int q2 = 0; q2 < 16; q2++){
            float4 w = w4[q2];
            pre[4*q2+0] = fmaf(t2, w.x, pre[4*q2+0]);
            pre[4*q2+1] = fmaf(t2, w.y, pre[4*q2+1]);
            pre[4*q2+2] = fmaf(t2, w.z, pre[4*q2+2]);
            pre[4*q2+3] = fmaf(t2, w.w, pre[4*q2+3]);
        }
    }
    float he[HIDN];
    #pragma unroll
    for (int f = 0; f < HIDN; f++) he[f] = sBo2[f];
    #pragma unroll
    for (int k = 0; k < HIDN; k++){
        float a = pre[k];
        a = a / (1.0f + expf(-a));
        const float4* w4 = (const float4*)&sW2[k][0];
        #pragma unroll
        for (int q2 = 0; q2 < 16; q2++){
            float4 w = w4[q2];
            he[4*q2+0] = fmaf(a, w.x, he[4*q2+0]);
            he[4*q2+1] = fmaf(a, w.y, he[4*q2+1]);
            he[4*q2+2] = fmaf(a, w.z, he[4*q2+2]);
            he[4*q2+3] = fmaf(a, w.w, he[4*q2+3]);
        }
    }
    float4* o = (float4*)&g_he[pair*HIDN];
    #pragma unroll
    for (int q2 = 0; q2 < 16; q2++)
        o[q2] = make_float4(he[4*q2], he[4*q2+1], he[4*q2+2], he[4*q2+3]);

    float av[HH];
    #pragma unroll
    for (int hh = 0; hh < HH; hh++){
        float s = sBsem[hh];
        #pragma unroll
        for (int k = 0; k < HIDN; k++) s = fmaf(he[k], sWs[k][hh], s);
        s = (s > 0.f) ? s : 2.0f*expm1f(0.5f*s);
        if (i == j) s -= 1e5f;
        av[hh] = s;
    }
    *(float4*)&g_attl[pair*HH] = make_float4(av[0], av[1], av[2], av[3]);
}

// -------- K3: HMMA (mma.sync bf16) xmix GEMM + epilogue --------
// SMEM: rows padded to 528 B (132 words) for conflict-free ldmatrix
#define WROW 528
#define OFF_WT  0u                     // 256 * 528 = 135168
#define OFF_B   135168u                // 64 * 528 = 33792
#define OFF_ATT 168960u                // float4[256]
#define OFF_XH  173056u                // float4[256]
#define OFF_RED 177152u                // float4[256]
#define OFF_HEP 181248u                // float[512]
#define K3_SMEM 183296u

__global__ __launch_bounds__(256,1) void k3_attn(const float* __restrict__ W_vmix)
{
    extern __shared__ char smem[];
    unsigned int sbase = smem_u32(smem);
    float4* sAtt = (float4*)(smem + OFF_ATT);
    float4* sXh  = (float4*)(smem + OFF_XH);
    float4* sRed = (float4*)(smem + OFF_RED);
    float*  sHeP = (float*)(smem + OFF_HEP);

    int node = blockIdx.x;
    int t = threadIdx.x;
    long base = ((long)node)*NN;

    // ---- softmax over j (per head) ----
    float4 l = *(const float4*)&g_attl[(base + t)*HH];
    sRed[t] = l;
    sXh[t] = g_dx[base + t];
    __syncthreads();
    for (int s = 128; s; s >>= 1){
        if (t < s){
            float4 o2 = sRed[t+s]; float4 m = sRed[t];
            m.x = fmaxf(m.x,o2.x); m.y = fmaxf(m.y,o2.y);
            m.z = fmaxf(m.z,o2.z); m.w = fmaxf(m.w,o2.w);
            sRed[t] = m;
        }
        __syncthreads();
    }
    float4 mx = sRed[0];
    __syncthreads();
    float4 e = make_float4(expf(l.x-mx.x), expf(l.y-mx.y), expf(l.z-mx.z), expf(l.w-mx.w));
    sRed[t] = e;
    __syncthreads();
    for (int s = 128; s; s >>= 1){
        if (t < s){
            float4 o2 = sRed[t+s]; float4 m = sRed[t];
            m.x += o2.x; m.y += o2.y; m.z += o2.z; m.w += o2.w;
            sRed[t] = m;
        }
        __syncthreads();
    }
    float4 sm = sRed[0];
    __syncthreads();
    sAtt[t] = make_float4(e.x/sm.x, e.y/sm.y, e.z/sm.z, e.w/sm.w);

    // ---- copy Wt into padded SMEM (uint4) ----
    {
        const uint4* src = (const uint4*)g_Wt;
        for (int idx = t; idx < 8192; idx += 256){
            int r = idx >> 5, c4 = idx & 31;
            *(uint4*)(smem + OFF_WT + r*WROW + c4*16) = src[idx];
        }
    }
    __syncthreads();

    int lane = t & 31, warp = t >> 5;
    int g = lane >> 2, tig = lane & 3;
    unsigned int aBase = sbase + OFF_WT + (unsigned)(warp*32 + (lane & 15))*WROW
                       + (unsigned)((lane >> 4)*16);
    unsigned int bBase = sbase + OFF_B + (unsigned)((lane & 7))*WROW
                       + (unsigned)(((lane >> 3) & 1)*16);

    float cs[2][2][3];
    #pragma unroll
    for (int m = 0; m < 2; m++)
        #pragma unroll
        for (int r = 0; r < 2; r++)
            cs[m][r][0] = cs[m][r][1] = cs[m][r][2] = 0.f;
    float heS0 = 0.f, heS1 = 0.f;

    int cp = t & 127, jh = t >> 7;
    int fch = cp >> 1;
    int h0 = (2*cp) & 3, h1 = h0 + 1;

    for (int jb = 0; jb < 4; jb++){
        // build B tile: 64 j-rows x 256 c (bf16 pairs), he_sum partials
        #pragma unroll 4
        for (int jj = 0; jj < 32; jj++){
            int jl = jh*32 + jj;
            int j  = jb*64 + jl;
            float hev = g_he[(base + j)*HIDN + fch];
            float4 a4 = sAtt[j];
            float v0 = hev * ((const float*)&a4)[h0];
            float v1 = hev * ((const float*)&a4)[h1];
            heS0 += v0; heS1 += v1;
            *(unsigned int*)(smem + OFF_B + jl*WROW + cp*4) = pack_bf2(v0, v1);
        }
        __syncthreads();

        float d[64];
        #pragma unroll
        for (int q = 0; q < 64; q++) d[q] = 0.f;

        #pragma unroll 4
        for (int k = 0; k < 16; k++){
            unsigned int a0[4], a1[4];
            unsigned int ak = aBase + (unsigned)(k*32);
            LDSM_X4(a0, ak);
            LDSM_X4(a1, ak + 16*WROW);
            #pragma unroll
            for (int n = 0; n < 8; n++){
                unsigned int bfr[2];
                LDSM_X2(bfr, bBase + (unsigned)(n*8*WROW + k*32));
                MMA16816(d + n*4,      a0, bfr[0], bfr[1]);
                MMA16816(d + 32 + n*4, a1, bfr[0], bfr[1]);
            }
        }

        // epilogue: tanh + cs accumulation
        #pragma unroll
        for (int m = 0; m < 2; m++){
            #pragma unroll
            for (int n = 0; n < 8; n++){
                int j0 = jb*64 + n*8 + tig*2;
                float4 x0 = sXh[j0], x1 = sXh[j0+1];
                float t0 = tanhfast(d[m*32+n*4+0]);
                float t1 = tanhfast(d[m*32+n*4+1]);
                float t2 = tanhfast(d[m*32+n*4+2]);
                float t3 = tanhfast(d[m*32+n*4+3]);
                cs[m][0][0] = fmaf(t0, x0.y, fmaf(t1, x1.y, cs[m][0][0]));
                cs[m][0][1] = fmaf(t0, x0.z, fmaf(t1, x1.z, cs[m][0][1]));
                cs[m][0][2] = fmaf(t0, x0.w, fmaf(t1, x1.w, cs[m][0][2]));
                cs[m][1][0] = fmaf(t2, x0.y, fmaf(t3, x1.y, cs[m][1][0]));
                cs[m][1][1] = fmaf(t2, x0.z, fmaf(t3, x1.z, cs[m][1][1]));
                cs[m][1][2] = fmaf(t2, x0.w, fmaf(t3, x1.w, cs[m][1][2]));
            }
        }
        __syncthreads();
    }

    // he_sum write
    sHeP[jh*256 + 2*cp    ] = heS0;
    sHeP[jh*256 + 2*cp + 1] = heS1;

    // reduce cs over the quad (lanes with same g share c' rows)
    #pragma unroll
    for (int m = 0; m < 2; m++)
        #pragma unroll
        for (int r = 0; r < 2; r++)
            #pragma unroll
            for (int q = 0; q < 3; q++){
                float v = cs[m][r][q];
                v += __shfl_xor_sync(0xFFFFFFFFu, v, 1);
                v += __shfl_xor_sync(0xFFFFFFFFu, v, 2);
                cs[m][r][q] = v;
            }

    const float invn = 1.0f/(float)NN;
    float pd0 = 0.f, pd1 = 0.f, pd2 = 0.f;
    if (tig == 0){
        #pragma unroll
        for (int m = 0; m < 2; m++){
            #pragma unroll
            for (int r = 0; r < 2; r++){
                int cpr = warp*32 + m*16 + r*8 + g;
                float a = cs[m][r][0]*invn;
                float b2 = cs[m][r][1]*invn;
                float c2 = cs[m][r][2]*invn;
                g_cn[node*CC + cpr] = a*a + b2*b2 + c2*c2;
                float wv = W_vmix[cpr];
                pd0 = fmaf(a, wv, pd0);
                pd1 = fmaf(b2, wv, pd1);
                pd2 = fmaf(c2, wv, pd2);
            }
        }
    }
    __syncthreads();
    g_hesum[node*CC + t] = sHeP[t] + sHeP[256 + t];
    sRed[t] = make_float4(pd0, pd1, pd2, 0.f);
    __syncthreads();
    for (int s = 128; s; s >>= 1){
        if (t < s){
            float4 o2 = sRed[t+s]; float4 m2 = sRed[t];
            m2.x += o2.x; m2.y += o2.y; m2.z += o2.z;
            sRed[t] = m2;
        }
        __syncthreads();
    }
    if (t == 0){
        float4 r = sRed[0];
        g_dv[node*4+0] = r.x; g_dv[node*4+1] = r.y; g_dv[node*4+2] = r.z;
    }
}

// -------- K4: node MLPs + outputs --------
__global__ void k4_node(
    const float* __restrict__ h, const float* __restrict__ x, const float* __restrict__ v,
    const float* __restrict__ W_p1, const float* __restrict__ b_p1,
    const float* __restrict__ W_p2, const float* __restrict__ b_p2,
    const float* __restrict__ W_n1, const float* __restrict__ b_n1,
    const float* __restrict__ W_n2, const float* __restrict__ b_n2,
    const float* __restrict__ W_v1, const float* __restrict__ b_v1,
    const float* __restrict__ W_v2, float* __restrict__ out)
{
    int node = blockIdx.x; int t = threadIdx.x;
    __shared__ float sh[FF], she[CC], scn[CC], sb1[HIDN], sb2[HIDN], shn[HIDN];
    sh[t] = h[node*FF + t];
    for (int k = t; k < CC; k += HIDN){
        she[k] = g_hesum[node*CC + k];
        scn[k] = g_cn[node*CC + k];
    }
    __syncthreads();
    float a = b_p1[t];
    for (int k = 0; k < CC; k++) a = fmaf(scn[k], W_p1[k*HIDN + t], a);
    a = siluf(a); sb1[t] = a; __syncthreads();
    float hc = b_p2[t];
    for (int k = 0; k < HIDN; k++) hc = fmaf(sb1[k], W_p2[k*HIDN + t], hc);
    hc = siluf(hc); sb2[t] = hc; __syncthreads();
    float n1 = b_n1[t];
    for (int k = 0; k < FF; k++)   n1 = fmaf(sh[k],  W_n1[k*HIDN + t], n1);
    for (int k = 0; k < CC; k++)   n1 = fmaf(she[k], W_n1[(FF+k)*HIDN + t], n1);
    for (int k = 0; k < HIDN; k++) n1 = fmaf(sb2[k], W_n1[(FF+CC+k)*HIDN + t], n1);
    n1 = siluf(n1); sb1[t] = n1; __syncthreads();
    float hn = b_n2[t];
    for (int k = 0; k < HIDN; k++) hn = fmaf(sb1[k], W_n2[k*HIDN + t], hn);
    hn = sh[t] + siluf(hn);
    shn[t] = hn;
    out[node*FF + t] = hn;
    __syncthreads();
    float v1 = b_v1[t];
    for (int k = 0; k < HIDN; k++) v1 = fmaf(shn[k], W_v1[k*HIDN + t], v1);
    v1 = siluf(v1);
    sb1[t] = v1 * W_v2[t];
    __syncthreads();
    for (int s = 32; s; s >>= 1){
        if (t < s) sb1[t] += sb1[t+s];
        __syncthreads();
    }
    if (t < 3){
        float vs = 2.0f/(1.0f + expf(-sb1[0]));
        float vn = g_dv[node*4 + t] + vs * v[node*3 + t];
        out[NODES*FF + node*3 + t]            = x[node*3 + t] + vn;
        out[NODES*FF + NODES*3 + node*3 + t]  = vn;
    }
}

extern "C" void kernel_launch(void* const* d_in, const int* in_sizes, int n_in,
                              void* d_out, int out_size)
{
    const float* h      = (const float*)d_in[0];
    const float* x      = (const float*)d_in[1];
    const float* v      = (const float*)d_in[2];
    const float* W_in   = (const float*)d_in[3];
    const float* b_in   = (const float*)d_in[4];
    const float* means  = (const float*)d_in[5];
    const float* betas  = (const float*)d_in[6];
    const float* W_o1   = (const float*)d_in[7];
    const float* b_o1   = (const float*)d_in[8];
    const float* W_o2   = (const float*)d_in[9];
    const float* b_o2   = (const float*)d_in[10];
    const float* W_sem  = (const float*)d_in[11];
    const float* b_sem  = (const float*)d_in[12];
    const float* W_xmix = (const float*)d_in[13];
    const float* W_p1   = (const float*)d_in[14];
    const float* b_p1   = (const float*)d_in[15];
    const float* W_p2   = (const float*)d_in[16];
    const float* b_p2   = (const float*)d_in[17];
    const float* W_n1   = (const float*)d_in[18];
    const float* b_n1   = (const float*)d_in[19];
    const float* W_n2   = (const float*)d_in[20];
    const float* b_n2   = (const float*)d_in[21];
    const float* W_v1   = (const float*)d_in[22];
    const float* b_v1   = (const float*)d_in[23];
    const float* W_v2   = (const float*)d_in[24];
    const float* W_vmix = (const float*)d_in[25];
    float* out = (float*)d_out;

    static int smem_set = 0;
    if (!smem_set){
        cudaFuncSetAttribute(k3_attn, cudaFuncAttributeMaxDynamicSharedMemorySize, K3_SMEM);
        smem_set = 1;
    }

    k0_wt<<<128, 256>>>(W_xmix);
    k1_node<<<NODES, 64>>>(h, W_in, W_o1);
    dim3 g2(NN/16, NN/16, BB);
    k2_edge<<<g2, 256>>>(x, W_o1, b_o1, W_o2, b_o2, W_sem, b_sem, b_in, means, betas);
    k3_attn<<<NODES, 256, K3_SMEM>>>(W_vmix);
    k4_node<<<NODES, 64>>>(h, x, v, W_p1, b_p1, W_p2, b_p2,
                           W_n1, b_n1, W_n2, b_n2, W_v1, b_v1, W_v2, out);
}

// round 5
// speedup vs baseline: 3.6511x; 1.0338x over previous
#include <cuda_runtime.h>
#include <math.h>

#define BB 2
#define NN 256
#define FF 64
#define HH 4
#define HIDN 64
#define CC 256
#define KF 50
#define NODES (BB*NN)
#define CUTF 5.0f
#define PI_F 3.14159265358979f

// -------- scratch (device globals; no runtime allocation) --------
__device__ float g_Ain[NODES*KF];
__device__ float g_Bin[NODES*KF];
__device__ float g_P[NODES*HIDN];
__device__ float g_Q[NODES*HIDN];
__device__ float g_he[(long)BB*NN*NN*HIDN];   // h_e_mtx (32 MB)
__device__ float g_attl[(long)BB*NN*NN*HH];   // att logits
__device__ float4 g_dx[(long)BB*NN*NN];       // (d, xhat)
__device__ float g_hesum[NODES*CC];
__device__ float g_cn[NODES*CC];
__device__ float g_dvp[NODES*8];              // dv partials (2 halves)
// W_xmix^T in per-lane mma fragment layout: [mt 0..15][k 0..15][lane 0..31] uint4
__device__ uint4 g_WtF[8192];

__device__ __forceinline__ float siluf(float v){ return v/(1.0f+expf(-v)); }

__device__ __forceinline__ unsigned int pack_bf2(float lo, float hi){
    unsigned int r;
    asm("cvt.rn.bf16x2.f32 %0, %1, %2;" : "=r"(r) : "f"(hi), "f"(lo));
    return r;
}
__device__ __forceinline__ unsigned int smem_u32(const void* p){
    unsigned int a;
    asm("{ .reg .u64 t; cvta.to.shared.u64 t, %1; cvt.u32.u64 %0, t; }" : "=r"(a) : "l"(p));
    return a;
}
__device__ __forceinline__ float tanhfast(float x){
    float r; asm("tanh.approx.f32 %0, %1;" : "=f"(r) : "f"(x)); return r;
}
#define LDSM_X2(R, addr) \
    asm volatile("ldmatrix.sync.aligned.m8n8.x2.shared.b16 {%0,%1}, [%2];" \
        : "=r"((R)[0]),"=r"((R)[1]) : "r"(addr))
#define MMA16816(D, A, B0, B1) \
    asm volatile("mma.sync.aligned.m16n8k16.row.col.f32.bf16.bf16.f32 " \
        "{%0,%1,%2,%3}, {%4,%5,%6,%7}, {%8,%9}, {%0,%1,%2,%3};" \
        : "+f"((D)[0]),"+f"((D)[1]),"+f"((D)[2]),"+f"((D)[3]) \
        : "r"((A)[0]),"r"((A)[1]),"r"((A)[2]),"r"((A)[3]),"r"(B0),"r"(B1))

// -------- K0: W_xmix^T bf16 in mma fragment layout --------
__global__ void k0_wt(const float* __restrict__ W){
    int idx = blockIdx.x*256 + threadIdx.x;   // 0..8191
    int lane = idx & 31;
    int k = (idx >> 5) & 15;
    int mt = idx >> 9;
    int g = lane >> 2, tig = lane & 3;
    int r0 = mt*16 + g, r1 = r0 + 8;
    int cp0 = k*8 + tig, cp1 = cp0 + 4;
    uint4 f;
    f.x = pack_bf2(W[(2*cp0)*CC + r0], W[(2*cp0+1)*CC + r0]);
    f.y = pack_bf2(W[(2*cp0)*CC + r1], W[(2*cp0+1)*CC + r1]);
    f.z = pack_bf2(W[(2*cp1)*CC + r0], W[(2*cp1+1)*CC + r0]);
    f.w = pack_bf2(W[(2*cp1)*CC + r1], W[(2*cp1+1)*CC + r1]);
    g_WtF[idx] = f;
}

// -------- K1: per-node partial products --------
__global__ void k1_node(const float* __restrict__ h,
                        const float* __restrict__ W_in,
                        const float* __restrict__ W_o1)
{
    int node = blockIdx.x; int t = threadIdx.x;
    __shared__ float sh[FF];
    sh[t] = h[node*FF + t];
    __syncthreads();
    float p = 0.f, q = 0.f;
    #pragma unroll 8
    for (int k = 0; k < FF; k++){
        float hv = sh[k];
        p = fmaf(hv, W_o1[k*HIDN + t], p);
        q = fmaf(hv, W_o1[(FF+k)*HIDN + t], q);
    }
    g_P[node*HIDN + t] = p;
    g_Q[node*HIDN + t] = q;
    if (t < KF){
        float a = 0.f, bv = 0.f;
        #pragma unroll 8
        for (int k = 0; k < FF; k++){
            float hv = sh[k];
            a  = fmaf(hv, W_in[k*KF + t], a);
            bv = fmaf(hv, W_in[(FF+k)*KF + t], bv);
        }
        g_Ain[node*KF + t] = a;
        g_Bin[node*KF + t] = bv;
    }
}

// -------- K2: edge model --------
__global__ __launch_bounds__(256,1) void k2_edge(
    const float* __restrict__ x,
    const float* __restrict__ W_o1, const float* __restrict__ b_o1,
    const float* __restrict__ W_o2, const float* __restrict__ b_o2,
    const float* __restrict__ W_sem, const float* __restrict__ b_sem,
    const float* __restrict__ b_in, const float* __restrict__ means,
    const float* __restrict__ betas)
{
    int b  = blockIdx.z;
    int i0 = blockIdx.y*16, j0 = blockIdx.x*16;
    int t  = threadIdx.x;
    int ti = t >> 4, tj = t & 15;

    __shared__ __align__(16) float sA[16][KF+3];
    __shared__ __align__(16) float sB[16][KF+3];
    __shared__ __align__(16) float sP[16][68];
    __shared__ __align__(16) float sQ[16][68];
    __shared__ float sXi[16][3], sXj[16][3];
    __shared__ __align__(16) float sW1m[KF+1][HIDN];
    __shared__ __align__(16) float sW2[HIDN][HIDN];
    __shared__ float sWs[HIDN][HH];
    __shared__ float sMean[KF], sBeta[KF], sBinV[KF];
    __shared__ __align__(16) float sBo1[HIDN];
    __shared__ __align__(16) float sBo2[HIDN];
    __shared__ float sBsem[HH];

    for (int idx = t; idx < 16*KF; idx += 256){
        int r = idx / KF, c = idx - r*KF;
        sA[r][c] = g_Ain[(b*NN + j0 + r)*KF + c];
        sB[r][c] = g_Bin[(b*NN + i0 + r)*KF + c];
    }
    for (int idx = t; idx < 16*HIDN; idx += 256){
        int r = idx >> 6, c = idx & 63;
        sP[r][c] = g_P[(b*NN + j0 + r)*HIDN + c];
        sQ[r][c] = g_Q[(b*NN + i0 + r)*HIDN + c];
    }
    if (t < 48){
        int r = t/3, c = t - r*3;
        sXi[r][c] = x[(b*NN + i0 + r)*3 + c];
        sXj[r][c] = x[(b*NN + j0 + r)*3 + c];
    }
    for (int idx = t; idx < (KF+1)*HIDN; idx += 256)
        sW1m[idx>>6][idx&63] = W_o1[(128 + (idx>>6))*HIDN + (idx&63)];
    for (int idx = t; idx < HIDN*HIDN; idx += 256)
        sW2[idx>>6][idx&63] = W_o2[idx];
    if (t < HIDN*HH) sWs[t>>2][t&3] = W_sem[t];
    if (t < KF){ sMean[t] = means[t]; sBeta[t] = betas[t]; sBinV[t] = b_in[t]; }
    if (t < HIDN){ sBo1[t] = b_o1[t]; sBo2[t] = b_o2[t]; }
    if (t < HH) sBsem[t] = b_sem[t];
    __syncthreads();

    int i = i0 + ti, j = j0 + tj;
    float dx = sXj[tj][0] - sXi[ti][0];
    float dy = sXj[tj][1] - sXi[ti][1];
    float dz = sXj[tj][2] - sXi[ti][2];
    float s2 = dx*dx + dy*dy + dz*dz;
    float d  = sqrtf(s2 + 1e-5f);
    float inv = 1.0f / (d + 1e-5f);
    long pair = ((long)(b*NN + i))*NN + j;
    g_dx[pair] = make_float4(d, dx*inv, dy*inv, dz*inv);

    float cutv = (d < CUTF) ? 0.5f*(cosf(d*(PI_F/CUTF)) + 1.0f) : 0.0f;
    float em = expf(-d);

    float pre[HIDN];
    {
        const float* wd = &sW1m[KF][0];
        #pragma unroll
        for (int f = 0; f < HIDN; f++)
            pre[f] = sP[tj][f] + sQ[ti][f] + sBo1[f] + d*wd[f];
    }
    for (int c = 0; c < KF; c++){
        float h1 = sA[tj][c] + sB[ti][c] + sBinV[c];
        float dm = em - sMean[c];
        float r  = cutv * expf(-sBeta[c]*dm*dm);
        float t2 = r * h1;
        const float4* w4 = (const float4*)&sW1m[c][0];
        #pragma unroll
        for (int q2 = 0; q2 < 16; q2++){
            float4 w = w4[q2];
            pre[4*q2+0] = fmaf(t2, w.x, pre[4*q2+0]);
            pre[4*q2+1] = fmaf(t2, w.y, pre[4*q2+1]);
            pre[4*q2+2] = fmaf(t2, w.z, pre[4*q2+2]);
            pre[4*q2+3] = fmaf(t2, w.w, pre[4*q2+3]);
        }
    }
    float he[HIDN];
    #pragma unroll
    for (int f = 0; f < HIDN; f++) he[f] = sBo2[f];
    #pragma unroll
    for (int k = 0; k < HIDN; k++){
        float a = pre[k];
        a = a / (1.0f + expf(-a));
        const float4* w4 = (const float4*)&sW2[k][0];
        #pragma unroll
        for (int q2 = 0; q2 < 16; q2++){
            float4 w = w4[q2];
            he[4*q2+0] = fmaf(a, w.x, he[4*q2+0]);
            he[4*q2+1] = fmaf(a, w.y, he[4*q2+1]);
            he[4*q2+2] = fmaf(a, w.z, he[4*q2+2]);
            he[4*q2+3] = fmaf(a, w.w, he[4*q2+3]);
        }
    }
    float4* o = (float4*)&g_he[pair*HIDN];
    #pragma unroll
    for (int q2 = 0; q2 < 16; q2++)
        o[q2] = make_float4(he[4*q2], he[4*q2+1], he[4*q2+2], he[4*q2+3]);

    float av[HH];
    #pragma unroll
    for (int hh = 0; hh < HH; hh++){
        float s = sBsem[hh];
        #pragma unroll
        for (int k = 0; k < HIDN; k++) s = fmaf(he[k], sWs[k][hh], s);
        s = (s > 0.f) ? s : 2.0f*expm1f(0.5f*s);
        if (i == j) s -= 1e5f;
        av[hh] = s;
    }
    *(float4*)&g_attl[pair*HH] = make_float4(av[0], av[1], av[2], av[3]);
}

// -------- K3: HMMA xmix GEMM, 2 CTAs per node (m-halves) --------
#define WROW 528
#define OFF_A   0u            // A frags (half): 8 mt * 16 k * 32 lanes * 16B = 65536
#define OFF_B   65536u        // 64 * 528 = 33792
#define OFF_ATT 99328u        // float4[256]
#define OFF_XH  103424u       // float4[256]
#define OFF_RED 107520u       // float4[256]
#define OFF_HEP 111616u       // float[512]
#define K3_SMEM 113664u

__global__ __launch_bounds__(256,2) void k3_attn(const float* __restrict__ W_vmix)
{
    extern __shared__ char smem[];
    unsigned int sbase = smem_u32(smem);
    float4* sAtt = (float4*)(smem + OFF_ATT);
    float4* sXh  = (float4*)(smem + OFF_XH);
    float4* sRed = (float4*)(smem + OFF_RED);
    float*  sHeP = (float*)(smem + OFF_HEP);
    const uint4* sA4 = (const uint4*)(smem + OFF_A);

    int node = blockIdx.x >> 1;
    int half = blockIdx.x & 1;
    int t = threadIdx.x;
    long base = ((long)node)*NN;

    // ---- copy A-half frags into smem ----
    {
        const uint4* src = g_WtF + half*4096;
        uint4* dst = (uint4*)(smem + OFF_A);
        for (int idx = t; idx < 4096; idx += 256) dst[idx] = src[idx];
    }

    // ---- softmax over j (per head) ----
    float4 l = *(const float4*)&g_attl[(base + t)*HH];
    sRed[t] = l;
    sXh[t] = g_dx[base + t];
    __syncthreads();
    for (int s = 128; s; s >>= 1){
        if (t < s){
            float4 o2 = sRed[t+s]; float4 m = sRed[t];
            m.x = fmaxf(m.x,o2.x); m.y = fmaxf(m.y,o2.y);
            m.z = fmaxf(m.z,o2.z); m.w = fmaxf(m.w,o2.w);
            sRed[t] = m;
        }
        __syncthreads();
    }
    float4 mx = sRed[0];
    __syncthreads();
    float4 e = make_float4(expf(l.x-mx.x), expf(l.y-mx.y), expf(l.z-mx.z), expf(l.w-mx.w));
    sRed[t] = e;
    __syncthreads();
    for (int s = 128; s; s >>= 1){
        if (t < s){
            float4 o2 = sRed[t+s]; float4 m = sRed[t];
            m.x += o2.x; m.y += o2.y; m.z += o2.z; m.w += o2.w;
            sRed[t] = m;
        }
        __syncthreads();
    }
    float4 sm = sRed[0];
    __syncthreads();
    sAtt[t] = make_float4(e.x/sm.x, e.y/sm.y, e.z/sm.z, e.w/sm.w);
    __syncthreads();

    int lane = t & 31, warp = t >> 5;
    int g = lane >> 2, tig = lane & 3;
    unsigned int bBase = sbase + OFF_B + (unsigned)((lane & 7))*WROW
                       + (unsigned)(((lane >> 3) & 1)*16);

    float cs[2][3];
    cs[0][0]=cs[0][1]=cs[0][2]=cs[1][0]=cs[1][1]=cs[1][2]=0.f;
    float heS0 = 0.f, heS1 = 0.f;

    int cp = t & 127, jh = t >> 7;
    int fch = cp >> 1;
    int h0 = (2*cp) & 3, h1 = h0 + 1;

    for (int jb = 0; jb < 4; jb++){
        // build B tile: 64 j-rows x 256 c (bf16 pairs)
        #pragma unroll 4
        for (int jj = 0; jj < 32; jj++){
            int jl = jh*32 + jj;
            int j  = jb*64 + jl;
            float hev = g_he[(base + j)*HIDN + fch];
            float4 a4 = sAtt[j];
            float v0 = hev * ((const float*)&a4)[h0];
            float v1 = hev * ((const float*)&a4)[h1];
            heS0 += v0; heS1 += v1;
            *(unsigned int*)(smem + OFF_B + jl*WROW + cp*4) = pack_bf2(v0, v1);
        }
        __syncthreads();

        float acc[32];
        #pragma unroll
        for (int q = 0; q < 32; q++) acc[q] = 0.f;

        #pragma unroll 4
        for (int k = 0; k < 16; k++){
            uint4 aF = sA4[(warp*16 + k)*32 + lane];
            #pragma unroll
            for (int n = 0; n < 8; n++){
                unsigned int bfr[2];
                LDSM_X2(bfr, bBase + (unsigned)(n*8*WROW + k*32));
                MMA16816(acc + n*4, (unsigned int*)&aF, bfr[0], bfr[1]);
            }
        }

        // epilogue: tanh + cs accumulation
        #pragma unroll
        for (int n = 0; n < 8; n++){
            int j0 = jb*64 + n*8 + tig*2;
            float4 x0 = sXh[j0], x1 = sXh[j0+1];
            float t0 = tanhfast(acc[n*4+0]);
            float t1 = tanhfast(acc[n*4+1]);
            float t2 = tanhfast(acc[n*4+2]);
            float t3 = tanhfast(acc[n*4+3]);
            cs[0][0] = fmaf(t0, x0.y, fmaf(t1, x1.y, cs[0][0]));
            cs[0][1] = fmaf(t0, x0.z, fmaf(t1, x1.z, cs[0][1]));
            cs[0][2] = fmaf(t0, x0.w, fmaf(t1, x1.w, cs[0][2]));
            cs[1][0] = fmaf(t2, x0.y, fmaf(t3, x1.y, cs[1][0]));
            cs[1][1] = fmaf(t2, x0.z, fmaf(t3, x1.z, cs[1][1]));
            cs[1][2] = fmaf(t2, x0.w, fmaf(t3, x1.w, cs[1][2]));
        }
        __syncthreads();
    }

    sHeP[jh*256 + 2*cp    ] = heS0;
    sHeP[jh*256 + 2*cp + 1] = heS1;

    // reduce cs over the quad (lanes with same g share c' rows)
    #pragma unroll
    for (int r = 0; r < 2; r++)
        #pragma unroll
        for (int q = 0; q < 3; q++){
            float v = cs[r][q];
            v += __shfl_xor_sync(0xFFFFFFFFu, v, 1);
            v += __shfl_xor_sync(0xFFFFFFFFu, v, 2);
            cs[r][q] = v;
        }

    const float invn = 1.0f/(float)NN;
    float pd0 = 0.f, pd1 = 0.f, pd2 = 0.f;
    if (tig == 0){
        #pragma unroll
        for (int r = 0; r < 2; r++){
            int cpr = half*128 + warp*16 + r*8 + g;
            float a  = cs[r][0]*invn;
            float b2 = cs[r][1]*invn;
            float c2 = cs[r][2]*invn;
            g_cn[node*CC + cpr] = a*a + b2*b2 + c2*c2;
            float wv = W_vmix[cpr];
            pd0 = fmaf(a, wv, pd0);
            pd1 = fmaf(b2, wv, pd1);
            pd2 = fmaf(c2, wv, pd2);
        }
    }
    __syncthreads();
    if (half == 0)
        g_hesum[node*CC + t] = sHeP[t] + sHeP[256 + t];
    sRed[t] = make_float4(pd0, pd1, pd2, 0.f);
    __syncthreads();
    for (int s = 128; s; s >>= 1){
        if (t < s){
            float4 o2 = sRed[t+s]; float4 m2 = sRed[t];
            m2.x += o2.x; m2.y += o2.y; m2.z += o2.z;
            sRed[t] = m2;
        }
        __syncthreads();
    }
    if (t == 0){
        float4 r = sRed[0];
        g_dvp[node*8 + half*4 + 0] = r.x;
        g_dvp[node*8 + half*4 + 1] = r.y;
        g_dvp[node*8 + half*4 + 2] = r.z;
    }
}

// -------- K4: node MLPs + outputs (4-way k-split, 256 threads) --------
__global__ __launch_bounds__(256) void k4_node(
    const float* __restrict__ h, const float* __restrict__ x, const float* __restrict__ v,
    const float* __restrict__ W_p1, const float* __restrict__ b_p1,
    const float* __restrict__ W_p2, const float* __restrict__ b_p2,
    const float* __restrict__ W_n1, const float* __restrict__ b_n1,
    const float* __restrict__ W_n2, const float* __restrict__ b_n2,
    const float* __restrict__ W_v1, const float* __restrict__ b_v1,
    const float* __restrict__ W_v2, float* __restrict__ out)
{
    int node = blockIdx.x; int t = threadIdx.x;
    int to = t & 63, ko = t >> 6;
    __shared__ float sIn[384];        // [h(64) | hesum(256) | hcomb(64)]
    __shared__ float sCn[CC];
    __shared__ float sAcc[256];
    __shared__ float sX[HIDN], sY[HIDN];
    __shared__ float sFin[2];

    if (t < 64) sIn[t] = h[node*FF + t];
    for (int k = t; k < CC; k += 256){
        sIn[64 + k] = g_hesum[node*CC + k];
        sCn[k] = g_cn[node*CC + k];
    }
    __syncthreads();

    // p1: 256 -> 64
    {
        float acc = 0.f;
        int k0 = ko*64;
        #pragma unroll 8
        for (int k = 0; k < 64; k++)
            acc = fmaf(sCn[k0+k], W_p1[(k0+k)*HIDN + to], acc);
        sAcc[t] = acc;
    }
    __syncthreads();
    if (ko == 0)
        sX[to] = siluf(b_p1[to] + sAcc[to] + sAcc[64+to] + sAcc[128+to] + sAcc[192+to]);
    __syncthreads();
    // p2: 64 -> 64 (h_comb)
    {
        float acc = 0.f;
        int k0 = ko*16;
        #pragma unroll
        for (int k = 0; k < 16; k++)
            acc = fmaf(sX[k0+k], W_p2[(k0+k)*HIDN + to], acc);
        sAcc[t] = acc;
    }
    __syncthreads();
    if (ko == 0)
        sIn[320 + to] = siluf(b_p2[to] + sAcc[to] + sAcc[64+to] + sAcc[128+to] + sAcc[192+to]);
    __syncthreads();
    // n1: 384 -> 64
    {
        float acc = 0.f;
        int k0 = ko*96;
        #pragma unroll 8
        for (int k = 0; k < 96; k++)
            acc = fmaf(sIn[k0+k], W_n1[(k0+k)*HIDN + to], acc);
        sAcc[t] = acc;
    }
    __syncthreads();
    if (ko == 0)
        sX[to] = siluf(b_n1[to] + sAcc[to] + sAcc[64+to] + sAcc[128+to] + sAcc[192+to]);
    __syncthreads();
    // n2: 64 -> 64, residual -> h_new
    {
        float acc = 0.f;
        int k0 = ko*16;
        #pragma unroll
        for (int k = 0; k < 16; k++)
            acc = fmaf(sX[k0+k], W_n2[(k0+k)*HIDN + to], acc);
        sAcc[t] = acc;
    }
    __syncthreads();
    if (ko == 0){
        float hn = sIn[to] + siluf(b_n2[to] + sAcc[to] + sAcc[64+to] + sAcc[128+to] + sAcc[192+to]);
        sY[to] = hn;
        out[node*FF + to] = hn;
    }
    __syncthreads();
    // v1: 64 -> 64
    {
        float acc = 0.f;
        int k0 = ko*16;
        #pragma unroll
        for (int k = 0; k < 16; k++)
            acc = fmaf(sY[k0+k], W_v1[(k0+k)*HIDN + to], acc);
        sAcc[t] = acc;
    }
    __syncthreads();
    if (ko == 0)
        sX[to] = siluf(b_v1[to] + sAcc[to] + sAcc[64+to] + sAcc[128+to] + sAcc[192+to]) * W_v2[to];
    __syncthreads();
    if (t < 32){
        float s = sX[t] + sX[t+32];
        #pragma unroll
        for (int o2 = 16; o2; o2 >>= 1)
            s += __shfl_xor_sync(0xFFFFFFFFu, s, o2);
        if (t == 0) sFin[0] = s;
    }
    __syncthreads();
    if (t < 3){
        float vs = 2.0f/(1.0f + expf(-sFin[0]));
        float vn = g_dvp[node*8 + t] + g_dvp[node*8 + 4 + t] + vs * v[node*3 + t];
        out[NODES*FF + node*3 + t]            = x[node*3 + t] + vn;
        out[NODES*FF + NODES*3 + node*3 + t]  = vn;
    }
}

extern "C" void kernel_launch(void* const* d_in, const int* in_sizes, int n_in,
                              void* d_out, int out_size)
{
    const float* h      = (const float*)d_in[0];
    const float* x      = (const float*)d_in[1];
    const float* v      = (const float*)d_in[2];
    const float* W_in   = (const float*)d_in[3];
    const float* b_in   = (const float*)d_in[4];
    const float* means  = (const float*)d_in[5];
    const float* betas  = (const float*)d_in[6];
    const float* W_o1   = (const float*)d_in[7];
    const float* b_o1   = (const float*)d_in[8];
    const float* W_o2   = (const float*)d_in[9];
    const float* b_o2   = (const float*)d_in[10];
    const float* W_sem  = (const float*)d_in[11];
    const float* b_sem  = (const float*)d_in[12];
    const float* W_xmix = (const float*)d_in[13];
    const float* W_p1   = (const float*)d_in[14];
    const float* b_p1   = (const float*)d_in[15];
    const float* W_p2   = (const float*)d_in[16];
    const float* b_p2   = (const float*)d_in[17];
    const float* W_n1   = (const float*)d_in[18];
    const float* b_n1   = (const float*)d_in[19];
    const float* W_n2   = (const float*)d_in[20];
    const float* b_n2   = (const float*)d_in[21];
    const float* W_v1   = (const float*)d_in[22];
    const float* b_v1   = (const float*)d_in[23];
    const float* W_v2   = (const float*)d_in[24];
    const float* W_vmix = (const float*)d_in[25];
    float* out = (float*)d_out;

    static int smem_set = 0;
    if (!smem_set){
        cudaFuncSetAttribute(k3_attn, cudaFuncAttributeMaxDynamicSharedMemorySize, K3_SMEM);
        smem_set = 1;
    }

    k0_wt<<<32, 256>>>(W_xmix);
    k1_node<<<NODES, 64>>>(h, W_in, W_o1);
    dim3 g2(NN/16, NN/16, BB);
    k2_edge<<<g2, 256>>>(x, W_o1, b_o1, W_o2, b_o2, W_sem, b_sem, b_in, means, betas);
    k3_attn<<<NODES*2, 256, K3_SMEM>>>(W_vmix);
    k4_node<<<NODES, 256>>>(h, x, v, W_p1, b_p1, W_p2, b_p2,
                            W_n1, b_n1, W_n2, b_n2, W_v1, b_v1, W_v2, out);
}

// round 6
// speedup vs baseline: 3.9365x; 1.0782x over previous
#include <cuda_runtime.h>
#include <math.h>

#define BB 2
#define NN 256
#define FF 64
#define HH 4
#define HIDN 64
#define CC 256
#define KF 50
#define NODES (BB*NN)
#define CUTF 5.0f
#define PI_F 3.14159265358979f

// -------- scratch (device globals; no runtime allocation) --------
__device__ float g_Ain[NODES*KF];
__device__ float g_Bin[NODES*KF];
__device__ float g_P[NODES*HIDN];
__device__ float g_Q[NODES*HIDN];
__device__ unsigned int g_heb[(long)BB*NN*NN*32];  // h_e bf16 pairs (16 MB)
__device__ float g_attl[(long)BB*NN*NN*HH];        // att logits
__device__ float4 g_dx[(long)BB*NN*NN];            // (d, xhat)
__device__ float g_hesum[NODES*CC];
__device__ float g_cn[NODES*CC];
__device__ float g_dvp[NODES*8];                   // dv partials (2 halves)
// W_xmix^T in per-lane mma fragment layout: [mt 0..15][k 0..15][lane 0..31] uint4
__device__ uint4 g_WtF[8192];

__device__ __forceinline__ float siluf(float v){ return v/(1.0f+expf(-v)); }

__device__ __forceinline__ unsigned int pack_bf2(float lo, float hi){
    unsigned int r;
    asm("cvt.rn.bf16x2.f32 %0, %1, %2;" : "=r"(r) : "f"(hi), "f"(lo));
    return r;
}
__device__ __forceinline__ unsigned int hmul2(unsigned int a, unsigned int b){
    unsigned int r;
    asm("mul.rn.bf16x2 %0, %1, %2;" : "=r"(r) : "r"(a), "r"(b));
    return r;
}
__device__ __forceinline__ unsigned int smem_u32(const void* p){
    unsigned int a;
    asm("{ .reg .u64 t; cvta.to.shared.u64 t, %1; cvt.u32.u64 %0, t; }" : "=r"(a) : "l"(p));
    return a;
}
__device__ __forceinline__ float tanhfast(float x){
    float r; asm("tanh.approx.f32 %0, %1;" : "=f"(r) : "f"(x)); return r;
}
#define LDSM_X2(R, addr) \
    asm volatile("ldmatrix.sync.aligned.m8n8.x2.shared.b16 {%0,%1}, [%2];" \
        : "=r"((R)[0]),"=r"((R)[1]) : "r"(addr))
#define MMA16816(D, A, B0, B1) \
    asm volatile("mma.sync.aligned.m16n8k16.row.col.f32.bf16.bf16.f32 " \
        "{%0,%1,%2,%3}, {%4,%5,%6,%7}, {%8,%9}, {%0,%1,%2,%3};" \
        : "+f"((D)[0]),"+f"((D)[1]),"+f"((D)[2]),"+f"((D)[3]) \
        : "r"((A)[0]),"r"((A)[1]),"r"((A)[2]),"r"((A)[3]),"r"(B0),"r"(B1))

// -------- K0: W_xmix^T bf16 in mma fragment layout --------
__global__ void k0_wt(const float* __restrict__ W){
    int idx = blockIdx.x*256 + threadIdx.x;   // 0..8191
    int lane = idx & 31;
    int k = (idx >> 5) & 15;
    int mt = idx >> 9;
    int g = lane >> 2, tig = lane & 3;
    int r0 = mt*16 + g, r1 = r0 + 8;
    int cp0 = k*8 + tig, cp1 = cp0 + 4;
    uint4 f;
    f.x = pack_bf2(W[(2*cp0)*CC + r0], W[(2*cp0+1)*CC + r0]);
    f.y = pack_bf2(W[(2*cp0)*CC + r1], W[(2*cp0+1)*CC + r1]);
    f.z = pack_bf2(W[(2*cp1)*CC + r0], W[(2*cp1+1)*CC + r0]);
    f.w = pack_bf2(W[(2*cp1)*CC + r1], W[(2*cp1+1)*CC + r1]);
    g_WtF[idx] = f;
}

// -------- K1: per-node partial products --------
__global__ void k1_node(const float* __restrict__ h,
                        const float* __restrict__ W_in,
                        const float* __restrict__ W_o1)
{
    int node = blockIdx.x; int t = threadIdx.x;
    __shared__ float sh[FF];
    sh[t] = h[node*FF + t];
    __syncthreads();
    float p = 0.f, q = 0.f;
    #pragma unroll 8
    for (int k = 0; k < FF; k++){
        float hv = sh[k];
        p = fmaf(hv, W_o1[k*HIDN + t], p);
        q = fmaf(hv, W_o1[(FF+k)*HIDN + t], q);
    }
    g_P[node*HIDN + t] = p;
    g_Q[node*HIDN + t] = q;
    if (t < KF){
        float a = 0.f, bv = 0.f;
        #pragma unroll 8
        for (int k = 0; k < FF; k++){
            float hv = sh[k];
            a  = fmaf(hv, W_in[k*KF + t], a);
            bv = fmaf(hv, W_in[(FF+k)*KF + t], bv);
        }
        g_Ain[node*KF + t] = a;
        g_Bin[node*KF + t] = bv;
    }
}

// -------- K2: edge model --------
__global__ __launch_bounds__(256,1) void k2_edge(
    const float* __restrict__ x,
    const float* __restrict__ W_o1, const float* __restrict__ b_o1,
    const float* __restrict__ W_o2, const float* __restrict__ b_o2,
    const float* __restrict__ W_sem, const float* __restrict__ b_sem,
    const float* __restrict__ b_in, const float* __restrict__ means,
    const float* __restrict__ betas)
{
    int b  = blockIdx.z;
    int i0 = blockIdx.y*16, j0 = blockIdx.x*16;
    int t  = threadIdx.x;
    int ti = t >> 4, tj = t & 15;

    __shared__ __align__(16) float sA[16][KF+3];
    __shared__ __align__(16) float sB[16][KF+3];
    __shared__ __align__(16) float sP[16][68];
    __shared__ __align__(16) float sQ[16][68];
    __shared__ float sXi[16][3], sXj[16][3];
    __shared__ __align__(16) float sW1m[KF+1][HIDN];
    __shared__ __align__(16) float sW2[HIDN][HIDN];
    __shared__ float sWs[HIDN][HH];
    __shared__ float sMean[KF], sBeta[KF], sBinV[KF];
    __shared__ __align__(16) float sBo1[HIDN];
    __shared__ __align__(16) float sBo2[HIDN];
    __shared__ float sBsem[HH];

    for (int idx = t; idx < 16*KF; idx += 256){
        int r = idx / KF, c = idx - r*KF;
        sA[r][c] = g_Ain[(b*NN + j0 + r)*KF + c];
        sB[r][c] = g_Bin[(b*NN + i0 + r)*KF + c];
    }
    for (int idx = t; idx < 16*HIDN; idx += 256){
        int r = idx >> 6, c = idx & 63;
        sP[r][c] = g_P[(b*NN + j0 + r)*HIDN + c];
        sQ[r][c] = g_Q[(b*NN + i0 + r)*HIDN + c];
    }
    if (t < 48){
        int r = t/3, c = t - r*3;
        sXi[r][c] = x[(b*NN + i0 + r)*3 + c];
        sXj[r][c] = x[(b*NN + j0 + r)*3 + c];
    }
    for (int idx = t; idx < (KF+1)*HIDN; idx += 256)
        sW1m[idx>>6][idx&63] = W_o1[(128 + (idx>>6))*HIDN + (idx&63)];
    for (int idx = t; idx < HIDN*HIDN; idx += 256)
        sW2[idx>>6][idx&63] = W_o2[idx];
    if (t < HIDN*HH) sWs[t>>2][t&3] = W_sem[t];
    if (t < KF){ sMean[t] = means[t]; sBeta[t] = betas[t]; sBinV[t] = b_in[t]; }
    if (t < HIDN){ sBo1[t] = b_o1[t]; sBo2[t] = b_o2[t]; }
    if (t < HH) sBsem[t] = b_sem[t];
    __syncthreads();

    int i = i0 + ti, j = j0 + tj;
    float dx = sXj[tj][0] - sXi[ti][0];
    float dy = sXj[tj][1] - sXi[ti][1];
    float dz = sXj[tj][2] - sXi[ti][2];
    float s2 = dx*dx + dy*dy + dz*dz;
    float d  = sqrtf(s2 + 1e-5f);
    float inv = 1.0f / (d + 1e-5f);
    long pair = ((long)(b*NN + i))*NN + j;
    g_dx[pair] = make_float4(d, dx*inv, dy*inv, dz*inv);

    float cutv = (d < CUTF) ? 0.5f*(cosf(d*(PI_F/CUTF)) + 1.0f) : 0.0f;
    float em = expf(-d);

    float pre[HIDN];
    {
        const float* wd = &sW1m[KF][0];
        #pragma unroll
        for (int f = 0; f < HIDN; f++)
            pre[f] = sP[tj][f] + sQ[ti][f] + sBo1[f] + d*wd[f];
    }
    for (int c = 0; c < KF; c++){
        float h1 = sA[tj][c] + sB[ti][c] + sBinV[c];
        float dm = em - sMean[c];
        float r  = cutv * expf(-sBeta[c]*dm*dm);
        float t2 = r * h1;
        const float4* w4 = (const float4*)&sW1m[c][0];
        #pragma unroll
        for (int q2 = 0; q2 < 16; q2++){
            float4 w = w4[q2];
            pre[4*q2+0] = fmaf(t2, w.x, pre[4*q2+0]);
            pre[4*q2+1] = fmaf(t2, w.y, pre[4*q2+1]);
            pre[4*q2+2] = fmaf(t2, w.z, pre[4*q2+2]);
            pre[4*q2+3] = fmaf(t2, w.w, pre[4*q2+3]);
        }
    }
    float he[HIDN];
    #pragma unroll
    for (int f = 0; f < HIDN; f++) he[f] = sBo2[f];
    #pragma unroll
    for (int k = 0; k < HIDN; k++){
        float a = pre[k];
        a = a / (1.0f + expf(-a));
        const float4* w4 = (const float4*)&sW2[k][0];
        #pragma unroll
        for (int q2 = 0; q2 < 16; q2++){
            float4 w = w4[q2];
            he[4*q2+0] = fmaf(a, w.x, he[4*q2+0]);
            he[4*q2+1] = fmaf(a, w.y, he[4*q2+1]);
            he[4*q2+2] = fmaf(a, w.z, he[4*q2+2]);
            he[4*q2+3] = fmaf(a, w.w, he[4*q2+3]);
        }
    }
    // write h_e as bf16 pairs (f-major)
    {
        uint4* o = (uint4*)(g_heb + pair*32);
        #pragma unroll
        for (int q2 = 0; q2 < 8; q2++){
            uint4 w;
            w.x = pack_bf2(he[8*q2+0], he[8*q2+1]);
            w.y = pack_bf2(he[8*q2+2], he[8*q2+3]);
            w.z = pack_bf2(he[8*q2+4], he[8*q2+5]);
            w.w = pack_bf2(he[8*q2+6], he[8*q2+7]);
            o[q2] = w;
        }
    }

    float av[HH];
    #pragma unroll
    for (int hh = 0; hh < HH; hh++){
        float s = sBsem[hh];
        #pragma unroll
        for (int k = 0; k < HIDN; k++) s = fmaf(he[k], sWs[k][hh], s);
        s = (s > 0.f) ? s : 2.0f*expm1f(0.5f*s);
        if (i == j) s -= 1e5f;
        av[hh] = s;
    }
    *(float4*)&g_attl[pair*HH] = make_float4(av[0], av[1], av[2], av[3]);
}

// -------- K3: HMMA xmix GEMM, 2 CTAs per node (m-halves) --------
#define WROW 528
#define OFF_A    0u            // A frags (half): 4096 uint4 = 65536
#define OFF_B    65536u        // 64 * 528 = 33792 -> 99328
#define OFF_ATT  99328u        // float4[256] -> 103424
#define OFF_XH   103424u       // float4[256] -> 107520
#define OFF_RED  107520u       // float4[256] -> 111616
#define OFF_ATTP 111616u       // uint[256][2] -> 113664
#define K3_SMEM  113664u

__global__ __launch_bounds__(256,2) void k3_attn(const float* __restrict__ W_vmix)
{
    extern __shared__ char smem[];
    unsigned int sbase = smem_u32(smem);
    float4* sAtt = (float4*)(smem + OFF_ATT);
    float4* sXh  = (float4*)(smem + OFF_XH);
    float4* sRed = (float4*)(smem + OFF_RED);
    unsigned int* sAttP = (unsigned int*)(smem + OFF_ATTP);
    const uint4* sA4 = (const uint4*)(smem + OFF_A);

    int node = blockIdx.x >> 1;
    int half = blockIdx.x & 1;
    int t = threadIdx.x;
    long base = ((long)node)*NN;

    // ---- copy A-half frags into smem ----
    {
        const uint4* src = g_WtF + half*4096;
        uint4* dst = (uint4*)(smem + OFF_A);
        for (int idx = t; idx < 4096; idx += 256) dst[idx] = src[idx];
    }

    // ---- softmax over j (per head) ----
    float4 l = *(const float4*)&g_attl[(base + t)*HH];
    sRed[t] = l;
    sXh[t] = g_dx[base + t];
    __syncthreads();
    for (int s = 128; s; s >>= 1){
        if (t < s){
            float4 o2 = sRed[t+s]; float4 m = sRed[t];
            m.x = fmaxf(m.x,o2.x); m.y = fmaxf(m.y,o2.y);
            m.z = fmaxf(m.z,o2.z); m.w = fmaxf(m.w,o2.w);
            sRed[t] = m;
        }
        __syncthreads();
    }
    float4 mx = sRed[0];
    __syncthreads();
    float4 e = make_float4(expf(l.x-mx.x), expf(l.y-mx.y), expf(l.z-mx.z), expf(l.w-mx.w));
    sRed[t] = e;
    __syncthreads();
    for (int s = 128; s; s >>= 1){
        if (t < s){
            float4 o2 = sRed[t+s]; float4 m = sRed[t];
            m.x += o2.x; m.y += o2.y; m.z += o2.z; m.w += o2.w;
            sRed[t] = m;
        }
        __syncthreads();
    }
    float4 sm = sRed[0];
    __syncthreads();
    float4 att = make_float4(e.x/sm.x, e.y/sm.y, e.z/sm.z, e.w/sm.w);
    sAtt[t] = att;
    sAttP[2*t  ] = pack_bf2(att.x, att.y);
    sAttP[2*t+1] = pack_bf2(att.z, att.w);
    __syncthreads();

    // ---- he_sum (half-0 CTAs only): coalesced bf16 loads, fp32 accum ----
    if (half == 0){
        int f = t & 63, q = t >> 6;
        int sh = (f & 1)*16;
        const unsigned int* hb = g_heb + (base + q*64)*32 + (f >> 1);
        float s0=0.f, s1=0.f, s2=0.f, s3=0.f;
        #pragma unroll 4
        for (int jj = 0; jj < 64; jj++){
            unsigned int u = hb[jj*32];
            float hev = __uint_as_float(((u >> sh) & 0xFFFFu) << 16);
            float4 a4 = sAtt[q*64 + jj];
            s0 = fmaf(hev, a4.x, s0); s1 = fmaf(hev, a4.y, s1);
            s2 = fmaf(hev, a4.z, s2); s3 = fmaf(hev, a4.w, s3);
        }
        sRed[t] = make_float4(s0, s1, s2, s3);
    }
    __syncthreads();
    if (half == 0){
        int f = t >> 2, hh2 = t & 3;
        float s = ((const float*)&sRed[f])[hh2]
                + ((const float*)&sRed[64+f])[hh2]
                + ((const float*)&sRed[128+f])[hh2]
                + ((const float*)&sRed[192+f])[hh2];
        g_hesum[node*CC + t] = s;
    }
    __syncthreads();

    int lane = t & 31, warp = t >> 5;
    int g = lane >> 2, tig = lane & 3;
    unsigned int bBase = sbase + OFF_B + (unsigned)((lane & 7))*WROW
                       + (unsigned)(((lane >> 3) & 1)*16);

    float cs[2][3];
    cs[0][0]=cs[0][1]=cs[0][2]=cs[1][0]=cs[1][1]=cs[1][2]=0.f;

    int jl = t & 63, ch0 = t >> 6, ch1 = ch0 + 4;   // this thread's j-row + 2 chunks

    for (int jb = 0; jb < 4; jb++){
        // ---- vectorized B-build: B[j][c] = he_bf16[j,f] * attP[j,hpair] ----
        {
            const uint4* heRow = (const uint4*)(g_heb + (base + jb*64 + jl)*32);
            uint4 u0 = heRow[ch0];
            uint4 u1 = heRow[ch1];
            int ja = jb*64 + jl;
            unsigned int ap0 = sAttP[2*ja], ap1 = sAttP[2*ja+1];
            char* brow = smem + OFF_B + jl*WROW;
            unsigned int dd; uint4 o;
            #define BPAIR(uu, chv, comp) { \
                dd = __byte_perm(uu, uu, 0x1010); o.x = hmul2(dd, ap0); o.y = hmul2(dd, ap1); \
                dd = __byte_perm(uu, uu, 0x3232); o.z = hmul2(dd, ap0); o.w = hmul2(dd, ap1); \
                *(uint4*)(brow + (chv)*64 + (comp)*16) = o; }
            BPAIR(u0.x, ch0, 0) BPAIR(u0.y, ch0, 1) BPAIR(u0.z, ch0, 2) BPAIR(u0.w, ch0, 3)
            BPAIR(u1.x, ch1, 0) BPAIR(u1.y, ch1, 1) BPAIR(u1.z, ch1, 2) BPAIR(u1.w, ch1, 3)
            #undef BPAIR
        }
        __syncthreads();

        float acc[32];
        #pragma unroll
        for (int q = 0; q < 32; q++) acc[q] = 0.f;

        #pragma unroll 4
        for (int k = 0; k < 16; k++){
            uint4 aF = sA4[(warp*16 + k)*32 + lane];
            #pragma unroll
            for (int n = 0; n < 8; n++){
                unsigned int bfr[2];
                LDSM_X2(bfr, bBase + (unsigned)(n*8*WROW + k*32));
                MMA16816(acc + n*4, (unsigned int*)&aF, bfr[0], bfr[1]);
            }
        }

        // epilogue: tanh + cs accumulation
        #pragma unroll
        for (int n = 0; n < 8; n++){
            int j0 = jb*64 + n*8 + tig*2;
            float4 x0 = sXh[j0], x1 = sXh[j0+1];
            float t0 = tanhfast(acc[n*4+0]);
            float t1 = tanhfast(acc[n*4+1]);
            float t2 = tanhfast(acc[n*4+2]);
            float t3 = tanhfast(acc[n*4+3]);
            cs[0][0] = fmaf(t0, x0.y, fmaf(t1, x1.y, cs[0][0]));
            cs[0][1] = fmaf(t0, x0.z, fmaf(t1, x1.z, cs[0][1]));
            cs[0][2] = fmaf(t0, x0.w, fmaf(t1, x1.w, cs[0][2]));
            cs[1][0] = fmaf(t2, x0.y, fmaf(t3, x1.y, cs[1][0]));
            cs[1][1] = fmaf(t2, x0.z, fmaf(t3, x1.z, cs[1][1]));
            cs[1][2] = fmaf(t2, x0.w, fmaf(t3, x1.w, cs[1][2]));
        }
        __syncthreads();
    }

    // reduce cs over the quad (lanes with same g share c' rows)
    #pragma unroll
    for (int r = 0; r < 2; r++)
        #pragma unroll
        for (int q = 0; q < 3; q++){
            float v = cs[r][q];
            v += __shfl_xor_sync(0xFFFFFFFFu, v, 1);
            v += __shfl_xor_sync(0xFFFFFFFFu, v, 2);
            cs[r][q] = v;
        }

    const float invn = 1.0f/(float)NN;
    float pd0 = 0.f, pd1 = 0.f, pd2 = 0.f;
    if (tig == 0){
        #pragma unroll
        for (int r = 0; r < 2; r++){
            int cpr = half*128 + warp*16 + r*8 + g;
            float a  = cs[r][0]*invn;
            float b2 = cs[r][1]*invn;
            float c2 = cs[r][2]*invn;
            g_cn[node*CC + cpr] = a*a + b2*b2 + c2*c2;
            float wv = W_vmix[cpr];
            pd0 = fmaf(a, wv, pd0);
            pd1 = fmaf(b2, wv, pd1);
            pd2 = fmaf(c2, wv, pd2);
        }
    }
    __syncthreads();
    sRed[t] = make_float4(pd0, pd1, pd2, 0.f);
    __syncthreads();
    for (int s = 128; s; s >>= 1){
        if (t < s){
            float4 o2 = sRed[t+s]; float4 m2 = sRed[t];
            m2.x += o2.x; m2.y += o2.y; m2.z += o2.z;
            sRed[t] = m2;
        }
        __syncthreads();
    }
    if (t == 0){
        float4 r = sRed[0];
        g_dvp[node*8 + half*4 + 0] = r.x;
        g_dvp[node*8 + half*4 + 1] = r.y;
        g_dvp[node*8 + half*4 + 2] = r.z;
    }
}

// -------- K4: node MLPs + outputs (4-way k-split, 256 threads) --------
__global__ __launch_bounds__(256) void k4_node(
    const float* __restrict__ h, const float* __restrict__ x, const float* __restrict__ v,
    const float* __restrict__ W_p1, const float* __restrict__ b_p1,
    const float* __restrict__ W_p2, const float* __restrict__ b_p2,
    const float* __restrict__ W_n1, const float* __restrict__ b_n1,
    const float* __restrict__ W_n2, const float* __restrict__ b_n2,
    const float* __restrict__ W_v1, const float* __restrict__ b_v1,
    const float* __restrict__ W_v2, float* __restrict__ out)
{
    int node = blockIdx.x; int t = threadIdx.x;
    int to = t & 63, ko = t >> 6;
    __shared__ float sIn[384];        // [h(64) | hesum(256) | hcomb(64)]
    __shared__ float sCn[CC];
    __shared__ float sAcc[256];
    __shared__ float sX[HIDN], sY[HIDN];
    __shared__ float sFin[2];

    if (t < 64) sIn[t] = h[node*FF + t];
    for (int k = t; k < CC; k += 256){
        sIn[64 + k] = g_hesum[node*CC + k];
        sCn[k] = g_cn[node*CC + k];
    }
    __syncthreads();

    // p1: 256 -> 64
    {
        float acc = 0.f;
        int k0 = ko*64;
        #pragma unroll 8
        for (int k = 0; k < 64; k++)
            acc = fmaf(sCn[k0+k], W_p1[(k0+k)*HIDN + to], acc);
        sAcc[t] = acc;
    }
    __syncthreads();
    if (ko == 0)
        sX[to] = siluf(b_p1[to] + sAcc[to] + sAcc[64+to] + sAcc[128+to] + sAcc[192+to]);
    __syncthreads();
    // p2: 64 -> 64 (h_comb)
    {
        float acc = 0.f;
        int k0 = ko*16;
        #pragma unroll
        for (int k = 0; k < 16; k++)
            acc = fmaf(sX[k0+k], W_p2[(k0+k)*HIDN + to], acc);
        sAcc[t] = acc;
    }
    __syncthreads();
    if (ko == 0)
        sIn[320 + to] = siluf(b_p2[to] + sAcc[to] + sAcc[64+to] + sAcc[128+to] + sAcc[192+to]);
    __syncthreads();
    // n1: 384 -> 64
    {
        float acc = 0.f;
        int k0 = ko*96;
        #pragma unroll 8
        for (int k = 0; k < 96; k++)
            acc = fmaf(sIn[k0+k], W_n1[(k0+k)*HIDN + to], acc);
        sAcc[t] = acc;
    }
    __syncthreads();
    if (ko == 0)
        sX[to] = siluf(b_n1[to] + sAcc[to] + sAcc[64+to] + sAcc[128+to] + sAcc[192+to]);
    __syncthreads();
    // n2: 64 -> 64, residual -> h_new
    {
        float acc = 0.f;
        int k0 = ko*16;
        #pragma unroll
        for (int k = 0; k < 16; k++)
            acc = fmaf(sX[k0+k], W_n2[(k0+k)*HIDN + to], acc);
        sAcc[t] = acc;
    }
    __syncthreads();
    if (ko == 0){
        float hn = sIn[to] + siluf(b_n2[to] + sAcc[to] + sAcc[64+to] + sAcc[128+to] + sAcc[192+to]);
        sY[to] = hn;
        out[node*FF + to] = hn;
    }
    __syncthreads();
    // v1: 64 -> 64
    {
        float acc = 0.f;
        int k0 = ko*16;
        #pragma unroll
        for (int k = 0; k < 16; k++)
            acc = fmaf(sY[k0+k], W_v1[(k0+k)*HIDN + to], acc);
        sAcc[t] = acc;
    }
    __syncthreads();
    if (ko == 0)
        sX[to] = siluf(b_v1[to] + sAcc[to] + sAcc[64+to] + sAcc[128+to] + sAcc[192+to]) * W_v2[to];
    __syncthreads();
    if (t < 32){
        float s = sX[t] + sX[t+32];
        #pragma unroll
        for (int o2 = 16; o2; o2 >>= 1)
            s += __shfl_xor_sync(0xFFFFFFFFu, s, o2);
        if (t == 0) sFin[0] = s;
    }
    __syncthreads();
    if (t < 3){
        float vs = 2.0f/(1.0f + expf(-sFin[0]));
        float vn = g_dvp[node*8 + t] + g_dvp[node*8 + 4 + t] + vs * v[node*3 + t];
        out[NODES*FF + node*3 + t]            = x[node*3 + t] + vn;
        out[NODES*FF + NODES*3 + node*3 + t]  = vn;
    }
}

extern "C" void kernel_launch(void* const* d_in, const int* in_sizes, int n_in,
                              void* d_out, int out_size)
{
    const float* h      = (const float*)d_in[0];
    const float* x      = (const float*)d_in[1];
    const float* v      = (const float*)d_in[2];
    const float* W_in   = (const float*)d_in[3];
    const float* b_in   = (const float*)d_in[4];
    const float* means  = (const float*)d_in[5];
    const float* betas  = (const float*)d_in[6];
    const float* W_o1   = (const float*)d_in[7];
    const float* b_o1   = (const float*)d_in[8];
    const float* W_o2   = (const float*)d_in[9];
    const float* b_o2   = (const float*)d_in[10];
    const float* W_sem  = (const float*)d_in[11];
    const float* b_sem  = (const float*)d_in[12];
    const float* W_xmix = (const float*)d_in[13];
    const float* W_p1   = (const float*)d_in[14];
    const float* b_p1   = (const float*)d_in[15];
    const float* W_p2   = (const float*)d_in[16];
    const float* b_p2   = (const float*)d_in[17];
    const float* W_n1   = (const float*)d_in[18];
    const float* b_n1   = (const float*)d_in[19];
    const float* W_n2   = (const float*)d_in[20];
    const float* b_n2   = (const float*)d_in[21];
    const float* W_v1   = (const float*)d_in[22];
    const float* b_v1   = (const float*)d_in[23];
    const float* W_v2   = (const float*)d_in[24];
    const float* W_vmix = (const float*)d_in[25];
    float* out = (float*)d_out;

    static int smem_set = 0;
    if (!smem_set){
        cudaFuncSetAttribute(k3_attn, cudaFuncAttributeMaxDynamicSharedMemorySize, K3_SMEM);
        smem_set = 1;
    }

    k0_wt<<<32, 256>>>(W_xmix);
    k1_node<<<NODES, 64>>>(h, W_in, W_o1);
    dim3 g2(NN/16, NN/16, BB);
    k2_edge<<<g2, 256>>>(x, W_o1, b_o1, W_o2, b_o2, W_sem, b_sem, b_in, means, betas);
    k3_attn<<<NODES*2, 256, K3_SMEM>>>(W_vmix);
    k4_node<<<NODES, 256>>>(h, x, v, W_p1, b_p1, W_p2, b_p2,
                            W_n1, b_n1, W_n2, b_n2, W_v1, b_v1, W_v2, out);
}

// round 7
// speedup vs baseline: 4.0486x; 1.0285x over previous
#include <cuda_runtime.h>
#include <math.h>

#define BB 2
#define NN 256
#define FF 64
#define HH 4
#define HIDN 64
#define CC 256
#define KF 50
#define NODES (BB*NN)
#define CUTF 5.0f
#define PI_F 3.14159265358979f

// -------- scratch (device globals; no runtime allocation) --------
__device__ float g_Ain[NODES*KF];
__device__ float g_Bin[NODES*KF];
__device__ float g_P[NODES*HIDN];
__device__ float g_Q[NODES*HIDN];
__device__ unsigned int g_heb[(long)BB*NN*NN*32];  // h_e bf16 pairs (16 MB)
__device__ float g_attl[(long)BB*NN*NN*HH];        // att logits
__device__ float4 g_dx[(long)BB*NN*NN];            // (d, xhat)
__device__ float g_hesum[NODES*CC];
__device__ float g_cn[NODES*CC];
__device__ float g_dvp[NODES*8];                   // dv partials (2 halves)
// W_xmix^T in per-lane mma fragment layout: [mt 0..15][k 0..15][lane 0..31] uint4
__device__ uint4 g_WtF[8192];

__device__ __forceinline__ float siluf(float v){ return v/(1.0f+expf(-v)); }

__device__ __forceinline__ unsigned int pack_bf2(float lo, float hi){
    unsigned int r;
    asm("cvt.rn.bf16x2.f32 %0, %1, %2;" : "=r"(r) : "f"(hi), "f"(lo));
    return r;
}
__device__ __forceinline__ unsigned int hmul2(unsigned int a, unsigned int b){
    unsigned int r;
    asm("mul.rn.bf16x2 %0, %1, %2;" : "=r"(r) : "r"(a), "r"(b));
    return r;
}
__device__ __forceinline__ unsigned int smem_u32(const void* p){
    unsigned int a;
    asm("{ .reg .u64 t; cvta.to.shared.u64 t, %1; cvt.u32.u64 %0, t; }" : "=r"(a) : "l"(p));
    return a;
}
__device__ __forceinline__ float tanhfast(float x){
    float r; asm("tanh.approx.f32 %0, %1;" : "=f"(r) : "f"(x)); return r;
}
#define LDSM_X4(R, addr) \
    asm volatile("ldmatrix.sync.aligned.m8n8.x4.shared.b16 {%0,%1,%2,%3}, [%4];" \
        : "=r"((R)[0]),"=r"((R)[1]),"=r"((R)[2]),"=r"((R)[3]) : "r"(addr))
#define MMA16816(D, A, B0, B1) \
    asm volatile("mma.sync.aligned.m16n8k16.row.col.f32.bf16.bf16.f32 " \
        "{%0,%1,%2,%3}, {%4,%5,%6,%7}, {%8,%9}, {%0,%1,%2,%3};" \
        : "+f"((D)[0]),"+f"((D)[1]),"+f"((D)[2]),"+f"((D)[3]) \
        : "r"((A)[0]),"r"((A)[1]),"r"((A)[2]),"r"((A)[3]),"r"(B0),"r"(B1))

// -------- K0: W_xmix^T bf16 in mma fragment layout --------
__global__ void k0_wt(const float* __restrict__ W){
    int idx = blockIdx.x*256 + threadIdx.x;   // 0..8191
    int lane = idx & 31;
    int k = (idx >> 5) & 15;
    int mt = idx >> 9;
    int g = lane >> 2, tig = lane & 3;
    int r0 = mt*16 + g, r1 = r0 + 8;
    int cp0 = k*8 + tig, cp1 = cp0 + 4;
    uint4 f;
    f.x = pack_bf2(W[(2*cp0)*CC + r0], W[(2*cp0+1)*CC + r0]);
    f.y = pack_bf2(W[(2*cp0)*CC + r1], W[(2*cp0+1)*CC + r1]);
    f.z = pack_bf2(W[(2*cp1)*CC + r0], W[(2*cp1+1)*CC + r0]);
    f.w = pack_bf2(W[(2*cp1)*CC + r1], W[(2*cp1+1)*CC + r1]);
    g_WtF[idx] = f;
}

// -------- K1: per-node partial products --------
__global__ void k1_node(const float* __restrict__ h,
                        const float* __restrict__ W_in,
                        const float* __restrict__ W_o1)
{
    int node = blockIdx.x; int t = threadIdx.x;
    __shared__ float sh[FF];
    sh[t] = h[node*FF + t];
    __syncthreads();
    float p = 0.f, q = 0.f;
    #pragma unroll 8
    for (int k = 0; k < FF; k++){
        float hv = sh[k];
        p = fmaf(hv, W_o1[k*HIDN + t], p);
        q = fmaf(hv, W_o1[(FF+k)*HIDN + t], q);
    }
    g_P[node*HIDN + t] = p;
    g_Q[node*HIDN + t] = q;
    if (t < KF){
        float a = 0.f, bv = 0.f;
        #pragma unroll 8
        for (int k = 0; k < FF; k++){
            float hv = sh[k];
            a  = fmaf(hv, W_in[k*KF + t], a);
            bv = fmaf(hv, W_in[(FF+k)*KF + t], bv);
        }
        g_Ain[node*KF + t] = a;
        g_Bin[node*KF + t] = bv;
    }
}

// -------- K2: edge model (2 CTAs/SM, he in two 32-wide passes) --------
__global__ __launch_bounds__(256,2) void k2_edge(
    const float* __restrict__ x,
    const float* __restrict__ W_o1, const float* __restrict__ b_o1,
    const float* __restrict__ W_o2, const float* __restrict__ b_o2,
    const float* __restrict__ W_sem, const float* __restrict__ b_sem,
    const float* __restrict__ b_in, const float* __restrict__ means,
    const float* __restrict__ betas)
{
    int b  = blockIdx.z;
    int i0 = blockIdx.y*16, j0 = blockIdx.x*16;
    int t  = threadIdx.x;
    int ti = t >> 4, tj = t & 15;

    __shared__ __align__(16) float sA[16][KF+3];
    __shared__ __align__(16) float sB[16][KF+3];
    __shared__ __align__(16) float sP[16][68];
    __shared__ __align__(16) float sQ[16][68];
    __shared__ float sXi[16][3], sXj[16][3];
    __shared__ __align__(16) float sW1m[KF+1][HIDN];
    __shared__ __align__(16) float sW2[HIDN][HIDN];
    __shared__ float sWs[HIDN][HH];
    __shared__ float sMean[KF], sBeta[KF], sBinV[KF];
    __shared__ __align__(16) float sBo1[HIDN];
    __shared__ __align__(16) float sBo2[HIDN];
    __shared__ float sBsem[HH];

    for (int idx = t; idx < 16*KF; idx += 256){
        int r = idx / KF, c = idx - r*KF;
        sA[r][c] = g_Ain[(b*NN + j0 + r)*KF + c];
        sB[r][c] = g_Bin[(b*NN + i0 + r)*KF + c];
    }
    for (int idx = t; idx < 16*HIDN; idx += 256){
        int r = idx >> 6, c = idx & 63;
        sP[r][c] = g_P[(b*NN + j0 + r)*HIDN + c];
        sQ[r][c] = g_Q[(b*NN + i0 + r)*HIDN + c];
    }
    if (t < 48){
        int r = t/3, c = t - r*3;
        sXi[r][c] = x[(b*NN + i0 + r)*3 + c];
        sXj[r][c] = x[(b*NN + j0 + r)*3 + c];
    }
    for (int idx = t; idx < (KF+1)*HIDN; idx += 256)
        sW1m[idx>>6][idx&63] = W_o1[(128 + (idx>>6))*HIDN + (idx&63)];
    for (int idx = t; idx < HIDN*HIDN; idx += 256)
        sW2[idx>>6][idx&63] = W_o2[idx];
    if (t < HIDN*HH) sWs[t>>2][t&3] = W_sem[t];
    if (t < KF){ sMean[t] = means[t]; sBeta[t] = betas[t]; sBinV[t] = b_in[t]; }
    if (t < HIDN){ sBo1[t] = b_o1[t]; sBo2[t] = b_o2[t]; }
    if (t < HH) sBsem[t] = b_sem[t];
    __syncthreads();

    int i = i0 + ti, j = j0 + tj;
    float dx = sXj[tj][0] - sXi[ti][0];
    float dy = sXj[tj][1] - sXi[ti][1];
    float dz = sXj[tj][2] - sXi[ti][2];
    float s2 = dx*dx + dy*dy + dz*dz;
    float d  = sqrtf(s2 + 1e-5f);
    float inv = 1.0f / (d + 1e-5f);
    long pair = ((long)(b*NN + i))*NN + j;
    g_dx[pair] = make_float4(d, dx*inv, dy*inv, dz*inv);

    float cutv = (d < CUTF) ? 0.5f*(cosf(d*(PI_F/CUTF)) + 1.0f) : 0.0f;
    float em = expf(-d);

    float pre[HIDN];
    {
        const float* wd = &sW1m[KF][0];
        #pragma unroll
        for (int f = 0; f < HIDN; f++)
            pre[f] = sP[tj][f] + sQ[ti][f] + sBo1[f] + d*wd[f];
    }
    for (int c = 0; c < KF; c++){
        float h1 = sA[tj][c] + sB[ti][c] + sBinV[c];
        float dm = em - sMean[c];
        float r  = cutv * expf(-sBeta[c]*dm*dm);
        float t2 = r * h1;
        const float4* w4 = (const float4*)&sW1m[c][0];
        #pragma unroll
        for (int q2 = 0; q2 < 16; q2++){
            float4 w = w4[q2];
            pre[4*q2+0] = fmaf(t2, w.x, pre[4*q2+0]);
            pre[4*q2+1] = fmaf(t2, w.y, pre[4*q2+1]);
            pre[4*q2+2] = fmaf(t2, w.z, pre[4*q2+2]);
            pre[4*q2+3] = fmaf(t2, w.w, pre[4*q2+3]);
        }
    }
    // silu in place
    #pragma unroll
    for (int k = 0; k < HIDN; k++)
        pre[k] = pre[k] / (1.0f + expf(-pre[k]));

    float av[HH];
    #pragma unroll
    for (int hh = 0; hh < HH; hh++) av[hh] = sBsem[hh];

    // he in two 32-wide passes (keeps live regs ~pre[64]+he[32])
    #pragma unroll
    for (int hf = 0; hf < 2; hf++){
        float he[32];
        #pragma unroll
        for (int f = 0; f < 32; f++) he[f] = sBo2[hf*32 + f];
        #pragma unroll 4
        for (int k = 0; k < HIDN; k++){
            float a = pre[k];
            const float4* w4 = (const float4*)&sW2[k][hf*32];
            #pragma unroll
            for (int q2 = 0; q2 < 8; q2++){
                float4 w = w4[q2];
                he[4*q2+0] = fmaf(a, w.x, he[4*q2+0]);
                he[4*q2+1] = fmaf(a, w.y, he[4*q2+1]);
                he[4*q2+2] = fmaf(a, w.z, he[4*q2+2]);
                he[4*q2+3] = fmaf(a, w.w, he[4*q2+3]);
            }
        }
        // write bf16 pairs
        uint4* o = (uint4*)(g_heb + pair*32 + hf*16);
        #pragma unroll
        for (int q2 = 0; q2 < 4; q2++){
            uint4 w;
            w.x = pack_bf2(he[8*q2+0], he[8*q2+1]);
            w.y = pack_bf2(he[8*q2+2], he[8*q2+3]);
            w.z = pack_bf2(he[8*q2+4], he[8*q2+5]);
            w.w = pack_bf2(he[8*q2+6], he[8*q2+7]);
            o[q2] = w;
        }
        // att partial
        #pragma unroll
        for (int hh = 0; hh < HH; hh++){
            float s = av[hh];
            #pragma unroll
            for (int f = 0; f < 32; f++)
                s = fmaf(he[f], sWs[hf*32 + f][hh], s);
            av[hh] = s;
        }
    }

    #pragma unroll
    for (int hh = 0; hh < HH; hh++){
        float s = av[hh];
        s = (s > 0.f) ? s : 2.0f*expm1f(0.5f*s);
        if (i == j) s -= 1e5f;
        av[hh] = s;
    }
    *(float4*)&g_attl[pair*HH] = make_float4(av[0], av[1], av[2], av[3]);
}

// -------- K3: HMMA xmix GEMM, 2 CTAs per node (m-halves) --------
#define WROW 528
#define OFF_A    0u            // A frags (half): 4096 uint4 = 65536
#define OFF_B    65536u        // 64 * 528 = 33792 -> 99328
#define OFF_ATT  99328u        // float4[256] -> 103424
#define OFF_XH   103424u       // float4[256] -> 107520
#define OFF_RED  107520u       // float4[256] -> 111616
#define OFF_ATTP 111616u       // uint[256][2] -> 113664
#define K3_SMEM  113664u

__global__ __launch_bounds__(256,2) void k3_attn(const float* __restrict__ W_vmix)
{
    extern __shared__ char smem[];
    unsigned int sbase = smem_u32(smem);
    float4* sAtt = (float4*)(smem + OFF_ATT);
    float4* sXh  = (float4*)(smem + OFF_XH);
    float4* sRed = (float4*)(smem + OFF_RED);
    unsigned int* sAttP = (unsigned int*)(smem + OFF_ATTP);
    const uint4* sA4 = (const uint4*)(smem + OFF_A);

    int node = blockIdx.x >> 1;
    int half = blockIdx.x & 1;
    int t = threadIdx.x;
    long base = ((long)node)*NN;

    // ---- copy A-half frags into smem ----
    {
        const uint4* src = g_WtF + half*4096;
        uint4* dst = (uint4*)(smem + OFF_A);
        for (int idx = t; idx < 4096; idx += 256) dst[idx] = src[idx];
    }

    // ---- softmax over j (per head) ----
    float4 l = *(const float4*)&g_attl[(base + t)*HH];
    sRed[t] = l;
    sXh[t] = g_dx[base + t];
    __syncthreads();
    for (int s = 128; s; s >>= 1){
        if (t < s){
            float4 o2 = sRed[t+s]; float4 m = sRed[t];
            m.x = fmaxf(m.x,o2.x); m.y = fmaxf(m.y,o2.y);
            m.z = fmaxf(m.z,o2.z); m.w = fmaxf(m.w,o2.w);
            sRed[t] = m;
        }
        __syncthreads();
    }
    float4 mx = sRed[0];
    __syncthreads();
    float4 e = make_float4(expf(l.x-mx.x), expf(l.y-mx.y), expf(l.z-mx.z), expf(l.w-mx.w));
    sRed[t] = e;
    __syncthreads();
    for (int s = 128; s; s >>= 1){
        if (t < s){
            float4 o2 = sRed[t+s]; float4 m = sRed[t];
            m.x += o2.x; m.y += o2.y; m.z += o2.z; m.w += o2.w;
            sRed[t] = m;
        }
        __syncthreads();
    }
    float4 sm = sRed[0];
    __syncthreads();
    float4 att = make_float4(e.x/sm.x, e.y/sm.y, e.z/sm.z, e.w/sm.w);
    sAtt[t] = att;
    sAttP[2*t  ] = pack_bf2(att.x, att.y);
    sAttP[2*t+1] = pack_bf2(att.z, att.w);
    __syncthreads();

    // ---- he_sum (half-0 CTAs only): coalesced bf16 loads, fp32 accum ----
    if (half == 0){
        int f = t & 63, q = t >> 6;
        int sh = (f & 1)*16;
        const unsigned int* hb = g_heb + (base + q*64)*32 + (f >> 1);
        float s0=0.f, s1=0.f, s2=0.f, s3=0.f;
        #pragma unroll 4
        for (int jj = 0; jj < 64; jj++){
            unsigned int u = hb[jj*32];
            float hev = __uint_as_float(((u >> sh) & 0xFFFFu) << 16);
            float4 a4 = sAtt[q*64 + jj];
            s0 = fmaf(hev, a4.x, s0); s1 = fmaf(hev, a4.y, s1);
            s2 = fmaf(hev, a4.z, s2); s3 = fmaf(hev, a4.w, s3);
        }
        sRed[t] = make_float4(s0, s1, s2, s3);
    }
    __syncthreads();
    if (half == 0){
        int f = t >> 2, hh2 = t & 3;
        float s = ((const float*)&sRed[f])[hh2]
                + ((const float*)&sRed[64+f])[hh2]
                + ((const float*)&sRed[128+f])[hh2]
                + ((const float*)&sRed[192+f])[hh2];
        g_hesum[node*CC + t] = s;
    }
    __syncthreads();

    int lane = t & 31, warp = t >> 5;
    int g = lane >> 2, tig = lane & 3;
    // ldmatrix.x4 base: lanes 0-7 -> (n, k-lo), 8-15 -> (n, k-hi),
    //                   16-23 -> (n+1, k-lo), 24-31 -> (n+1, k-hi)
    unsigned int bBase4 = sbase + OFF_B + (unsigned)((lane & 7))*WROW
                        + (unsigned)(((lane >> 3) & 1)*16)
                        + (unsigned)(((lane >> 4) & 1)*(8*WROW));

    float cs[2][3];
    cs[0][0]=cs[0][1]=cs[0][2]=cs[1][0]=cs[1][1]=cs[1][2]=0.f;

    int jl = t & 63, ch0 = t >> 6, ch1 = ch0 + 4;   // this thread's j-row + 2 chunks

    for (int jb = 0; jb < 4; jb++){
        // ---- vectorized B-build: B[j][c] = he_bf16[j,f] * attP[j,hpair] ----
        {
            const uint4* heRow = (const uint4*)(g_heb + (base + jb*64 + jl)*32);
            uint4 u0 = heRow[ch0];
            uint4 u1 = heRow[ch1];
            int ja = jb*64 + jl;
            unsigned int ap0 = sAttP[2*ja], ap1 = sAttP[2*ja+1];
            char* brow = smem + OFF_B + jl*WROW;
            unsigned int dd; uint4 o;
            #define BPAIR(uu, chv, comp) { \
                dd = __byte_perm(uu, uu, 0x1010); o.x = hmul2(dd, ap0); o.y = hmul2(dd, ap1); \
                dd = __byte_perm(uu, uu, 0x3232); o.z = hmul2(dd, ap0); o.w = hmul2(dd, ap1); \
                *(uint4*)(brow + (chv)*64 + (comp)*16) = o; }
            BPAIR(u0.x, ch0, 0) BPAIR(u0.y, ch0, 1) BPAIR(u0.z, ch0, 2) BPAIR(u0.w, ch0, 3)
            BPAIR(u1.x, ch1, 0) BPAIR(u1.y, ch1, 1) BPAIR(u1.z, ch1, 2) BPAIR(u1.w, ch1, 3)
            #undef BPAIR
        }
        __syncthreads();

        float acc[32];
        #pragma unroll
        for (int q = 0; q < 32; q++) acc[q] = 0.f;

        #pragma unroll 4
        for (int k = 0; k < 16; k++){
            uint4 aF = sA4[(warp*16 + k)*32 + lane];
            #pragma unroll
            for (int np = 0; np < 4; np++){
                unsigned int bfr[4];
                LDSM_X4(bfr, bBase4 + (unsigned)(np*16*WROW + k*32));
                MMA16816(acc + np*8,     (unsigned int*)&aF, bfr[0], bfr[1]);
                MMA16816(acc + np*8 + 4, (unsigned int*)&aF, bfr[2], bfr[3]);
            }
        }

        // epilogue: tanh + cs accumulation
        #pragma unroll
        for (int n = 0; n < 8; n++){
            int j0 = jb*64 + n*8 + tig*2;
            float4 x0 = sXh[j0], x1 = sXh[j0+1];
            float t0 = tanhfast(acc[n*4+0]);
            float t1 = tanhfast(acc[n*4+1]);
            float t2 = tanhfast(acc[n*4+2]);
            float t3 = tanhfast(acc[n*4+3]);
            cs[0][0] = fmaf(t0, x0.y, fmaf(t1, x1.y, cs[0][0]));
            cs[0][1] = fmaf(t0, x0.z, fmaf(t1, x1.z, cs[0][1]));
            cs[0][2] = fmaf(t0, x0.w, fmaf(t1, x1.w, cs[0][2]));
            cs[1][0] = fmaf(t2, x0.y, fmaf(t3, x1.y, cs[1][0]));
            cs[1][1] = fmaf(t2, x0.z, fmaf(t3, x1.z, cs[1][1]));
            cs[1][2] = fmaf(t2, x0.w, fmaf(t3, x1.w, cs[1][2]));
        }
        __syncthreads();
    }

    // reduce cs over the quad (lanes with same g share c' rows)
    #pragma unroll
    for (int r = 0; r < 2; r++)
        #pragma unroll
        for (int q = 0; q < 3; q++){
            float v = cs[r][q];
            v += __shfl_xor_sync(0xFFFFFFFFu, v, 1);
            v += __shfl_xor_sync(0xFFFFFFFFu, v, 2);
            cs[r][q] = v;
        }

    const float invn = 1.0f/(float)NN;
    float pd0 = 0.f, pd1 = 0.f, pd2 = 0.f;
    if (tig == 0){
        #pragma unroll
        for (int r = 0; r < 2; r++){
            int cpr = half*128 + warp*16 + r*8 + g;
            float a  = cs[r][0]*invn;
            float b2 = cs[r][1]*invn;
            float c2 = cs[r][2]*invn;
            g_cn[node*CC + cpr] = a*a + b2*b2 + c2*c2;
            float wv = W_vmix[cpr];
            pd0 = fmaf(a, wv, pd0);
            pd1 = fmaf(b2, wv, pd1);
            pd2 = fmaf(c2, wv, pd2);
        }
    }
    __syncthreads();
    sRed[t] = make_float4(pd0, pd1, pd2, 0.f);
    __syncthreads();
    for (int s = 128; s; s >>= 1){
        if (t < s){
            float4 o2 = sRed[t+s]; float4 m2 = sRed[t];
            m2.x += o2.x; m2.y += o2.y; m2.z += o2.z;
            sRed[t] = m2;
        }
        __syncthreads();
    }
    if (t == 0){
        float4 r = sRed[0];
        g_dvp[node*8 + half*4 + 0] = r.x;
        g_dvp[node*8 + half*4 + 1] = r.y;
        g_dvp[node*8 + half*4 + 2] = r.z;
    }
}

// -------- K4: node MLPs + outputs (4-way k-split, 256 threads) --------
__global__ __launch_bounds__(256) void k4_node(
    const float* __restrict__ h, const float* __restrict__ x, const float* __restrict__ v,
    const float* __restrict__ W_p1, const float* __restrict__ b_p1,
    const float* __restrict__ W_p2, const float* __restrict__ b_p2,
    const float* __restrict__ W_n1, const float* __restrict__ b_n1,
    const float* __restrict__ W_n2, const float* __restrict__ b_n2,
    const float* __restrict__ W_v1, const float* __restrict__ b_v1,
    const float* __restrict__ W_v2, float* __restrict__ out)
{
    int node = blockIdx.x; int t = threadIdx.x;
    int to = t & 63, ko = t >> 6;
    __shared__ float sIn[384];        // [h(64) | hesum(256) | hcomb(64)]
    __shared__ float sCn[CC];
    __shared__ float sAcc[256];
    __shared__ float sX[HIDN], sY[HIDN];
    __shared__ float sFin[2];

    if (t < 64) sIn[t] = h[node*FF + t];
    for (int k = t; k < CC; k += 256){
        sIn[64 + k] = g_hesum[node*CC + k];
        sCn[k] = g_cn[node*CC + k];
    }
    __syncthreads();

    // p1: 256 -> 64
    {
        float acc = 0.f;
        int k0 = ko*64;
        #pragma unroll 8
        for (int k = 0; k < 64; k++)
            acc = fmaf(sCn[k0+k], W_p1[(k0+k)*HIDN + to], acc);
        sAcc[t] = acc;
    }
    __syncthreads();
    if (ko == 0)
        sX[to] = siluf(b_p1[to] + sAcc[to] + sAcc[64+to] + sAcc[128+to] + sAcc[192+to]);
    __syncthreads();
    // p2: 64 -> 64 (h_comb)
    {
        float acc = 0.f;
        int k0 = ko*16;
        #pragma unroll
        for (int k = 0; k < 16; k++)
            acc = fmaf(sX[k0+k], W_p2[(k0+k)*HIDN + to], acc);
        sAcc[t] = acc;
    }
    __syncthreads();
    if (ko == 0)
        sIn[320 + to] = siluf(b_p2[to] + sAcc[to] + sAcc[64+to] + sAcc[128+to] + sAcc[192+to]);
    __syncthreads();
    // n1: 384 -> 64
    {
        float acc = 0.f;
        int k0 = ko*96;
        #pragma unroll 8
        for (int k = 0; k < 96; k++)
            acc = fmaf(sIn[k0+k], W_n1[(k0+k)*HIDN + to], acc);
        sAcc[t] = acc;
    }
    __syncthreads();
    if (ko == 0)
        sX[to] = siluf(b_n1[to] + sAcc[to] + sAcc[64+to] + sAcc[128+to] + sAcc[192+to]);
    __syncthreads();
    // n2: 64 -> 64, residual -> h_new
    {
        float acc = 0.f;
        int k0 = ko*16;
        #pragma unroll
        for (int k = 0; k < 16; k++)
            acc = fmaf(sX[k0+k], W_n2[(k0+k)*HIDN + to], acc);
        sAcc[t] = acc;
    }
    __syncthreads();
    if (ko == 0){
        float hn = sIn[to] + siluf(b_n2[to] + sAcc[to] + sAcc[64+to] + sAcc[128+to] + sAcc[192+to]);
        sY[to] = hn;
        out[node*FF + to] = hn;
    }
    __syncthreads();
    // v1: 64 -> 64
    {
        float acc = 0.f;
        int k0 = ko*16;
        #pragma unroll
        for (int k = 0; k < 16; k++)
            acc = fmaf(sY[k0+k], W_v1[(k0+k)*HIDN + to], acc);
        sAcc[t] = acc;
    }
    __syncthreads();
    if (ko == 0)
        sX[to] = siluf(b_v1[to] + sAcc[to] + sAcc[64+to] + sAcc[128+to] + sAcc[192+to]) * W_v2[to];
    __syncthreads();
    if (t < 32){
        float s = sX[t] + sX[t+32];
        #pragma unroll
        for (int o2 = 16; o2; o2 >>= 1)
            s += __shfl_xor_sync(0xFFFFFFFFu, s, o2);
        if (t == 0) sFin[0] = s;
    }
    __syncthreads();
    if (t < 3){
        float vs = 2.0f/(1.0f + expf(-sFin[0]));
        float vn = g_dvp[node*8 + t] + g_dvp[node*8 + 4 + t] + vs * v[node*3 + t];
        out[NODES*FF + node*3 + t]            = x[node*3 + t] + vn;
        out[NODES*FF + NODES*3 + node*3 + t]  = vn;
    }
}

extern "C" void kernel_launch(void* const* d_in, const int* in_sizes, int n_in,
                              void* d_out, int out_size)
{
    const float* h      = (const float*)d_in[0];
    const float* x      = (const float*)d_in[1];
    const float* v      = (const float*)d_in[2];
    const float* W_in   = (const float*)d_in[3];
    const float* b_in   = (const float*)d_in[4];
    const float* means  = (const float*)d_in[5];
    const float* betas  = (const float*)d_in[6];
    const float* W_o1   = (const float*)d_in[7];
    const float* b_o1   = (const float*)d_in[8];
    const float* W_o2   = (const float*)d_in[9];
    const float* b_o2   = (const float*)d_in[10];
    const float* W_sem  = (const float*)d_in[11];
    const float* b_sem  = (const float*)d_in[12];
    const float* W_xmix = (const float*)d_in[13];
    const float* W_p1   = (const float*)d_in[14];
    const float* b_p1   = (const float*)d_in[15];
    const float* W_p2   = (const float*)d_in[16];
    const float* b_p2   = (const float*)d_in[17];
    const float* W_n1   = (const float*)d_in[18];
    const float* b_n1   = (const float*)d_in[19];
    const float* W_n2   = (const float*)d_in[20];
    const float* b_n2   = (const float*)d_in[21];
    const float* W_v1   = (const float*)d_in[22];
    const float* b_v1   = (const float*)d_in[23];
    const float* W_v2   = (const float*)d_in[24];
    const float* W_vmix = (const float*)d_in[25];
    float* out = (float*)d_out;

    static int smem_set = 0;
    if (!smem_set){
        cudaFuncSetAttribute(k3_attn, cudaFuncAttributeMaxDynamicSharedMemorySize, K3_SMEM);
        smem_set = 1;
    }

    k0_wt<<<32, 256>>>(W_xmix);
    k1_node<<<NODES, 64>>>(h, W_in, W_o1);
    dim3 g2(NN/16, NN/16, BB);
    k2_edge<<<g2, 256>>>(x, W_o1, b_o1, W_o2, b_o2, W_sem, b_sem, b_in, means, betas);
    k3_attn<<<NODES*2, 256, K3_SMEM>>>(W_vmix);
    k4_node<<<NODES, 256>>>(h, x, v, W_p1, b_p1, W_p2, b_p2,
                            W_n1, b_n1, W_n2, b_n2, W_v1, b_v1, W_v2, out);
}

// round 12
// speedup vs baseline: 5.4429x; 1.3444x over previous
#include <cuda_runtime.h>
#include <math.h>

#define BB 2
#define NN 256
#define FF 64
#define HH 4
#define HIDN 64
#define CC 256
#define KF 50
#define NODES (BB*NN)
#define CUTF 5.0f
#define PI_F 3.14159265358979f

// -------- scratch (device globals; no runtime allocation) --------
__device__ float g_Ain[NODES*KF];
__device__ float g_Bin[NODES*KF];
__device__ float g_P[NODES*HIDN];
__device__ float g_Q[NODES*HIDN];
__device__ unsigned int g_heb[(long)BB*NN*NN*32];  // h_e bf16 pairs (16 MB)
__device__ float g_attl[(long)BB*NN*NN*HH];        // att logits
__device__ float4 g_dx[(long)BB*NN*NN];            // (d, xhat)
__device__ float g_hesum[NODES*CC];
__device__ float g_cn[NODES*CC];
__device__ float g_dvp[NODES*8];                   // dv partials (2 halves)
// W_xmix^T in per-lane mma bf16 fragment layout
__device__ uint4 g_WtF[8192];
// W_o1[128:179] and W_o2 in per-lane tf32 B-fragment layout
__device__ uint2 g_Wf[4096];

__device__ __forceinline__ float siluf(float v){ return v/(1.0f+expf(-v)); }
__device__ __forceinline__ float silu_fast(float v){
    return v * __fdividef(1.0f, 1.0f + __expf(-v));
}

__device__ __forceinline__ unsigned int pack_bf2(float lo, float hi){
    unsigned int r;
    asm("cvt.rn.bf16x2.f32 %0, %1, %2;" : "=r"(r) : "f"(hi), "f"(lo));
    return r;
}
__device__ __forceinline__ unsigned int hmul2(unsigned int a, unsigned int b){
    unsigned int r;
    asm("mul.rn.bf16x2 %0, %1, %2;" : "=r"(r) : "r"(a), "r"(b));
    return r;
}
__device__ __forceinline__ unsigned int smem_u32(const void* p){
    unsigned int a;
    asm("{ .reg .u64 t; cvta.to.shared.u64 t, %1; cvt.u32.u64 %0, t; }" : "=r"(a) : "l"(p));
    return a;
}
__device__ __forceinline__ float tanhfast(float x){
    float r; asm("tanh.approx.f32 %0, %1;" : "=f"(r) : "f"(x)); return r;
}
#define CVT_TF32(o, f) asm("cvt.rna.tf32.f32 %0, %1;" : "=r"(o) : "f"(f))
#define LDSM_X4(R, addr) \
    asm volatile("ldmatrix.sync.aligned.m8n8.x4.shared.b16 {%0,%1,%2,%3}, [%4];" \
        : "=r"((R)[0]),"=r"((R)[1]),"=r"((R)[2]),"=r"((R)[3]) : "r"(addr))
#define MMA16816(D, A, B0, B1) \
    asm volatile("mma.sync.aligned.m16n8k16.row.col.f32.bf16.bf16.f32 " \
        "{%0,%1,%2,%3}, {%4,%5,%6,%7}, {%8,%9}, {%0,%1,%2,%3};" \
        : "+f"((D)[0]),"+f"((D)[1]),"+f"((D)[2]),"+f"((D)[3]) \
        : "r"((A)[0]),"r"((A)[1]),"r"((A)[2]),"r"((A)[3]),"r"(B0),"r"(B1))
#define MMATF32(D, a0,a1,a2,a3, b0,b1) \
    asm volatile("mma.sync.aligned.m16n8k8.row.col.f32.tf32.tf32.f32 " \
        "{%0,%1,%2,%3}, {%4,%5,%6,%7}, {%8,%9}, {%0,%1,%2,%3};" \
        : "+f"((D)[0]),"+f"((D)[1]),"+f"((D)[2]),"+f"((D)[3]) \
        : "r"(a0),"r"(a1),"r"(a2),"r"(a3),"r"(b0),"r"(b1))

// -------- K0: W_xmix^T bf16 in mma fragment layout --------
__global__ void k0_wt(const float* __restrict__ W){
    int idx = blockIdx.x*256 + threadIdx.x;
    int lane = idx & 31;
    int k = (idx >> 5) & 15;
    int mt = idx >> 9;
    int g = lane >> 2, tig = lane & 3;
    int r0 = mt*16 + g, r1 = r0 + 8;
    int cp0 = k*8 + tig, cp1 = cp0 + 4;
    uint4 f;
    f.x = pack_bf2(W[(2*cp0)*CC + r0], W[(2*cp0+1)*CC + r0]);
    f.y = pack_bf2(W[(2*cp0)*CC + r1], W[(2*cp0+1)*CC + r1]);
    f.z = pack_bf2(W[(2*cp1)*CC + r0], W[(2*cp1+1)*CC + r0]);
    f.w = pack_bf2(W[(2*cp1)*CC + r1], W[(2*cp1+1)*CC + r1]);
    g_WtF[idx] = f;
}

// -------- K0b: W1 (= W_o1 rows 128..178, zero-pad to 64) and W2 as tf32 B frags --------
__global__ void k0b_wf(const float* __restrict__ W_o1, const float* __restrict__ W_o2){
    int idx = blockIdx.x*256 + threadIdx.x;   // 0..4095
    int lane = idx & 31;
    int nt = (idx >> 5) & 7;
    int kt = (idx >> 8) & 7;
    int m  = idx >> 11;
    int g = lane >> 2, tig = lane & 3;
    int k0 = kt*8 + tig, k1 = k0 + 4, n = nt*8 + g;
    float v0, v1;
    if (m == 0){
        v0 = (k0 <= 50) ? W_o1[(128 + k0)*HIDN + n] : 0.f;
        v1 = (k1 <= 50) ? W_o1[(128 + k1)*HIDN + n] : 0.f;
    } else {
        v0 = W_o2[k0*HIDN + n];
        v1 = W_o2[k1*HIDN + n];
    }
    unsigned u0, u1;
    CVT_TF32(u0, v0); CVT_TF32(u1, v1);
    g_Wf[m*2048 + (kt*8 + nt)*32 + lane] = make_uint2(u0, u1);
}

// -------- K1: per-node partial products --------
__global__ void k1_node(const float* __restrict__ h,
                        const float* __restrict__ W_in,
                        const float* __restrict__ W_o1)
{
    int node = blockIdx.x; int t = threadIdx.x;
    __shared__ float sh[FF];
    sh[t] = h[node*FF + t];
    __syncthreads();
    float p = 0.f, q = 0.f;
    #pragma unroll 8
    for (int k = 0; k < FF; k++){
        float hv = sh[k];
        p = fmaf(hv, W_o1[k*HIDN + t], p);
        q = fmaf(hv, W_o1[(FF+k)*HIDN + t], q);
    }
    g_P[node*HIDN + t] = p;
    g_Q[node*HIDN + t] = q;
    if (t < KF){
        float a = 0.f, bv = 0.f;
        #pragma unroll 8
        for (int k = 0; k < FF; k++){
            float hv = sh[k];
            a  = fmaf(hv, W_in[k*KF + t], a);
            bv = fmaf(hv, W_in[(FF+k)*KF + t], bv);
        }
        g_Ain[node*KF + t] = a;
        g_Bin[node*KF + t] = bv;
    }
}

// -------- K2: edge model via tf32 MMA --------
#define K2_OFF_A1   0u
#define K2_OFF_W1   32768u
#define K2_OFF_W2   49152u
#define K2_OFF_P    65536u
#define K2_OFF_Q    69888u
#define K2_OFF_AIN  72064u
#define K2_OFF_BIN  75392u
#define K2_OFF_WS   77056u
#define K2_OFF_BO1  78080u
#define K2_OFF_MEAN 78336u
#define K2_OFF_BETA 78544u
#define K2_OFF_BINV 78752u
#define K2_OFF_XI   78960u
#define K2_OFF_XJ   79088u
#define K2_OFF_BSEM 79344u
#define K2_SMEM     79360u

__global__ __launch_bounds__(256,2) void k2_edge(
    const float* __restrict__ x,
    const float* __restrict__ b_o1, const float* __restrict__ b_in,
    const float* __restrict__ means, const float* __restrict__ betas,
    const float* __restrict__ W_sem, const float* __restrict__ b_sem)
{
    extern __shared__ char smem[];
    int b  = blockIdx.z;
    int i0 = blockIdx.y*8, j0 = blockIdx.x*16;
    int t  = threadIdx.x;

    float* sP   = (float*)(smem + K2_OFF_P);     // [16][68]
    float* sQ   = (float*)(smem + K2_OFF_Q);     // [8][68]
    float* sAin = (float*)(smem + K2_OFF_AIN);   // [16][52]
    float* sBin = (float*)(smem + K2_OFF_BIN);   // [8][52]
    float4* sWs = (float4*)(smem + K2_OFF_WS);   // [64]
    float* sBo1 = (float*)(smem + K2_OFF_BO1);
    float* sMean= (float*)(smem + K2_OFF_MEAN);
    float* sBeta= (float*)(smem + K2_OFF_BETA);
    float* sBinV= (float*)(smem + K2_OFF_BINV);
    float* sXi  = (float*)(smem + K2_OFF_XI);    // [8][4]
    float* sXj  = (float*)(smem + K2_OFF_XJ);    // [16][4]

    // ---- fills (ALL loops strided; 256 threads only!) ----
    for (int idx = t; idx < 1024; idx += 256){
        ((uint4*)(smem + K2_OFF_W1))[idx] = ((const uint4*)g_Wf)[idx];
        ((uint4*)(smem + K2_OFF_W2))[idx] = ((const uint4*)g_Wf)[1024 + idx];
        sP[(idx >> 6)*68 + (idx & 63)] = g_P[(b*NN + j0 + (idx >> 6))*HIDN + (idx & 63)];
    }
    for (int idx = t; idx < 512; idx += 256)
        sQ[(idx >> 6)*68 + (idx & 63)] = g_Q[(b*NN + i0 + (idx >> 6))*HIDN + (idx & 63)];
    for (int idx = t; idx < 800; idx += 256){
        int r = idx/50, c = idx - r*50;
        sAin[r*52 + c] = g_Ain[(b*NN + j0 + r)*KF + c];
    }
    for (int idx = t; idx < 400; idx += 256){
        int r = idx/50, c = idx - r*50;
        sBin[r*52 + c] = g_Bin[(b*NN + i0 + r)*KF + c];
    }
    if (t < 64){
        sWs[t] = ((const float4*)W_sem)[t];
        sBo1[t] = b_o1[t];
    }
    if (t < 50){ sMean[t] = means[t]; sBeta[t] = betas[t]; sBinV[t] = b_in[t]; }
    if (t < 48){ int r = t/3, c = t - r*3; sXj[r*4 + c] = x[(b*NN + j0 + r)*3 + c]; }
    else if (t < 72){ int u = t - 48; int r = u/3, c = u - r*3; sXi[r*4 + c] = x[(b*NN + i0 + r)*3 + c]; }
    if (t == 0) *(float4*)(smem + K2_OFF_BSEM) = *(const float4*)b_sem;
    // zero A1 kt 6,7 (c = 51..63 padding region)
    {
        uint4 z = make_uint4(0,0,0,0);
        for (int idx = t; idx < 512; idx += 256){
            int mt = idx >> 6, rest = idx & 63;
            ((uint4*)(smem + K2_OFF_A1))[(mt*8 + 6 + (rest >> 5))*32 + (rest & 31)] = z;
        }
    }
    __syncthreads();

    // ---- per-pair scalar build of A1 (tf32 frag layout), d, g_dx ----
    {
        int p = t & 127, bh = t >> 7;
        int il = p >> 4, jl = p & 15;
        float dxv = sXj[jl*4+0] - sXi[il*4+0];
        float dyv = sXj[jl*4+1] - sXi[il*4+1];
        float dzv = sXj[jl*4+2] - sXi[il*4+2];
        float d = sqrtf(dxv*dxv + dyv*dyv + dzv*dzv + 1e-5f);
        float cutv = (d < CUTF) ? 0.5f*(__cosf(d*(PI_F/CUTF)) + 1.0f) : 0.f;
        float em = __expf(-d);
        int gg = jl & 7, regRow = jl >> 3;
        unsigned base1 = (unsigned)(il*8)*512u + (unsigned)(gg*4)*16u + (unsigned)regRow*4u;
        if (bh){
            long pair = ((long)(b*NN + i0 + il))*NN + j0 + jl;
            float inv = 1.0f/(d + 1e-5f);
            g_dx[pair] = make_float4(d, dxv*inv, dyv*inv, dzv*inv);
        }
        int c0 = bh ? 26 : 0, c1 = bh ? 51 : 26;
        for (int c = c0; c < c1; c++){
            float val;
            if (c == 50) val = d;
            else {
                float h1 = sAin[jl*52 + c] + sBin[il*52 + c] + sBinV[c];
                float dm = em - sMean[c];
                val = cutv * __expf(-sBeta[c]*dm*dm) * h1;
            }
            unsigned r32; CVT_TF32(r32, val);
            unsigned addr = K2_OFF_A1 + base1 + (unsigned)((c >> 3))*512u
                          + (unsigned)(c & 3)*16u + (unsigned)((c >> 2) & 1)*8u;
            *(unsigned*)(smem + addr) = r32;
        }
    }
    __syncthreads();

    int lane = t & 31, warp = t >> 5;   // warp = m-tile = i-local
    int g2 = lane >> 2, tig = lane & 3;
    const uint4* A1v = (const uint4*)(smem + K2_OFF_A1);
    const uint2* W1v = (const uint2*)(smem + K2_OFF_W1);
    const uint2* W2v = (const uint2*)(smem + K2_OFF_W2);

    // ---- GEMM1: pre = A1 @ W1 ----
    float acc1[8][4];
    #pragma unroll
    for (int n = 0; n < 8; n++){ acc1[n][0]=acc1[n][1]=acc1[n][2]=acc1[n][3]=0.f; }
    #pragma unroll
    for (int kt = 0; kt < 8; kt++){
        uint4 aF = A1v[(warp*8 + kt)*32 + lane];
        #pragma unroll
        for (int nt = 0; nt < 8; nt++){
            uint2 bF = W1v[(kt*8 + nt)*32 + lane];
            MMATF32(acc1[nt], aF.x, aF.y, aF.z, aF.w, bF.x, bF.y);
        }
    }
    // ---- base + silu ----
    #pragma unroll
    for (int nt = 0; nt < 8; nt++){
        int f0 = nt*8 + tig*2;
        float q0 = sQ[warp*68 + f0]   + sBo1[f0];
        float q1 = sQ[warp*68 + f0+1] + sBo1[f0+1];
        acc1[nt][0] = silu_fast(acc1[nt][0] + sP[g2*68 + f0]       + q0);
        acc1[nt][1] = silu_fast(acc1[nt][1] + sP[g2*68 + f0+1]     + q1);
        acc1[nt][2] = silu_fast(acc1[nt][2] + sP[(g2+8)*68 + f0]   + q0);
        acc1[nt][3] = silu_fast(acc1[nt][3] + sP[(g2+8)*68 + f0+1] + q1);
    }
    // ---- GEMM2: he = silu(pre) @ W2, A-frags via in-register repack ----
    float acc2[8][4];
    #pragma unroll
    for (int n = 0; n < 8; n++){ acc2[n][0]=acc2[n][1]=acc2[n][2]=acc2[n][3]=0.f; }
    int s0 = (lane & ~3) | (tig >> 1);
    int s1 = s0 + 2;
    bool odd = (tig & 1);
    #pragma unroll
    for (int kt = 0; kt < 8; kt++){
        float v0 = __shfl_sync(0xFFFFFFFFu, acc1[kt][0], s0);
        float v1 = __shfl_sync(0xFFFFFFFFu, acc1[kt][1], s0);
        float v2 = __shfl_sync(0xFFFFFFFFu, acc1[kt][2], s0);
        float v3 = __shfl_sync(0xFFFFFFFFu, acc1[kt][3], s0);
        float w0 = __shfl_sync(0xFFFFFFFFu, acc1[kt][0], s1);
        float w1 = __shfl_sync(0xFFFFFFFFu, acc1[kt][1], s1);
        float w2 = __shfl_sync(0xFFFFFFFFu, acc1[kt][2], s1);
        float w3 = __shfl_sync(0xFFFFFFFFu, acc1[kt][3], s1);
        unsigned a0, a1, a2, a3;
        CVT_TF32(a0, odd ? v1 : v0);
        CVT_TF32(a1, odd ? v3 : v2);
        CVT_TF32(a2, odd ? w1 : w0);
        CVT_TF32(a3, odd ? w3 : w2);
        #pragma unroll
        for (int nt = 0; nt < 8; nt++){
            uint2 bF = W2v[(kt*8 + nt)*32 + lane];
            MMATF32(acc2[nt], a0, a1, a2, a3, bF.x, bF.y);
        }
    }
    // ---- epilogue: write he (bf16), att logits ----
    long rowPair0 = ((long)(b*NN + i0 + warp))*NN + j0 + g2;
    long rowPair1 = rowPair0 + 8;
    float l00=0.f,l01=0.f,l02=0.f,l03=0.f;
    float l10=0.f,l11=0.f,l12=0.f,l13=0.f;
    #pragma unroll
    for (int nt = 0; nt < 8; nt++){
        int f0 = nt*8 + tig*2;
        float h00 = acc2[nt][0], h01 = acc2[nt][1];
        float h10 = acc2[nt][2], h11 = acc2[nt][3];
        g_heb[rowPair0*32 + (f0 >> 1)] = pack_bf2(h00, h01);
        g_heb[rowPair1*32 + (f0 >> 1)] = pack_bf2(h10, h11);
        float4 ws0 = sWs[f0], ws1 = sWs[f0+1];
        l00 = fmaf(h00, ws0.x, fmaf(h01, ws1.x, l00));
        l01 = fmaf(h00, ws0.y, fmaf(h01, ws1.y, l01));
        l02 = fmaf(h00, ws0.z, fmaf(h01, ws1.z, l02));
        l03 = fmaf(h00, ws0.w, fmaf(h01, ws1.w, l03));
        l10 = fmaf(h10, ws0.x, fmaf(h11, ws1.x, l10));
        l11 = fmaf(h10, ws0.y, fmaf(h11, ws1.y, l11));
        l12 = fmaf(h10, ws0.z, fmaf(h11, ws1.z, l12));
        l13 = fmaf(h10, ws0.w, fmaf(h11, ws1.w, l13));
    }
    #define QRED(v) v += __shfl_xor_sync(0xFFFFFFFFu, v, 1); v += __shfl_xor_sync(0xFFFFFFFFu, v, 2);
    QRED(l00) QRED(l01) QRED(l02) QRED(l03)
    QRED(l10) QRED(l11) QRED(l12) QRED(l13)
    #undef QRED
    if (tig == 0){
        float4 bsem = *(float4*)(smem + K2_OFF_BSEM);
        float r0[4] = {l00 + bsem.x, l01 + bsem.y, l02 + bsem.z, l03 + bsem.w};
        float r1[4] = {l10 + bsem.x, l11 + bsem.y, l12 + bsem.z, l13 + bsem.w};
        #pragma unroll
        for (int hh = 0; hh < 4; hh++){
            r0[hh] = (r0[hh] > 0.f) ? r0[hh] : 2.0f*(__expf(0.5f*r0[hh]) - 1.0f);
            r1[hh] = (r1[hh] > 0.f) ? r1[hh] : 2.0f*(__expf(0.5f*r1[hh]) - 1.0f);
        }
        if (i0 + warp == j0 + g2)     { r0[0]-=1e5f; r0[1]-=1e5f; r0[2]-=1e5f; r0[3]-=1e5f; }
        if (i0 + warp == j0 + g2 + 8) { r1[0]-=1e5f; r1[1]-=1e5f; r1[2]-=1e5f; r1[3]-=1e5f; }
        *(float4*)&g_attl[rowPair0*HH] = make_float4(r0[0], r0[1], r0[2], r0[3]);
        *(float4*)&g_attl[rowPair1*HH] = make_float4(r1[0], r1[1], r1[2], r1[3]);
    }
}

// -------- K3: HMMA xmix GEMM, 2 CTAs per node (m-halves) --------
#define WROW 528
#define OFF_A    0u
#define OFF_B    65536u
#define OFF_ATT  99328u
#define OFF_XH   103424u
#define OFF_RED  107520u
#define OFF_ATTP 111616u
#define K3_SMEM  113664u

__global__ __launch_bounds__(256,2) void k3_attn(const float* __restrict__ W_vmix)
{
    extern __shared__ char smem[];
    unsigned int sbase = smem_u32(smem);
    float4* sAtt = (float4*)(smem + OFF_ATT);
    float4* sXh  = (float4*)(smem + OFF_XH);
    float4* sRed = (float4*)(smem + OFF_RED);
    unsigned int* sAttP = (unsigned int*)(smem + OFF_ATTP);
    const uint4* sA4 = (const uint4*)(smem + OFF_A);

    int node = blockIdx.x >> 1;
    int half = blockIdx.x & 1;
    int t = threadIdx.x;
    long base = ((long)node)*NN;

    {
        const uint4* src = g_WtF + half*4096;
        uint4* dst = (uint4*)(smem + OFF_A);
        for (int idx = t; idx < 4096; idx += 256) dst[idx] = src[idx];
    }

    float4 l = *(const float4*)&g_attl[(base + t)*HH];
    sRed[t] = l;
    sXh[t] = g_dx[base + t];
    __syncthreads();
    for (int s = 128; s; s >>= 1){
        if (t < s){
            float4 o2 = sRed[t+s]; float4 m = sRed[t];
            m.x = fmaxf(m.x,o2.x); m.y = fmaxf(m.y,o2.y);
            m.z = fmaxf(m.z,o2.z); m.w = fmaxf(m.w,o2.w);
            sRed[t] = m;
        }
        __syncthreads();
    }
    float4 mx = sRed[0];
    __syncthreads();
    float4 e = make_float4(expf(l.x-mx.x), expf(l.y-mx.y), expf(l.z-mx.z), expf(l.w-mx.w));
    sRed[t] = e;
    __syncthreads();
    for (int s = 128; s; s >>= 1){
        if (t < s){
            float4 o2 = sRed[t+s]; float4 m = sRed[t];
            m.x += o2.x; m.y += o2.y; m.z += o2.z; m.w += o2.w;
            sRed[t] = m;
        }
        __syncthreads();
    }
    float4 sm = sRed[0];
    __syncthreads();
    float4 att = make_float4(e.x/sm.x, e.y/sm.y, e.z/sm.z, e.w/sm.w);
    sAtt[t] = att;
    sAttP[2*t  ] = pack_bf2(att.x, att.y);
    sAttP[2*t+1] = pack_bf2(att.z, att.w);
    __syncthreads();

    if (half == 0){
        int f = t & 63, q = t >> 6;
        int sh = (f & 1)*16;
        const unsigned int* hb = g_heb + (base + q*64)*32 + (f >> 1);
        float s0=0.f, s1=0.f, s2=0.f, s3=0.f;
        #pragma unroll 4
        for (int jj = 0; jj < 64; jj++){
            unsigned int u = hb[jj*32];
            float hev = __uint_as_float(((u >> sh) & 0xFFFFu) << 16);
            float4 a4 = sAtt[q*64 + jj];
            s0 = fmaf(hev, a4.x, s0); s1 = fmaf(hev, a4.y, s1);
            s2 = fmaf(hev, a4.z, s2); s3 = fmaf(hev, a4.w, s3);
        }
        sRed[t] = make_float4(s0, s1, s2, s3);
    }
    __syncthreads();
    if (half == 0){
        int f = t >> 2, hh2 = t & 3;
        float s = ((const float*)&sRed[f])[hh2]
                + ((const float*)&sRed[64+f])[hh2]
                + ((const float*)&sRed[128+f])[hh2]
                + ((const float*)&sRed[192+f])[hh2];
        g_hesum[node*CC + t] = s;
    }
    __syncthreads();

    int lane = t & 31, warp = t >> 5;
    int g = lane >> 2, tig = lane & 3;
    unsigned int bBase4 = sbase + OFF_B + (unsigned)((lane & 7))*WROW
                        + (unsigned)(((lane >> 3) & 1)*16)
                        + (unsigned)(((lane >> 4) & 1)*(8*WROW));

    float cs[2][3];
    cs[0][0]=cs[0][1]=cs[0][2]=cs[1][0]=cs[1][1]=cs[1][2]=0.f;

    int jl = t & 63, ch0 = t >> 6, ch1 = ch0 + 4;

    for (int jb = 0; jb < 4; jb++){
        {
            const uint4* heRow = (const uint4*)(g_heb + (base + jb*64 + jl)*32);
            uint4 u0 = heRow[ch0];
            uint4 u1 = heRow[ch1];
            int ja = jb*64 + jl;
            unsigned int ap0 = sAttP[2*ja], ap1 = sAttP[2*ja+1];
            char* brow = smem + OFF_B + jl*WROW;
            unsigned int dd; uint4 o;
            #define BPAIR(uu, chv, comp) { \
                dd = __byte_perm(uu, uu, 0x1010); o.x = hmul2(dd, ap0); o.y = hmul2(dd, ap1); \
                dd = __byte_perm(uu, uu, 0x3232); o.z = hmul2(dd, ap0); o.w = hmul2(dd, ap1); \
                *(uint4*)(brow + (chv)*64 + (comp)*16) = o; }
            BPAIR(u0.x, ch0, 0) BPAIR(u0.y, ch0, 1) BPAIR(u0.z, ch0, 2) BPAIR(u0.w, ch0, 3)
            BPAIR(u1.x, ch1, 0) BPAIR(u1.y, ch1, 1) BPAIR(u1.z, ch1, 2) BPAIR(u1.w, ch1, 3)
            #undef BPAIR
        }
        __syncthreads();

        float acc[32];
        #pragma unroll
        for (int q = 0; q < 32; q++) acc[q] = 0.f;

        #pragma unroll 4
        for (int k = 0; k < 16; k++){
            uint4 aF = sA4[(warp*16 + k)*32 + lane];
            #pragma unroll
            for (int np = 0; np < 4; np++){
                unsigned int bfr[4];
                LDSM_X4(bfr, bBase4 + (unsigned)(np*16*WROW + k*32));
                MMA16816(acc + np*8,     (unsigned int*)&aF, bfr[0], bfr[1]);
                MMA16816(acc + np*8 + 4, (unsigned int*)&aF, bfr[2], bfr[3]);
            }
        }

        #pragma unroll
        for (int n = 0; n < 8; n++){
            int j0 = jb*64 + n*8 + tig*2;
            float4 x0 = sXh[j0], x1 = sXh[j0+1];
            float t0 = tanhfast(acc[n*4+0]);
            float t1 = tanhfast(acc[n*4+1]);
            float t2 = tanhfast(acc[n*4+2]);
            float t3 = tanhfast(acc[n*4+3]);
            cs[0][0] = fmaf(t0, x0.y, fmaf(t1, x1.y, cs[0][0]));
            cs[0][1] = fmaf(t0, x0.z, fmaf(t1, x1.z, cs[0][1]));
            cs[0][2] = fmaf(t0, x0.w, fmaf(t1, x1.w, cs[0][2]));
            cs[1][0] = fmaf(t2, x0.y, fmaf(t3, x1.y, cs[1][0]));
            cs[1][1] = fmaf(t2, x0.z, fmaf(t3, x1.z, cs[1][1]));
            cs[1][2] = fmaf(t2, x0.w, fmaf(t3, x1.w, cs[1][2]));
        }
        __syncthreads();
    }

    #pragma unroll
    for (int r = 0; r < 2; r++)
        #pragma unroll
        for (int q = 0; q < 3; q++){
            float v = cs[r][q];
            v += __shfl_xor_sync(0xFFFFFFFFu, v, 1);
            v += __shfl_xor_sync(0xFFFFFFFFu, v, 2);
            cs[r][q] = v;
        }

    const float invn = 1.0f/(float)NN;
    float pd0 = 0.f, pd1 = 0.f, pd2 = 0.f;
    if (tig == 0){
        #pragma unroll
        for (int r = 0; r < 2; r++){
            int cpr = half*128 + warp*16 + r*8 + g;
            float a  = cs[r][0]*invn;
            float b2 = cs[r][1]*invn;
            float c2 = cs[r][2]*invn;
            g_cn[node*CC + cpr] = a*a + b2*b2 + c2*c2;
            float wv = W_vmix[cpr];
            pd0 = fmaf(a, wv, pd0);
            pd1 = fmaf(b2, wv, pd1);
            pd2 = fmaf(c2, wv, pd2);
        }
    }
    __syncthreads();
    sRed[t] = make_float4(pd0, pd1, pd2, 0.f);
    __syncthreads();
    for (int s = 128; s; s >>= 1){
        if (t < s){
            float4 o2 = sRed[t+s]; float4 m2 = sRed[t];
            m2.x += o2.x; m2.y += o2.y; m2.z += o2.z;
            sRed[t] = m2;
        }
        __syncthreads();
    }
    if (t == 0){
        float4 r = sRed[0];
        g_dvp[node*8 + half*4 + 0] = r.x;
        g_dvp[node*8 + half*4 + 1] = r.y;
        g_dvp[node*8 + half*4 + 2] = r.z;
    }
}

// -------- K4: node MLPs + outputs --------
__global__ __launch_bounds__(256) void k4_node(
    const float* __restrict__ h, const float* __restrict__ x, const float* __restrict__ v,
    const float* __restrict__ W_p1, const float* __restrict__ b_p1,
    const float* __restrict__ W_p2, const float* __restrict__ b_p2,
    const float* __restrict__ W_n1, const float* __restrict__ b_n1,
    const float* __restrict__ W_n2, const float* __restrict__ b_n2,
    const float* __restrict__ W_v1, const float* __restrict__ b_v1,
    const float* __restrict__ W_v2, float* __restrict__ out)
{
    int node = blockIdx.x; int t = threadIdx.x;
    int to = t & 63, ko = t >> 6;
    __shared__ float sIn[384];
    __shared__ float sCn[CC];
    __shared__ float sAcc[256];
    __shared__ float sX[HIDN], sY[HIDN];
    __shared__ float sFin[2];

    if (t < 64) sIn[t] = h[node*FF + t];
    for (int k = t; k < CC; k += 256){
        sIn[64 + k] = g_hesum[node*CC + k];
        sCn[k] = g_cn[node*CC + k];
    }
    __syncthreads();

    {
        float acc = 0.f;
        int k0 = ko*64;
        #pragma unroll 8
        for (int k = 0; k < 64; k++)
            acc = fmaf(sCn[k0+k], W_p1[(k0+k)*HIDN + to], acc);
        sAcc[t] = acc;
    }
    __syncthreads();
    if (ko == 0)
        sX[to] = siluf(b_p1[to] + sAcc[to] + sAcc[64+to] + sAcc[128+to] + sAcc[192+to]);
    __syncthreads();
    {
        float acc = 0.f;
        int k0 = ko*16;
        #pragma unroll
        for (int k = 0; k < 16; k++)
            acc = fmaf(sX[k0+k], W_p2[(k0+k)*HIDN + to], acc);
        sAcc[t] = acc;
    }
    __syncthreads();
    if (ko == 0)
        sIn[320 + to] = siluf(b_p2[to] + sAcc[to] + sAcc[64+to] + sAcc[128+to] + sAcc[192+to]);
    __syncthreads();
    {
        float acc = 0.f;
        int k0 = ko*96;
        #pragma unroll 8
        for (int k = 0; k < 96; k++)
            acc = fmaf(sIn[k0+k], W_n1[(k0+k)*HIDN + to], acc);
        sAcc[t] = acc;
    }
    __syncthreads();
    if (ko == 0)
        sX[to] = siluf(b_n1[to] + sAcc[to] + sAcc[64+to] + sAcc[128+to] + sAcc[192+to]);
    __syncthreads();
    {
        float acc = 0.f;
        int k0 = ko*16;
        #pragma unroll
        for (int k = 0; k < 16; k++)
            acc = fmaf(sX[k0+k], W_n2[(k0+k)*HIDN + to], acc);
        sAcc[t] = acc;
    }
    __syncthreads();
    if (ko == 0){
        float hn = sIn[to] + siluf(b_n2[to] + sAcc[to] + sAcc[64+to] + sAcc[128+to] + sAcc[192+to]);
        sY[to] = hn;
        out[node*FF + to] = hn;
    }
    __syncthreads();
    {
        float acc = 0.f;
        int k0 = ko*16;
        #pragma unroll
        for (int k = 0; k < 16; k++)
            acc = fmaf(sY[k0+k], W_v1[(k0+k)*HIDN + to], acc);
        sAcc[t] = acc;
    }
    __syncthreads();
    if (ko == 0)
        sX[to] = siluf(b_v1[to] + sAcc[to] + sAcc[64+to] + sAcc[128+to] + sAcc[192+to]) * W_v2[to];
    __syncthreads();
    if (t < 32){
        float s = sX[t] + sX[t+32];
        #pragma unroll
        for (int o2 = 16; o2; o2 >>= 1)
            s += __shfl_xor_sync(0xFFFFFFFFu, s, o2);
        if (t == 0) sFin[0] = s;
    }
    __syncthreads();
    if (t < 3){
        float vs = 2.0f/(1.0f + expf(-sFin[0]));
        float vn = g_dvp[node*8 + t] + g_dvp[node*8 + 4 + t] + vs * v[node*3 + t];
        out[NODES*FF + node*3 + t]            = x[node*3 + t] + vn;
        out[NODES*FF + NODES*3 + node*3 + t]  = vn;
    }
}

extern "C" void kernel_launch(void* const* d_in, const int* in_sizes, int n_in,
                              void* d_out, int out_size)
{
    const float* h      = (const float*)d_in[0];
    const float* x      = (const float*)d_in[1];
    const float* v      = (const float*)d_in[2];
    const float* W_in   = (const float*)d_in[3];
    const float* b_in   = (const float*)d_in[4];
    const float* means  = (const float*)d_in[5];
    const float* betas  = (const float*)d_in[6];
    const float* W_o1   = (const float*)d_in[7];
    const float* b_o1   = (const float*)d_in[8];
    const float* W_o2   = (const float*)d_in[9];
    const float* b_o2   = (const float*)d_in[10];
    const float* W_sem  = (const float*)d_in[11];
    const float* b_sem  = (const float*)d_in[12];
    const float* W_xmix = (const float*)d_in[13];
    const float* W_p1   = (const float*)d_in[14];
    const float* b_p1   = (const float*)d_in[15];
    const float* W_p2   = (const float*)d_in[16];
    const float* b_p2   = (const float*)d_in[17];
    const float* W_n1   = (const float*)d_in[18];
    const float* b_n1   = (const float*)d_in[19];
    const float* W_n2   = (const float*)d_in[20];
    const float* b_n2   = (const float*)d_in[21];
    const float* W_v1   = (const float*)d_in[22];
    const float* b_v1   = (const float*)d_in[23];
    const float* W_v2   = (const float*)d_in[24];
    const float* W_vmix = (const float*)d_in[25];
    float* out = (float*)d_out;

    static int smem_set = 0;
    if (!smem_set){
        cudaFuncSetAttribute(k3_attn, cudaFuncAttributeMaxDynamicSharedMemorySize, K3_SMEM);
        cudaFuncSetAttribute(k2_edge, cudaFuncAttributeMaxDynamicSharedMemorySize, K2_SMEM);
        smem_set = 1;
    }

    k0_wt<<<32, 256>>>(W_xmix);
    k0b_wf<<<16, 256>>>(W_o1, W_o2);
    k1_node<<<NODES, 64>>>(h, W_in, W_o1);
    dim3 g2(NN/16, NN/8, BB);
    k2_edge<<<g2, 256, K2_SMEM>>>(x, b_o1, b_in, means, betas, W_sem, b_sem);
    k3_attn<<<NODES*2, 256, K3_SMEM>>>(W_vmix);
    k4_node<<<NODES, 256>>>(h, x, v, W_p1, b_p1, W_p2, b_p2,
                            W_n1, b_n1, W_n2, b_n2, W_v1, b_v1, W_v2, out);
}

// round 15
// speedup vs baseline: 5.4858x; 1.0079x over previous
#include <cuda_runtime.h>
#include <math.h>

#define BB 2
#define NN 256
#define FF 64
#define HH 4
#define HIDN 64
#define CC 256
#define KF 50
#define NODES (BB*NN)
#define CUTF 5.0f
#define PI_F 3.14159265358979f

// -------- scratch (device globals; no runtime allocation) --------
__device__ float g_Ain[NODES*KF];
__device__ float g_Bin[NODES*KF];
__device__ float g_P[NODES*HIDN];
__device__ float g_Q[NODES*HIDN];
__device__ unsigned int g_heb[(long)BB*NN*NN*32];  // h_e bf16 pairs (16 MB)
__device__ float g_attl[(long)BB*NN*NN*HH];        // att logits
__device__ float4 g_dx[(long)BB*NN*NN];            // (d, xhat)
__device__ float g_hesum[NODES*CC];
__device__ float g_cn[NODES*CC];
__device__ float g_dvp[NODES*8];                   // dv partials (2 halves)
// W_xmix head-decomposed A-frags: [half][w(8)][h(4)][kt(4)][lane(32)] uint4
__device__ uint4 g_WtF[8192];
// W_o1[128:179] and W_o2 in per-lane tf32 B-fragment layout
__device__ uint2 g_Wf[4096];

__device__ __forceinline__ float siluf(float v){ return v/(1.0f+expf(-v)); }
__device__ __forceinline__ float silu_fast(float v){
    return v * __fdividef(1.0f, 1.0f + __expf(-v));
}

__device__ __forceinline__ unsigned int pack_bf2(float lo, float hi){
    unsigned int r;
    asm("cvt.rn.bf16x2.f32 %0, %1, %2;" : "=r"(r) : "f"(hi), "f"(lo));
    return r;
}
__device__ __forceinline__ unsigned int smem_u32(const void* p){
    unsigned int a;
    asm("{ .reg .u64 t; cvta.to.shared.u64 t, %1; cvt.u32.u64 %0, t; }" : "=r"(a) : "l"(p));
    return a;
}
__device__ __forceinline__ float tanhfast(float x){
    float r; asm("tanh.approx.f32 %0, %1;" : "=f"(r) : "f"(x)); return r;
}
#define CVT_TF32(o, f) asm("cvt.rna.tf32.f32 %0, %1;" : "=r"(o) : "f"(f))
#define LDSM_X4(R, addr) \
    asm volatile("ldmatrix.sync.aligned.m8n8.x4.shared.b16 {%0,%1,%2,%3}, [%4];" \
        : "=r"((R)[0]),"=r"((R)[1]),"=r"((R)[2]),"=r"((R)[3]) : "r"(addr))
#define MMA16816(D, A, B0, B1) \
    asm volatile("mma.sync.aligned.m16n8k16.row.col.f32.bf16.bf16.f32 " \
        "{%0,%1,%2,%3}, {%4,%5,%6,%7}, {%8,%9}, {%0,%1,%2,%3};" \
        : "+f"((D)[0]),"+f"((D)[1]),"+f"((D)[2]),"+f"((D)[3]) \
        : "r"((A)[0]),"r"((A)[1]),"r"((A)[2]),"r"((A)[3]),"r"(B0),"r"(B1))
#define MMATF32(D, a0,a1,a2,a3, b0,b1) \
    asm volatile("mma.sync.aligned.m16n8k8.row.col.f32.tf32.tf32.f32 " \
        "{%0,%1,%2,%3}, {%4,%5,%6,%7}, {%8,%9}, {%0,%1,%2,%3};" \
        : "+f"((D)[0]),"+f"((D)[1]),"+f"((D)[2]),"+f"((D)[3]) \
        : "r"(a0),"r"(a1),"r"(a2),"r"(a3),"r"(b0),"r"(b1))

// -------- merged prep kernel: k1 (nodes), k0 (WtF), k0b (Wf) --------
__global__ void k_prep(const float* __restrict__ h,
                       const float* __restrict__ W_in,
                       const float* __restrict__ W_o1,
                       const float* __restrict__ W_o2,
                       const float* __restrict__ W_xmix)
{
    int bid = blockIdx.x;
    int t = threadIdx.x;
    if (bid < NODES){
        __shared__ float sh[FF];
        int node = bid;
        if (t < FF) sh[t] = h[node*FF + t];
        __syncthreads();
        if (t < FF){
            float p = 0.f, q = 0.f;
            #pragma unroll 8
            for (int k = 0; k < FF; k++){
                float hv = sh[k];
                p = fmaf(hv, W_o1[k*HIDN + t], p);
                q = fmaf(hv, W_o1[(FF+k)*HIDN + t], q);
            }
            g_P[node*HIDN + t] = p;
            g_Q[node*HIDN + t] = q;
            if (t < KF){
                float a = 0.f, bv = 0.f;
                #pragma unroll 8
                for (int k = 0; k < FF; k++){
                    float hv = sh[k];
                    a  = fmaf(hv, W_in[k*KF + t], a);
                    bv = fmaf(hv, W_in[(FF+k)*KF + t], bv);
                }
                g_Ain[node*KF + t] = a;
                g_Bin[node*KF + t] = bv;
            }
        }
    } else if (bid < NODES + 32){
        // ---- W_xmix head-decomposed A frags ----
        int idx = (bid - NODES)*256 + t;     // 0..8191
        int lane = idx & 31;
        int kt = (idx >> 5) & 3;
        int hh = (idx >> 7) & 3;
        int w  = (idx >> 9) & 7;
        int half = (idx >> 12) & 1;
        int g = lane >> 2, tig = lane & 3;
        int r0 = (half*8 + w)*16 + g, r1 = r0 + 8;
        int f0 = kt*16 + tig*2;
        int f8 = f0 + 8;
        const float* W = W_xmix;
        uint4 f;
        f.x = pack_bf2(W[(4*f0+hh)*CC + r0],     W[(4*(f0+1)+hh)*CC + r0]);
        f.y = pack_bf2(W[(4*f0+hh)*CC + r1],     W[(4*(f0+1)+hh)*CC + r1]);
        f.z = pack_bf2(W[(4*f8+hh)*CC + r0],     W[(4*(f8+1)+hh)*CC + r0]);
        f.w = pack_bf2(W[(4*f8+hh)*CC + r1],     W[(4*(f8+1)+hh)*CC + r1]);
        g_WtF[idx] = f;
    } else {
        // ---- W1/W2 tf32 B frags ----
        int idx = (bid - NODES - 32)*256 + t;   // 0..4095
        int lane = idx & 31;
        int nt = (idx >> 5) & 7;
        int kt = (idx >> 8) & 7;
        int m  = idx >> 11;
        int g = lane >> 2, tig = lane & 3;
        int k0 = kt*8 + tig, k1 = k0 + 4, n = nt*8 + g;
        float v0, v1;
        if (m == 0){
            v0 = (k0 <= 50) ? W_o1[(128 + k0)*HIDN + n] : 0.f;
            v1 = (k1 <= 50) ? W_o1[(128 + k1)*HIDN + n] : 0.f;
        } else {
            v0 = W_o2[k0*HIDN + n];
            v1 = W_o2[k1*HIDN + n];
        }
        unsigned u0, u1;
        CVT_TF32(u0, v0); CVT_TF32(u1, v1);
        g_Wf[m*2048 + (kt*8 + nt)*32 + lane] = make_uint2(u0, u1);
    }
}

// -------- K2: edge model via tf32 MMA --------
#define K2_OFF_A1   0u
#define K2_OFF_W1   32768u
#define K2_OFF_W2   49152u
#define K2_OFF_P    65536u
#define K2_OFF_Q    69888u
#define K2_OFF_AIN  72064u
#define K2_OFF_BIN  75392u
#define K2_OFF_WS   77056u
#define K2_OFF_BO1  78080u
#define K2_OFF_MEAN 78336u
#define K2_OFF_BETA 78544u
#define K2_OFF_BINV 78752u
#define K2_OFF_XI   78960u
#define K2_OFF_XJ   79088u
#define K2_OFF_BSEM 79344u
#define K2_SMEM     79360u

__global__ __launch_bounds__(256,2) void k2_edge(
    const float* __restrict__ x,
    const float* __restrict__ b_o1, const float* __restrict__ b_in,
    const float* __restrict__ means, const float* __restrict__ betas,
    const float* __restrict__ W_sem, const float* __restrict__ b_sem)
{
    extern __shared__ char smem[];
    int b  = blockIdx.z;
    int i0 = blockIdx.y*8, j0 = blockIdx.x*16;
    int t  = threadIdx.x;

    float* sP   = (float*)(smem + K2_OFF_P);
    float* sQ   = (float*)(smem + K2_OFF_Q);
    float* sAin = (float*)(smem + K2_OFF_AIN);
    float* sBin = (float*)(smem + K2_OFF_BIN);
    float4* sWs = (float4*)(smem + K2_OFF_WS);
    float* sBo1 = (float*)(smem + K2_OFF_BO1);
    float* sMean= (float*)(smem + K2_OFF_MEAN);
    float* sBeta= (float*)(smem + K2_OFF_BETA);
    float* sBinV= (float*)(smem + K2_OFF_BINV);
    float* sXi  = (float*)(smem + K2_OFF_XI);
    float* sXj  = (float*)(smem + K2_OFF_XJ);

    for (int idx = t; idx < 1024; idx += 256){
        ((uint4*)(smem + K2_OFF_W1))[idx] = ((const uint4*)g_Wf)[idx];
        ((uint4*)(smem + K2_OFF_W2))[idx] = ((const uint4*)g_Wf)[1024 + idx];
        sP[(idx >> 6)*68 + (idx & 63)] = g_P[(b*NN + j0 + (idx >> 6))*HIDN + (idx & 63)];
    }
    for (int idx = t; idx < 512; idx += 256)
        sQ[(idx >> 6)*68 + (idx & 63)] = g_Q[(b*NN + i0 + (idx >> 6))*HIDN + (idx & 63)];
    for (int idx = t; idx < 800; idx += 256){
        int r = idx/50, c = idx - r*50;
        sAin[r*52 + c] = g_Ain[(b*NN + j0 + r)*KF + c];
    }
    for (int idx = t; idx < 400; idx += 256){
        int r = idx/50, c = idx - r*50;
        sBin[r*52 + c] = g_Bin[(b*NN + i0 + r)*KF + c];
    }
    if (t < 64){
        sWs[t] = ((const float4*)W_sem)[t];
        sBo1[t] = b_o1[t];
    }
    if (t < 50){ sMean[t] = means[t]; sBeta[t] = betas[t]; sBinV[t] = b_in[t]; }
    if (t < 48){ int r = t/3, c = t - r*3; sXj[r*4 + c] = x[(b*NN + j0 + r)*3 + c]; }
    else if (t < 72){ int u = t - 48; int r = u/3, c = u - r*3; sXi[r*4 + c] = x[(b*NN + i0 + r)*3 + c]; }
    if (t == 0) *(float4*)(smem + K2_OFF_BSEM) = *(const float4*)b_sem;
    {
        uint4 z = make_uint4(0,0,0,0);
        for (int idx = t; idx < 512; idx += 256){
            int mt = idx >> 6, rest = idx & 63;
            ((uint4*)(smem + K2_OFF_A1))[(mt*8 + 6 + (rest >> 5))*32 + (rest & 31)] = z;
        }
    }
    __syncthreads();

    {
        int p = t & 127, bh = t >> 7;
        int il = p >> 4, jl = p & 15;
        float dxv = sXj[jl*4+0] - sXi[il*4+0];
        float dyv = sXj[jl*4+1] - sXi[il*4+1];
        float dzv = sXj[jl*4+2] - sXi[il*4+2];
        float d = sqrtf(dxv*dxv + dyv*dyv + dzv*dzv + 1e-5f);
        float cutv = (d < CUTF) ? 0.5f*(__cosf(d*(PI_F/CUTF)) + 1.0f) : 0.f;
        float em = __expf(-d);
        int gg = jl & 7, regRow = jl >> 3;
        unsigned base1 = (unsigned)(il*8)*512u + (unsigned)(gg*4)*16u + (unsigned)regRow*4u;
        if (bh){
            long pair = ((long)(b*NN + i0 + il))*NN + j0 + jl;
            float inv = 1.0f/(d + 1e-5f);
            g_dx[pair] = make_float4(d, dxv*inv, dyv*inv, dzv*inv);
        }
        int c0 = bh ? 26 : 0, c1 = bh ? 51 : 26;
        for (int c = c0; c < c1; c++){
            float val;
            if (c == 50) val = d;
            else {
                float h1 = sAin[jl*52 + c] + sBin[il*52 + c] + sBinV[c];
                float dm = em - sMean[c];
                val = cutv * __expf(-sBeta[c]*dm*dm) * h1;
            }
            unsigned r32; CVT_TF32(r32, val);
            unsigned addr = K2_OFF_A1 + base1 + (unsigned)((c >> 3))*512u
                          + (unsigned)(c & 3)*16u + (unsigned)((c >> 2) & 1)*8u;
            *(unsigned*)(smem + addr) = r32;
        }
    }
    __syncthreads();

    int lane = t & 31, warp = t >> 5;
    int g2 = lane >> 2, tig = lane & 3;
    const uint4* A1v = (const uint4*)(smem + K2_OFF_A1);
    const uint2* W1v = (const uint2*)(smem + K2_OFF_W1);
    const uint2* W2v = (const uint2*)(smem + K2_OFF_W2);

    float acc1[8][4];
    #pragma unroll
    for (int n = 0; n < 8; n++){ acc1[n][0]=acc1[n][1]=acc1[n][2]=acc1[n][3]=0.f; }
    #pragma unroll
    for (int kt = 0; kt < 8; kt++){
        uint4 aF = A1v[(warp*8 + kt)*32 + lane];
        #pragma unroll
        for (int nt = 0; nt < 8; nt++){
            uint2 bF = W1v[(kt*8 + nt)*32 + lane];
            MMATF32(acc1[nt], aF.x, aF.y, aF.z, aF.w, bF.x, bF.y);
        }
    }
    #pragma unroll
    for (int nt = 0; nt < 8; nt++){
        int f0 = nt*8 + tig*2;
        float q0 = sQ[warp*68 + f0]   + sBo1[f0];
        float q1 = sQ[warp*68 + f0+1] + sBo1[f0+1];
        acc1[nt][0] = silu_fast(acc1[nt][0] + sP[g2*68 + f0]       + q0);
        acc1[nt][1] = silu_fast(acc1[nt][1] + sP[g2*68 + f0+1]     + q1);
        acc1[nt][2] = silu_fast(acc1[nt][2] + sP[(g2+8)*68 + f0]   + q0);
        acc1[nt][3] = silu_fast(acc1[nt][3] + sP[(g2+8)*68 + f0+1] + q1);
    }
    float acc2[8][4];
    #pragma unroll
    for (int n = 0; n < 8; n++){ acc2[n][0]=acc2[n][1]=acc2[n][2]=acc2[n][3]=0.f; }
    int s0 = (lane & ~3) | (tig >> 1);
    int s1 = s0 + 2;
    bool odd = (tig & 1);
    #pragma unroll
    for (int kt = 0; kt < 8; kt++){
        float v0 = __shfl_sync(0xFFFFFFFFu, acc1[kt][0], s0);
        float v1 = __shfl_sync(0xFFFFFFFFu, acc1[kt][1], s0);
        float v2 = __shfl_sync(0xFFFFFFFFu, acc1[kt][2], s0);
        float v3 = __shfl_sync(0xFFFFFFFFu, acc1[kt][3], s0);
        float w0 = __shfl_sync(0xFFFFFFFFu, acc1[kt][0], s1);
        float w1 = __shfl_sync(0xFFFFFFFFu, acc1[kt][1], s1);
        float w2 = __shfl_sync(0xFFFFFFFFu, acc1[kt][2], s1);
        float w3 = __shfl_sync(0xFFFFFFFFu, acc1[kt][3], s1);
        unsigned a0, a1, a2, a3;
        CVT_TF32(a0, odd ? v1 : v0);
        CVT_TF32(a1, odd ? v3 : v2);
        CVT_TF32(a2, odd ? w1 : w0);
        CVT_TF32(a3, odd ? w3 : w2);
        #pragma unroll
        for (int nt = 0; nt < 8; nt++){
            uint2 bF = W2v[(kt*8 + nt)*32 + lane];
            MMATF32(acc2[nt], a0, a1, a2, a3, bF.x, bF.y);
        }
    }
    long rowPair0 = ((long)(b*NN + i0 + warp))*NN + j0 + g2;
    long rowPair1 = rowPair0 + 8;
    float l00=0.f,l01=0.f,l02=0.f,l03=0.f;
    float l10=0.f,l11=0.f,l12=0.f,l13=0.f;
    #pragma unroll
    for (int nt = 0; nt < 8; nt++){
        int f0 = nt*8 + tig*2;
        float h00 = acc2[nt][0], h01 = acc2[nt][1];
        float h10 = acc2[nt][2], h11 = acc2[nt][3];
        g_heb[rowPair0*32 + (f0 >> 1)] = pack_bf2(h00, h01);
        g_heb[rowPair1*32 + (f0 >> 1)] = pack_bf2(h10, h11);
        float4 ws0 = sWs[f0], ws1 = sWs[f0+1];
        l00 = fmaf(h00, ws0.x, fmaf(h01, ws1.x, l00));
        l01 = fmaf(h00, ws0.y, fmaf(h01, ws1.y, l01));
        l02 = fmaf(h00, ws0.z, fmaf(h01, ws1.z, l02));
        l03 = fmaf(h00, ws0.w, fmaf(h01, ws1.w, l03));
        l10 = fmaf(h10, ws0.x, fmaf(h11, ws1.x, l10));
        l11 = fmaf(h10, ws0.y, fmaf(h11, ws1.y, l11));
        l12 = fmaf(h10, ws0.z, fmaf(h11, ws1.z, l12));
        l13 = fmaf(h10, ws0.w, fmaf(h11, ws1.w, l13));
    }
    #define QRED(v) v += __shfl_xor_sync(0xFFFFFFFFu, v, 1); v += __shfl_xor_sync(0xFFFFFFFFu, v, 2);
    QRED(l00) QRED(l01) QRED(l02) QRED(l03)
    QRED(l10) QRED(l11) QRED(l12) QRED(l13)
    #undef QRED
    if (tig == 0){
        float4 bsem = *(float4*)(smem + K2_OFF_BSEM);
        float r0[4] = {l00 + bsem.x, l01 + bsem.y, l02 + bsem.z, l03 + bsem.w};
        float r1[4] = {l10 + bsem.x, l11 + bsem.y, l12 + bsem.z, l13 + bsem.w};
        #pragma unroll
        for (int hh = 0; hh < 4; hh++){
            r0[hh] = (r0[hh] > 0.f) ? r0[hh] : 2.0f*(__expf(0.5f*r0[hh]) - 1.0f);
            r1[hh] = (r1[hh] > 0.f) ? r1[hh] : 2.0f*(__expf(0.5f*r1[hh]) - 1.0f);
        }
        if (i0 + warp == j0 + g2)     { r0[0]-=1e5f; r0[1]-=1e5f; r0[2]-=1e5f; r0[3]-=1e5f; }
        if (i0 + warp == j0 + g2 + 8) { r1[0]-=1e5f; r1[1]-=1e5f; r1[2]-=1e5f; r1[3]-=1e5f; }
        *(float4*)&g_attl[rowPair0*HH] = make_float4(r0[0], r0[1], r0[2], r0[3]);
        *(float4*)&g_attl[rowPair1*HH] = make_float4(r1[0], r1[1], r1[2], r1[3]);
    }
}

// -------- K3: barrier-free head-decomposed HMMA xmix GEMM --------
// B = raw he (bf16), staged once with 144B pitch (16-aligned, 4-bank row shift)
#define HPITCH 144
#define OFF_A    0u            // A frags (half): 4096 uint4 = 65536
#define OFF_B    65536u        // he: 256*144 = 36864 -> 102400
#define OFF_ATT  102400u       // float4[256] -> 106496
#define OFF_XH   106496u       // float4[256] -> 110592
#define OFF_RED  110592u       // float4[256] -> 114688
#define K3_SMEM  114688u

__global__ __launch_bounds__(256,2) void k3_attn(const float* __restrict__ W_vmix)
{
    extern __shared__ char smem[];
    unsigned int sbase = smem_u32(smem);
    float4* sAtt = (float4*)(smem + OFF_ATT);
    float4* sXh  = (float4*)(smem + OFF_XH);
    float4* sRed = (float4*)(smem + OFF_RED);
    const uint4* sA4 = (const uint4*)(smem + OFF_A);

    int node = blockIdx.x >> 1;
    int half = blockIdx.x & 1;
    int t = threadIdx.x;
    long base = ((long)node)*NN;

    // ---- copy A-half frags into smem ----
    {
        const uint4* src = g_WtF + half*4096;
        uint4* dst = (uint4*)(smem + OFF_A);
        for (int idx = t; idx < 4096; idx += 256) dst[idx] = src[idx];
    }
    // ---- stage he (raw bf16) with 144B pitch ----
    {
        for (int idx = t; idx < 2048; idx += 256){
            int row = idx >> 3, ch = idx & 7;
            *(uint4*)(smem + OFF_B + row*HPITCH + ch*16)
                = *(const uint4*)(g_heb + (base + row)*32 + ch*4);
        }
    }

    // ---- softmax over j (per head) ----
    float4 l = *(const float4*)&g_attl[(base + t)*HH];
    sRed[t] = l;
    sXh[t] = g_dx[base + t];
    __syncthreads();
    for (int s = 128; s; s >>= 1){
        if (t < s){
            float4 o2 = sRed[t+s]; float4 m = sRed[t];
            m.x = fmaxf(m.x,o2.x); m.y = fmaxf(m.y,o2.y);
            m.z = fmaxf(m.z,o2.z); m.w = fmaxf(m.w,o2.w);
            sRed[t] = m;
        }
        __syncthreads();
    }
    float4 mx = sRed[0];
    __syncthreads();
    float4 e = make_float4(expf(l.x-mx.x), expf(l.y-mx.y), expf(l.z-mx.z), expf(l.w-mx.w));
    sRed[t] = e;
    __syncthreads();
    for (int s = 128; s; s >>= 1){
        if (t < s){
            float4 o2 = sRed[t+s]; float4 m = sRed[t];
            m.x += o2.x; m.y += o2.y; m.z += o2.z; m.w += o2.w;
            sRed[t] = m;
        }
        __syncthreads();
    }
    float4 sm = sRed[0];
    __syncthreads();
    float4 att = make_float4(e.x/sm.x, e.y/sm.y, e.z/sm.z, e.w/sm.w);
    sAtt[t] = att;
    __syncthreads();

    // ---- he_sum (half-0 CTAs only) ----
    if (half == 0){
        int f = t & 63, q = t >> 6;
        int sh = (f & 1)*16;
        const unsigned int* hb = g_heb + (base + q*64)*32 + (f >> 1);
        float s0=0.f, s1=0.f, s2=0.f, s3=0.f;
        #pragma unroll 4
        for (int jj = 0; jj < 64; jj++){
            unsigned int u = hb[jj*32];
            float hev = __uint_as_float(((u >> sh) & 0xFFFFu) << 16);
            float4 a4 = sAtt[q*64 + jj];
            s0 = fmaf(hev, a4.x, s0); s1 = fmaf(hev, a4.y, s1);
            s2 = fmaf(hev, a4.z, s2); s3 = fmaf(hev, a4.w, s3);
        }
        sRed[t] = make_float4(s0, s1, s2, s3);
    }
    __syncthreads();
    if (half == 0){
        int f = t >> 2, hh2 = t & 3;
        float s = ((const float*)&sRed[f])[hh2]
                + ((const float*)&sRed[64+f])[hh2]
                + ((const float*)&sRed[128+f])[hh2]
                + ((const float*)&sRed[192+f])[hh2];
        g_hesum[node*CC + t] = s;
    }
    __syncthreads();   // after this, smem is read-only in the mainloop: no more barriers

    int lane = t & 31, warp = t >> 5;
    int g = lane >> 2, tig = lane & 3;
    unsigned int bBase4 = sbase + OFF_B + (unsigned)((lane & 7))*HPITCH
                        + (unsigned)(((lane >> 3) & 1)*16)
                        + (unsigned)(((lane >> 4) & 1)*(8*HPITCH));

    float cs[2][3];
    cs[0][0]=cs[0][1]=cs[0][2]=cs[1][0]=cs[1][1]=cs[1][2]=0.f;

    for (int jb = 0; jb < 4; jb++){
        float fin[32];
        #pragma unroll
        for (int q = 0; q < 32; q++) fin[q] = 0.f;
        unsigned int bJB = bBase4 + (unsigned)(jb*64*HPITCH);

        #pragma unroll
        for (int hh = 0; hh < 4; hh++){
            float G[32];
            #pragma unroll
            for (int q = 0; q < 32; q++) G[q] = 0.f;
            #pragma unroll
            for (int kt = 0; kt < 4; kt++){
                uint4 aF = sA4[(warp*16 + hh*4 + kt)*32 + lane];
                #pragma unroll
                for (int np = 0; np < 4; np++){
                    unsigned int bfr[4];
                    LDSM_X4(bfr, bJB + (unsigned)(np*16*HPITCH + kt*32));
                    MMA16816(G + np*8,     (unsigned int*)&aF, bfr[0], bfr[1]);
                    MMA16816(G + np*8 + 4, (unsigned int*)&aF, bfr[2], bfr[3]);
                }
            }
            // fold with fp32 att[j][hh]
            #pragma unroll
            for (int n = 0; n < 8; n++){
                int j0 = jb*64 + n*8 + tig*2;
                float a0 = *(const float*)(smem + OFF_ATT + (unsigned)(j0*16 + hh*4));
                float a1 = *(const float*)(smem + OFF_ATT + (unsigned)((j0+1)*16 + hh*4));
                fin[n*4+0] = fmaf(a0, G[n*4+0], fin[n*4+0]);
                fin[n*4+1] = fmaf(a1, G[n*4+1], fin[n*4+1]);
                fin[n*4+2] = fmaf(a0, G[n*4+2], fin[n*4+2]);
                fin[n*4+3] = fmaf(a1, G[n*4+3], fin[n*4+3]);
            }
        }

        // epilogue: tanh + cs accumulation
        #pragma unroll
        for (int n = 0; n < 8; n++){
            int j0 = jb*64 + n*8 + tig*2;
            float4 x0 = sXh[j0], x1 = sXh[j0+1];
            float t0 = tanhfast(fin[n*4+0]);
            float t1 = tanhfast(fin[n*4+1]);
            float t2 = tanhfast(fin[n*4+2]);
            float t3 = tanhfast(fin[n*4+3]);
            cs[0][0] = fmaf(t0, x0.y, fmaf(t1, x1.y, cs[0][0]));
            cs[0][1] = fmaf(t0, x0.z, fmaf(t1, x1.z, cs[0][1]));
            cs[0][2] = fmaf(t0, x0.w, fmaf(t1, x1.w, cs[0][2]));
            cs[1][0] = fmaf(t2, x0.y, fmaf(t3, x1.y, cs[1][0]));
            cs[1][1] = fmaf(t2, x0.z, fmaf(t3, x1.z, cs[1][1]));
            cs[1][2] = fmaf(t2, x0.w, fmaf(t3, x1.w, cs[1][2]));
        }
    }

    // reduce cs over the quad (lanes with same g share c' rows)
    #pragma unroll
    for (int r = 0; r < 2; r++)
        #pragma unroll
        for (int q = 0; q < 3; q++){
            float v = cs[r][q];
            v += __shfl_xor_sync(0xFFFFFFFFu, v, 1);
            v += __shfl_xor_sync(0xFFFFFFFFu, v, 2);
            cs[r][q] = v;
        }

    const float invn = 1.0f/(float)NN;
    float pd0 = 0.f, pd1 = 0.f, pd2 = 0.f;
    if (tig == 0){
        #pragma unroll
        for (int r = 0; r < 2; r++){
            int cpr = half*128 + warp*16 + r*8 + g;
            float a  = cs[r][0]*invn;
            float b2 = cs[r][1]*invn;
            float c2 = cs[r][2]*invn;
            g_cn[node*CC + cpr] = a*a + b2*b2 + c2*c2;
            float wv = W_vmix[cpr];
            pd0 = fmaf(a, wv, pd0);
            pd1 = fmaf(b2, wv, pd1);
            pd2 = fmaf(c2, wv, pd2);
        }
    }
    __syncthreads();
    sRed[t] = make_float4(pd0, pd1, pd2, 0.f);
    __syncthreads();
    for (int s = 128; s; s >>= 1){
        if (t < s){
            float4 o2 = sRed[t+s]; float4 m2 = sRed[t];
            m2.x += o2.x; m2.y += o2.y; m2.z += o2.z;
            sRed[t] = m2;
        }
        __syncthreads();
    }
    if (t == 0){
        float4 r = sRed[0];
        g_dvp[node*8 + half*4 + 0] = r.x;
        g_dvp[node*8 + half*4 + 1] = r.y;
        g_dvp[node*8 + half*4 + 2] = r.z;
    }
}

// -------- K4: node MLPs + outputs --------
__global__ __launch_bounds__(256) void k4_node(
    const float* __restrict__ h, const float* __restrict__ x, const float* __restrict__ v,
    const float* __restrict__ W_p1, const float* __restrict__ b_p1,
    const float* __restrict__ W_p2, const float* __restrict__ b_p2,
    const float* __restrict__ W_n1, const float* __restrict__ b_n1,
    const float* __restrict__ W_n2, const float* __restrict__ b_n2,
    const float* __restrict__ W_v1, const float* __restrict__ b_v1,
    const float* __restrict__ W_v2, float* __restrict__ out)
{
    int node = blockIdx.x; int t = threadIdx.x;
    int to = t & 63, ko = t >> 6;
    __shared__ float sIn[384];
    __shared__ float sCn[CC];
    __shared__ float sAcc[256];
    __shared__ float sX[HIDN], sY[HIDN];
    __shared__ float sFin[2];

    if (t < 64) sIn[t] = h[node*FF + t];
    for (int k = t; k < CC; k += 256){
        sIn[64 + k] = g_hesum[node*CC + k];
        sCn[k] = g_cn[node*CC + k];
    }
    __syncthreads();

    {
        float acc = 0.f;
        int k0 = ko*64;
        #pragma unroll 8
        for (int k = 0; k < 64; k++)
            acc = fmaf(sCn[k0+k], W_p1[(k0+k)*HIDN + to], acc);
        sAcc[t] = acc;
    }
    __syncthreads();
    if (ko == 0)
        sX[to] = siluf(b_p1[to] + sAcc[to] + sAcc[64+to] + sAcc[128+to] + sAcc[192+to]);
    __syncthreads();
    {
        float acc = 0.f;
        int k0 = ko*16;
        #pragma unroll
        for (int k = 0; k < 16; k++)
            acc = fmaf(sX[k0+k], W_p2[(k0+k)*HIDN + to], acc);
        sAcc[t] = acc;
    }
    __syncthreads();
    if (ko == 0)
        sIn[320 + to] = siluf(b_p2[to] + sAcc[to] + sAcc[64+to] + sAcc[128+to] + sAcc[192+to]);
    __syncthreads();
    {
        float acc = 0.f;
        int k0 = ko*96;
        #pragma unroll 8
        for (int k = 0; k < 96; k++)
            acc = fmaf(sIn[k0+k], W_n1[(k0+k)*HIDN + to], acc);
        sAcc[t] = acc;
    }
    __syncthreads();
    if (ko == 0)
        sX[to] = siluf(b_n1[to] + sAcc[to] + sAcc[64+to] + sAcc[128+to] + sAcc[192+to]);
    __syncthreads();
    {
        float acc = 0.f;
        int k0 = ko*16;
        #pragma unroll
        for (int k = 0; k < 16; k++)
            acc = fmaf(sX[k0+k], W_n2[(k0+k)*HIDN + to], acc);
        sAcc[t] = acc;
    }
    __syncthreads();
    if (ko == 0){
        float hn = sIn[to] + siluf(b_n2[to] + sAcc[to] + sAcc[64+to] + sAcc[128+to] + sAcc[192+to]);
        sY[to] = hn;
        out[node*FF + to] = hn;
    }
    __syncthreads();
    {
        float acc = 0.f;
        int k0 = ko*16;
        #pragma unroll
        for (int k = 0; k < 16; k++)
            acc = fmaf(sY[k0+k], W_v1[(k0+k)*HIDN + to], acc);
        sAcc[t] = acc;
    }
    __syncthreads();
    if (ko == 0)
        sX[to] = siluf(b_v1[to] + sAcc[to] + sAcc[64+to] + sAcc[128+to] + sAcc[192+to]) * W_v2[to];
    __syncthreads();
    if (t < 32){
        float s = sX[t] + sX[t+32];
        #pragma unroll
        for (int o2 = 16; o2; o2 >>= 1)
            s += __shfl_xor_sync(0xFFFFFFFFu, s, o2);
        if (t == 0) sFin[0] = s;
    }
    __syncthreads();
    if (t < 3){
        float vs = 2.0f/(1.0f + expf(-sFin[0]));
        float vn = g_dvp[node*8 + t] + g_dvp[node*8 + 4 + t] + vs * v[node*3 + t];
        out[NODES*FF + node*3 + t]            = x[node*3 + t] + vn;
        out[NODES*FF + NODES*3 + node*3 + t]  = vn;
    }
}

extern "C" void kernel_launch(void* const* d_in, const int* in_sizes, int n_in,
                              void* d_out, int out_size)
{
    const float* h      = (const float*)d_in[0];
    const float* x      = (const float*)d_in[1];
    const float* v      = (const float*)d_in[2];
    const float* W_in   = (const float*)d_in[3];
    const float* b_in   = (const float*)d_in[4];
    const float* means  = (const float*)d_in[5];
    const float* betas  = (const float*)d_in[6];
    const float* W_o1   = (const float*)d_in[7];
    const float* b_o1   = (const float*)d_in[8];
    const float* W_o2   = (const float*)d_in[9];
    const float* b_o2   = (const float*)d_in[10];
    const float* W_sem  = (const float*)d_in[11];
    const float* b_sem  = (const float*)d_in[12];
    const float* W_xmix = (const float*)d_in[13];
    const float* W_p1   = (const float*)d_in[14];
    const float* b_p1   = (const float*)d_in[15];
    const float* W_p2   = (const float*)d_in[16];
    const float* b_p2   = (const float*)d_in[17];
    const float* W_n1   = (const float*)d_in[18];
    const float* b_n1   = (const float*)d_in[19];
    const float* W_n2   = (const float*)d_in[20];
    const float* b_n2   = (const float*)d_in[21];
    const float* W_v1   = (const float*)d_in[22];
    const float* b_v1   = (const float*)d_in[23];
    const float* W_v2   = (const float*)d_in[24];
    const float* W_vmix = (const float*)d_in[25];
    float* out = (float*)d_out;

    static int smem_set = 0;
    if (!smem_set){
        cudaFuncSetAttribute(k3_attn, cudaFuncAttributeMaxDynamicSharedMemorySize, K3_SMEM);
        cudaFuncSetAttribute(k2_edge, cudaFuncAttributeMaxDynamicSharedMemorySize, K2_SMEM);
        smem_set = 1;
    }

    k_prep<<<NODES + 48, 256>>>(h, W_in, W_o1, W_o2, W_xmix);
    dim3 g2(NN/16, NN/8, BB);
    k2_edge<<<g2, 256, K2_SMEM>>>(x, b_o1, b_in, means, betas, W_sem, b_sem);
    k3_attn<<<NODES*2, 256, K3_SMEM>>>(W_vmix);
    k4_node<<<NODES, 256>>>(h, x, v, W_p1, b_p1, W_p2, b_p2,
                            W_n1, b_n1, W_n2, b_n2, W_v1, b_v1, W_v2, out);
}

// round 16
// speedup vs baseline: 6.7245x; 1.2258x over previous
#include <cuda_runtime.h>
#include <math.h>

#define BB 2
#define NN 256
#define FF 64
#define HH 4
#define HIDN 64
#define CC 256
#define KF 50
#define NODES (BB*NN)
#define CUTF 5.0f
#define PI_F 3.14159265358979f

// -------- scratch (device globals; no runtime allocation) --------
__device__ float g_Ain[NODES*KF];
__device__ float g_Bin[NODES*KF];
__device__ float g_P[NODES*HIDN];
__device__ float g_Q[NODES*HIDN];
__device__ unsigned int g_heb[(long)BB*NN*NN*32];  // h_e bf16 pairs (16 MB)
__device__ float g_attl[(long)BB*NN*NN*HH];        // att logits
__device__ float4 g_dx[(long)BB*NN*NN];            // (d, xhat)
__device__ float g_hesum[NODES*CC];
__device__ float g_cn[NODES*CC];
__device__ float g_dvp[NODES*8];                   // dv partials (2 halves)
// W_xmix head-decomposed A-frags: [half][w(8)][h(4)][kt(4)][lane(32)] uint4
__device__ uint4 g_WtF[8192];
// W_o1[128:179] and W_o2 in per-lane tf32 B-fragment layout
__device__ uint2 g_Wf[4096];

__device__ __forceinline__ float siluf(float v){ return v/(1.0f+expf(-v)); }
__device__ __forceinline__ float silu_fast(float v){
    return v * __fdividef(1.0f, 1.0f + __expf(-v));
}

__device__ __forceinline__ unsigned int pack_bf2(float lo, float hi){
    unsigned int r;
    asm("cvt.rn.bf16x2.f32 %0, %1, %2;" : "=r"(r) : "f"(hi), "f"(lo));
    return r;
}
__device__ __forceinline__ unsigned int smem_u32(const void* p){
    unsigned int a;
    asm("{ .reg .u64 t; cvta.to.shared.u64 t, %1; cvt.u32.u64 %0, t; }" : "=r"(a) : "l"(p));
    return a;
}
__device__ __forceinline__ float tanhfast(float x){
    float r; asm("tanh.approx.f32 %0, %1;" : "=f"(r) : "f"(x)); return r;
}
#define CVT_TF32(o, f) asm("cvt.rna.tf32.f32 %0, %1;" : "=r"(o) : "f"(f))
#define LDSM_X4(R, addr) \
    asm volatile("ldmatrix.sync.aligned.m8n8.x4.shared.b16 {%0,%1,%2,%3}, [%4];" \
        : "=r"((R)[0]),"=r"((R)[1]),"=r"((R)[2]),"=r"((R)[3]) : "r"(addr))
#define MMA16816(D, A, B0, B1) \
    asm volatile("mma.sync.aligned.m16n8k16.row.col.f32.bf16.bf16.f32 " \
        "{%0,%1,%2,%3}, {%4,%5,%6,%7}, {%8,%9}, {%0,%1,%2,%3};" \
        : "+f"((D)[0]),"+f"((D)[1]),"+f"((D)[2]),"+f"((D)[3]) \
        : "r"((A)[0]),"r"((A)[1]),"r"((A)[2]),"r"((A)[3]),"r"(B0),"r"(B1))
#define MMATF32(D, a0,a1,a2,a3, b0,b1) \
    asm volatile("mma.sync.aligned.m16n8k8.row.col.f32.tf32.tf32.f32 " \
        "{%0,%1,%2,%3}, {%4,%5,%6,%7}, {%8,%9}, {%0,%1,%2,%3};" \
        : "+f"((D)[0]),"+f"((D)[1]),"+f"((D)[2]),"+f"((D)[3]) \
        : "r"(a0),"r"(a1),"r"(a2),"r"(a3),"r"(b0),"r"(b1))

// -------- merged prep kernel --------
__global__ void k_prep(const float* __restrict__ h,
                       const float* __restrict__ W_in,
                       const float* __restrict__ W_o1,
                       const float* __restrict__ W_o2,
                       const float* __restrict__ W_xmix)
{
    int bid = blockIdx.x;
    int t = threadIdx.x;
    if (bid < NODES){
        __shared__ float sh[FF];
        int node = bid;
        if (t < FF) sh[t] = h[node*FF + t];
        __syncthreads();
        if (t < FF){
            float p = 0.f, q = 0.f;
            #pragma unroll 8
            for (int k = 0; k < FF; k++){
                float hv = sh[k];
                p = fmaf(hv, W_o1[k*HIDN + t], p);
                q = fmaf(hv, W_o1[(FF+k)*HIDN + t], q);
            }
            g_P[node*HIDN + t] = p;
            g_Q[node*HIDN + t] = q;
            if (t < KF){
                float a = 0.f, bv = 0.f;
                #pragma unroll 8
                for (int k = 0; k < FF; k++){
                    float hv = sh[k];
                    a  = fmaf(hv, W_in[k*KF + t], a);
                    bv = fmaf(hv, W_in[(FF+k)*KF + t], bv);
                }
                g_Ain[node*KF + t] = a;
                g_Bin[node*KF + t] = bv;
            }
        }
    } else if (bid < NODES + 32){
        int idx = (bid - NODES)*256 + t;     // 0..8191
        int lane = idx & 31;
        int kt = (idx >> 5) & 3;
        int hh = (idx >> 7) & 3;
        int w  = (idx >> 9) & 7;
        int half = (idx >> 12) & 1;
        int g = lane >> 2, tig = lane & 3;
        int r0 = (half*8 + w)*16 + g, r1 = r0 + 8;
        int f0 = kt*16 + tig*2;
        int f8 = f0 + 8;
        const float* W = W_xmix;
        uint4 f;
        f.x = pack_bf2(W[(4*f0+hh)*CC + r0],     W[(4*(f0+1)+hh)*CC + r0]);
        f.y = pack_bf2(W[(4*f0+hh)*CC + r1],     W[(4*(f0+1)+hh)*CC + r1]);
        f.z = pack_bf2(W[(4*f8+hh)*CC + r0],     W[(4*(f8+1)+hh)*CC + r0]);
        f.w = pack_bf2(W[(4*f8+hh)*CC + r1],     W[(4*(f8+1)+hh)*CC + r1]);
        g_WtF[idx] = f;
    } else {
        int idx = (bid - NODES - 32)*256 + t;   // 0..4095
        int lane = idx & 31;
        int nt = (idx >> 5) & 7;
        int kt = (idx >> 8) & 7;
        int m  = idx >> 11;
        int g = lane >> 2, tig = lane & 3;
        int k0 = kt*8 + tig, k1 = k0 + 4, n = nt*8 + g;
        float v0, v1;
        if (m == 0){
            v0 = (k0 <= 50) ? W_o1[(128 + k0)*HIDN + n] : 0.f;
            v1 = (k1 <= 50) ? W_o1[(128 + k1)*HIDN + n] : 0.f;
        } else {
            v0 = W_o2[k0*HIDN + n];
            v1 = W_o2[k1*HIDN + n];
        }
        unsigned u0, u1;
        CVT_TF32(u0, v0); CVT_TF32(u1, v1);
        g_Wf[m*2048 + (kt*8 + nt)*32 + lane] = make_uint2(u0, u1);
    }
}

// -------- K2: edge model via tf32 MMA (unchanged) --------
#define K2_OFF_A1   0u
#define K2_OFF_W1   32768u
#define K2_OFF_W2   49152u
#define K2_OFF_P    65536u
#define K2_OFF_Q    69888u
#define K2_OFF_AIN  72064u
#define K2_OFF_BIN  75392u
#define K2_OFF_WS   77056u
#define K2_OFF_BO1  78080u
#define K2_OFF_MEAN 78336u
#define K2_OFF_BETA 78544u
#define K2_OFF_BINV 78752u
#define K2_OFF_XI   78960u
#define K2_OFF_XJ   79088u
#define K2_OFF_BSEM 79344u
#define K2_SMEM     79360u

__global__ __launch_bounds__(256,2) void k2_edge(
    const float* __restrict__ x,
    const float* __restrict__ b_o1, const float* __restrict__ b_in,
    const float* __restrict__ means, const float* __restrict__ betas,
    const float* __restrict__ W_sem, const float* __restrict__ b_sem)
{
    extern __shared__ char smem[];
    int b  = blockIdx.z;
    int i0 = blockIdx.y*8, j0 = blockIdx.x*16;
    int t  = threadIdx.x;

    float* sP   = (float*)(smem + K2_OFF_P);
    float* sQ   = (float*)(smem + K2_OFF_Q);
    float* sAin = (float*)(smem + K2_OFF_AIN);
    float* sBin = (float*)(smem + K2_OFF_BIN);
    float4* sWs = (float4*)(smem + K2_OFF_WS);
    float* sBo1 = (float*)(smem + K2_OFF_BO1);
    float* sMean= (float*)(smem + K2_OFF_MEAN);
    float* sBeta= (float*)(smem + K2_OFF_BETA);
    float* sBinV= (float*)(smem + K2_OFF_BINV);
    float* sXi  = (float*)(smem + K2_OFF_XI);
    float* sXj  = (float*)(smem + K2_OFF_XJ);

    for (int idx = t; idx < 1024; idx += 256){
        ((uint4*)(smem + K2_OFF_W1))[idx] = ((const uint4*)g_Wf)[idx];
        ((uint4*)(smem + K2_OFF_W2))[idx] = ((const uint4*)g_Wf)[1024 + idx];
        sP[(idx >> 6)*68 + (idx & 63)] = g_P[(b*NN + j0 + (idx >> 6))*HIDN + (idx & 63)];
    }
    for (int idx = t; idx < 512; idx += 256)
        sQ[(idx >> 6)*68 + (idx & 63)] = g_Q[(b*NN + i0 + (idx >> 6))*HIDN + (idx & 63)];
    for (int idx = t; idx < 800; idx += 256){
        int r = idx/50, c = idx - r*50;
        sAin[r*52 + c] = g_Ain[(b*NN + j0 + r)*KF + c];
    }
    for (int idx = t; idx < 400; idx += 256){
        int r = idx/50, c = idx - r*50;
        sBin[r*52 + c] = g_Bin[(b*NN + i0 + r)*KF + c];
    }
    if (t < 64){
        sWs[t] = ((const float4*)W_sem)[t];
        sBo1[t] = b_o1[t];
    }
    if (t < 50){ sMean[t] = means[t]; sBeta[t] = betas[t]; sBinV[t] = b_in[t]; }
    if (t < 48){ int r = t/3, c = t - r*3; sXj[r*4 + c] = x[(b*NN + j0 + r)*3 + c]; }
    else if (t < 72){ int u = t - 48; int r = u/3, c = u - r*3; sXi[r*4 + c] = x[(b*NN + i0 + r)*3 + c]; }
    if (t == 0) *(float4*)(smem + K2_OFF_BSEM) = *(const float4*)b_sem;
    {
        uint4 z = make_uint4(0,0,0,0);
        for (int idx = t; idx < 512; idx += 256){
            int mt = idx >> 6, rest = idx & 63;
            ((uint4*)(smem + K2_OFF_A1))[(mt*8 + 6 + (rest >> 5))*32 + (rest & 31)] = z;
        }
    }
    __syncthreads();

    {
        int p = t & 127, bh = t >> 7;
        int il = p >> 4, jl = p & 15;
        float dxv = sXj[jl*4+0] - sXi[il*4+0];
        float dyv = sXj[jl*4+1] - sXi[il*4+1];
        float dzv = sXj[jl*4+2] - sXi[il*4+2];
        float d = sqrtf(dxv*dxv + dyv*dyv + dzv*dzv + 1e-5f);
        float cutv = (d < CUTF) ? 0.5f*(__cosf(d*(PI_F/CUTF)) + 1.0f) : 0.f;
        float em = __expf(-d);
        int gg = jl & 7, regRow = jl >> 3;
        unsigned base1 = (unsigned)(il*8)*512u + (unsigned)(gg*4)*16u + (unsigned)regRow*4u;
        if (bh){
            long pair = ((long)(b*NN + i0 + il))*NN + j0 + jl;
            float inv = 1.0f/(d + 1e-5f);
            g_dx[pair] = make_float4(d, dxv*inv, dyv*inv, dzv*inv);
        }
        int c0 = bh ? 26 : 0, c1 = bh ? 51 : 26;
        for (int c = c0; c < c1; c++){
            float val;
            if (c == 50) val = d;
            else {
                float h1 = sAin[jl*52 + c] + sBin[il*52 + c] + sBinV[c];
                float dm = em - sMean[c];
                val = cutv * __expf(-sBeta[c]*dm*dm) * h1;
            }
            unsigned r32; CVT_TF32(r32, val);
            unsigned addr = K2_OFF_A1 + base1 + (unsigned)((c >> 3))*512u
                          + (unsigned)(c & 3)*16u + (unsigned)((c >> 2) & 1)*8u;
            *(unsigned*)(smem + addr) = r32;
        }
    }
    __syncthreads();

    int lane = t & 31, warp = t >> 5;
    int g2 = lane >> 2, tig = lane & 3;
    const uint4* A1v = (const uint4*)(smem + K2_OFF_A1);
    const uint2* W1v = (const uint2*)(smem + K2_OFF_W1);
    const uint2* W2v = (const uint2*)(smem + K2_OFF_W2);

    float acc1[8][4];
    #pragma unroll
    for (int n = 0; n < 8; n++){ acc1[n][0]=acc1[n][1]=acc1[n][2]=acc1[n][3]=0.f; }
    #pragma unroll
    for (int kt = 0; kt < 8; kt++){
        uint4 aF = A1v[(warp*8 + kt)*32 + lane];
        #pragma unroll
        for (int nt = 0; nt < 8; nt++){
            uint2 bF = W1v[(kt*8 + nt)*32 + lane];
            MMATF32(acc1[nt], aF.x, aF.y, aF.z, aF.w, bF.x, bF.y);
        }
    }
    #pragma unroll
    for (int nt = 0; nt < 8; nt++){
        int f0 = nt*8 + tig*2;
        float q0 = sQ[warp*68 + f0]   + sBo1[f0];
        float q1 = sQ[warp*68 + f0+1] + sBo1[f0+1];
        acc1[nt][0] = silu_fast(acc1[nt][0] + sP[g2*68 + f0]       + q0);
        acc1[nt][1] = silu_fast(acc1[nt][1] + sP[g2*68 + f0+1]     + q1);
        acc1[nt][2] = silu_fast(acc1[nt][2] + sP[(g2+8)*68 + f0]   + q0);
        acc1[nt][3] = silu_fast(acc1[nt][3] + sP[(g2+8)*68 + f0+1] + q1);
    }
    float acc2[8][4];
    #pragma unroll
    for (int n = 0; n < 8; n++){ acc2[n][0]=acc2[n][1]=acc2[n][2]=acc2[n][3]=0.f; }
    int s0 = (lane & ~3) | (tig >> 1);
    int s1 = s0 + 2;
    bool odd = (tig & 1);
    #pragma unroll
    for (int kt = 0; kt < 8; kt++){
        float v0 = __shfl_sync(0xFFFFFFFFu, acc1[kt][0], s0);
        float v1 = __shfl_sync(0xFFFFFFFFu, acc1[kt][1], s0);
        float v2 = __shfl_sync(0xFFFFFFFFu, acc1[kt][2], s0);
        float v3 = __shfl_sync(0xFFFFFFFFu, acc1[kt][3], s0);
        float w0 = __shfl_sync(0xFFFFFFFFu, acc1[kt][0], s1);
        float w1 = __shfl_sync(0xFFFFFFFFu, acc1[kt][1], s1);
        float w2 = __shfl_sync(0xFFFFFFFFu, acc1[kt][2], s1);
        float w3 = __shfl_sync(0xFFFFFFFFu, acc1[kt][3], s1);
        unsigned a0, a1, a2, a3;
        CVT_TF32(a0, odd ? v1 : v0);
        CVT_TF32(a1, odd ? v3 : v2);
        CVT_TF32(a2, odd ? w1 : w0);
        CVT_TF32(a3, odd ? w3 : w2);
        #pragma unroll
        for (int nt = 0; nt < 8; nt++){
            uint2 bF = W2v[(kt*8 + nt)*32 + lane];
            MMATF32(acc2[nt], a0, a1, a2, a3, bF.x, bF.y);
        }
    }
    long rowPair0 = ((long)(b*NN + i0 + warp))*NN + j0 + g2;
    long rowPair1 = rowPair0 + 8;
    float l00=0.f,l01=0.f,l02=0.f,l03=0.f;
    float l10=0.f,l11=0.f,l12=0.f,l13=0.f;
    #pragma unroll
    for (int nt = 0; nt < 8; nt++){
        int f0 = nt*8 + tig*2;
        float h00 = acc2[nt][0], h01 = acc2[nt][1];
        float h10 = acc2[nt][2], h11 = acc2[nt][3];
        g_heb[rowPair0*32 + (f0 >> 1)] = pack_bf2(h00, h01);
        g_heb[rowPair1*32 + (f0 >> 1)] = pack_bf2(h10, h11);
        float4 ws0 = sWs[f0], ws1 = sWs[f0+1];
        l00 = fmaf(h00, ws0.x, fmaf(h01, ws1.x, l00));
        l01 = fmaf(h00, ws0.y, fmaf(h01, ws1.y, l01));
        l02 = fmaf(h00, ws0.z, fmaf(h01, ws1.z, l02));
        l03 = fmaf(h00, ws0.w, fmaf(h01, ws1.w, l03));
        l10 = fmaf(h10, ws0.x, fmaf(h11, ws1.x, l10));
        l11 = fmaf(h10, ws0.y, fmaf(h11, ws1.y, l11));
        l12 = fmaf(h10, ws0.z, fmaf(h11, ws1.z, l12));
        l13 = fmaf(h10, ws0.w, fmaf(h11, ws1.w, l13));
    }
    #define QRED(v) v += __shfl_xor_sync(0xFFFFFFFFu, v, 1); v += __shfl_xor_sync(0xFFFFFFFFu, v, 2);
    QRED(l00) QRED(l01) QRED(l02) QRED(l03)
    QRED(l10) QRED(l11) QRED(l12) QRED(l13)
    #undef QRED
    if (tig == 0){
        float4 bsem = *(float4*)(smem + K2_OFF_BSEM);
        float r0[4] = {l00 + bsem.x, l01 + bsem.y, l02 + bsem.z, l03 + bsem.w};
        float r1[4] = {l10 + bsem.x, l11 + bsem.y, l12 + bsem.z, l13 + bsem.w};
        #pragma unroll
        for (int hh = 0; hh < 4; hh++){
            r0[hh] = (r0[hh] > 0.f) ? r0[hh] : 2.0f*(__expf(0.5f*r0[hh]) - 1.0f);
            r1[hh] = (r1[hh] > 0.f) ? r1[hh] : 2.0f*(__expf(0.5f*r1[hh]) - 1.0f);
        }
        if (i0 + warp == j0 + g2)     { r0[0]-=1e5f; r0[1]-=1e5f; r0[2]-=1e5f; r0[3]-=1e5f; }
        if (i0 + warp == j0 + g2 + 8) { r1[0]-=1e5f; r1[1]-=1e5f; r1[2]-=1e5f; r1[3]-=1e5f; }
        *(float4*)&g_attl[rowPair0*HH] = make_float4(r0[0], r0[1], r0[2], r0[3]);
        *(float4*)&g_attl[rowPair1*HH] = make_float4(r1[0], r1[1], r1[2], r1[3]);
    }
}

// -------- K3: head-hoisted barrier-free HMMA xmix GEMM --------
#define HPITCH 144
#define OFF_A    0u            // A frags (half): 4096 uint4 = 65536
#define OFF_B    65536u        // he: 256*144 = 36864 -> 102400
#define OFF_ATT  102400u       // float4[256] -> 106496
#define OFF_XH   106496u       // float4[256] -> 110592
#define OFF_RED  110592u       // float4[256] -> 114688
#define K3_SMEM  114688u

__global__ __launch_bounds__(256,2) void k3_attn(const float* __restrict__ W_vmix)
{
    extern __shared__ char smem[];
    unsigned int sbase = smem_u32(smem);
    float4* sAtt = (float4*)(smem + OFF_ATT);
    float4* sXh  = (float4*)(smem + OFF_XH);
    float4* sRed = (float4*)(smem + OFF_RED);
    const uint4* sA4 = (const uint4*)(smem + OFF_A);

    int node = blockIdx.x >> 1;
    int half = blockIdx.x & 1;
    int t = threadIdx.x;
    long base = ((long)node)*NN;

    {
        const uint4* src = g_WtF + half*4096;
        uint4* dst = (uint4*)(smem + OFF_A);
        for (int idx = t; idx < 4096; idx += 256) dst[idx] = src[idx];
    }
    {
        for (int idx = t; idx < 2048; idx += 256){
            int row = idx >> 3, ch = idx & 7;
            *(uint4*)(smem + OFF_B + row*HPITCH + ch*16)
                = *(const uint4*)(g_heb + (base + row)*32 + ch*4);
        }
    }

    // ---- softmax over j (per head) ----
    float4 l = *(const float4*)&g_attl[(base + t)*HH];
    sRed[t] = l;
    sXh[t] = g_dx[base + t];
    __syncthreads();
    for (int s = 128; s; s >>= 1){
        if (t < s){
            float4 o2 = sRed[t+s]; float4 m = sRed[t];
            m.x = fmaxf(m.x,o2.x); m.y = fmaxf(m.y,o2.y);
            m.z = fmaxf(m.z,o2.z); m.w = fmaxf(m.w,o2.w);
            sRed[t] = m;
        }
        __syncthreads();
    }
    float4 mx = sRed[0];
    __syncthreads();
    float4 e = make_float4(expf(l.x-mx.x), expf(l.y-mx.y), expf(l.z-mx.z), expf(l.w-mx.w));
    sRed[t] = e;
    __syncthreads();
    for (int s = 128; s; s >>= 1){
        if (t < s){
            float4 o2 = sRed[t+s]; float4 m = sRed[t];
            m.x += o2.x; m.y += o2.y; m.z += o2.z; m.w += o2.w;
            sRed[t] = m;
        }
        __syncthreads();
    }
    float4 sm = sRed[0];
    __syncthreads();
    float4 att = make_float4(e.x/sm.x, e.y/sm.y, e.z/sm.z, e.w/sm.w);
    sAtt[t] = att;
    __syncthreads();

    // ---- he_sum (half-0 CTAs only) ----
    if (half == 0){
        int f = t & 63, q = t >> 6;
        int sh = (f & 1)*16;
        const unsigned int* hb = g_heb + (base + q*64)*32 + (f >> 1);
        float s0=0.f, s1=0.f, s2=0.f, s3=0.f;
        #pragma unroll 4
        for (int jj = 0; jj < 64; jj++){
            unsigned int u = hb[jj*32];
            float hev = __uint_as_float(((u >> sh) & 0xFFFFu) << 16);
            float4 a4 = sAtt[q*64 + jj];
            s0 = fmaf(hev, a4.x, s0); s1 = fmaf(hev, a4.y, s1);
            s2 = fmaf(hev, a4.z, s2); s3 = fmaf(hev, a4.w, s3);
        }
        sRed[t] = make_float4(s0, s1, s2, s3);
    }
    __syncthreads();
    if (half == 0){
        int f = t >> 2, hh2 = t & 3;
        float s = ((const float*)&sRed[f])[hh2]
                + ((const float*)&sRed[64+f])[hh2]
                + ((const float*)&sRed[128+f])[hh2]
                + ((const float*)&sRed[192+f])[hh2];
        g_hesum[node*CC + t] = s;
    }
    __syncthreads();   // smem read-only beyond this point

    int lane = t & 31, warp = t >> 5;
    int g = lane >> 2, tig = lane & 3;
    unsigned int bBase4 = sbase + OFF_B + (unsigned)((lane & 7))*HPITCH
                        + (unsigned)(((lane >> 3) & 1)*16)
                        + (unsigned)(((lane >> 4) & 1)*(8*HPITCH));

    // preload all 16 A fragments into registers (invariant over jb/np)
    uint4 aC[4][4];
    #pragma unroll
    for (int hh = 0; hh < 4; hh++)
        #pragma unroll
        for (int kt = 0; kt < 4; kt++)
            aC[hh][kt] = sA4[(warp*16 + hh*4 + kt)*32 + lane];

    float cs[2][3];
    cs[0][0]=cs[0][1]=cs[0][2]=cs[1][0]=cs[1][1]=cs[1][2]=0.f;

    for (int jb = 0; jb < 4; jb++){
        unsigned int bJB = bBase4 + (unsigned)(jb*64*HPITCH);
        #pragma unroll
        for (int np = 0; np < 4; np++){
            float Gn[4][8];
            #pragma unroll
            for (int hh = 0; hh < 4; hh++)
                #pragma unroll
                for (int q = 0; q < 8; q++) Gn[hh][q] = 0.f;

            #pragma unroll
            for (int kt = 0; kt < 4; kt++){
                unsigned int bfr[4];
                LDSM_X4(bfr, bJB + (unsigned)(np*16*HPITCH + kt*32));
                #pragma unroll
                for (int hh = 0; hh < 4; hh++){
                    MMA16816(Gn[hh],     (unsigned int*)&aC[hh][kt], bfr[0], bfr[1]);
                    MMA16816(Gn[hh] + 4, (unsigned int*)&aC[hh][kt], bfr[2], bfr[3]);
                }
            }
            // fold heads with fp32 att, tanh, cs accumulation
            #pragma unroll
            for (int s = 0; s < 2; s++){
                int j0 = jb*64 + (np*2 + s)*8 + tig*2;
                float4 aA = sAtt[j0], aB = sAtt[j0+1];
                float f0 = fmaf(aA.x, Gn[0][s*4+0], fmaf(aA.y, Gn[1][s*4+0],
                           fmaf(aA.z, Gn[2][s*4+0], aA.w*Gn[3][s*4+0])));
                float f1 = fmaf(aB.x, Gn[0][s*4+1], fmaf(aB.y, Gn[1][s*4+1],
                           fmaf(aB.z, Gn[2][s*4+1], aB.w*Gn[3][s*4+1])));
                float f2 = fmaf(aA.x, Gn[0][s*4+2], fmaf(aA.y, Gn[1][s*4+2],
                           fmaf(aA.z, Gn[2][s*4+2], aA.w*Gn[3][s*4+2])));
                float f3 = fmaf(aB.x, Gn[0][s*4+3], fmaf(aB.y, Gn[1][s*4+3],
                           fmaf(aB.z, Gn[2][s*4+3], aB.w*Gn[3][s*4+3])));
                float t0 = tanhfast(f0);
                float t1 = tanhfast(f1);
                float t2 = tanhfast(f2);
                float t3 = tanhfast(f3);
                float4 x0 = sXh[j0], x1 = sXh[j0+1];
                cs[0][0] = fmaf(t0, x0.y, fmaf(t1, x1.y, cs[0][0]));
                cs[0][1] = fmaf(t0, x0.z, fmaf(t1, x1.z, cs[0][1]));
                cs[0][2] = fmaf(t0, x0.w, fmaf(t1, x1.w, cs[0][2]));
                cs[1][0] = fmaf(t2, x0.y, fmaf(t3, x1.y, cs[1][0]));
                cs[1][1] = fmaf(t2, x0.z, fmaf(t3, x1.z, cs[1][1]));
                cs[1][2] = fmaf(t2, x0.w, fmaf(t3, x1.w, cs[1][2]));
            }
        }
    }

    // reduce cs over the quad
    #pragma unroll
    for (int r = 0; r < 2; r++)
        #pragma unroll
        for (int q = 0; q < 3; q++){
            float v = cs[r][q];
            v += __shfl_xor_sync(0xFFFFFFFFu, v, 1);
            v += __shfl_xor_sync(0xFFFFFFFFu, v, 2);
            cs[r][q] = v;
        }

    const float invn = 1.0f/(float)NN;
    float pd0 = 0.f, pd1 = 0.f, pd2 = 0.f;
    if (tig == 0){
        #pragma unroll
        for (int r = 0; r < 2; r++){
            int cpr = half*128 + warp*16 + r*8 + g;
            float a  = cs[r][0]*invn;
            float b2 = cs[r][1]*invn;
            float c2 = cs[r][2]*invn;
            g_cn[node*CC + cpr] = a*a + b2*b2 + c2*c2;
            float wv = W_vmix[cpr];
            pd0 = fmaf(a, wv, pd0);
            pd1 = fmaf(b2, wv, pd1);
            pd2 = fmaf(c2, wv, pd2);
        }
    }
    __syncthreads();
    sRed[t] = make_float4(pd0, pd1, pd2, 0.f);
    __syncthreads();
    for (int s = 128; s; s >>= 1){
        if (t < s){
            float4 o2 = sRed[t+s]; float4 m2 = sRed[t];
            m2.x += o2.x; m2.y += o2.y; m2.z += o2.z;
            sRed[t] = m2;
        }
        __syncthreads();
    }
    if (t == 0){
        float4 r = sRed[0];
        g_dvp[node*8 + half*4 + 0] = r.x;
        g_dvp[node*8 + half*4 + 1] = r.y;
        g_dvp[node*8 + half*4 + 2] = r.z;
    }
}

// -------- K4: node MLPs + outputs, 2 nodes per CTA --------
__global__ __launch_bounds__(256) void k4_node(
    const float* __restrict__ h, const float* __restrict__ x, const float* __restrict__ v,
    const float* __restrict__ W_p1, const float* __restrict__ b_p1,
    const float* __restrict__ W_p2, const float* __restrict__ b_p2,
    const float* __restrict__ W_n1, const float* __restrict__ b_n1,
    const float* __restrict__ W_n2, const float* __restrict__ b_n2,
    const float* __restrict__ W_v1, const float* __restrict__ b_v1,
    const float* __restrict__ W_v2, float* __restrict__ out)
{
    int node0 = blockIdx.x*2;
    int node1 = node0 + 1;
    int t = threadIdx.x;
    int to = t & 63, ko = t >> 6;
    __shared__ float sIn[2][384];
    __shared__ float sCn[2][CC];
    __shared__ float sAcc[2][256];
    __shared__ float sX[2][HIDN], sY[2][HIDN];
    __shared__ float sFin[2];

    if (t < 64){ sIn[0][t] = h[node0*FF + t]; sIn[1][t] = h[node1*FF + t]; }
    for (int k = t; k < CC; k += 256){
        sIn[0][64 + k] = g_hesum[node0*CC + k];
        sCn[0][k] = g_cn[node0*CC + k];
        sIn[1][64 + k] = g_hesum[node1*CC + k];
        sCn[1][k] = g_cn[node1*CC + k];
    }
    __syncthreads();

    // p1: 256 -> 64
    {
        float a0 = 0.f, a1 = 0.f;
        int k0 = ko*64;
        #pragma unroll 8
        for (int k = 0; k < 64; k++){
            float w = W_p1[(k0+k)*HIDN + to];
            a0 = fmaf(sCn[0][k0+k], w, a0);
            a1 = fmaf(sCn[1][k0+k], w, a1);
        }
        sAcc[0][t] = a0; sAcc[1][t] = a1;
    }
    __syncthreads();
    if (ko == 0){
        sX[0][to] = siluf(b_p1[to] + sAcc[0][to] + sAcc[0][64+to] + sAcc[0][128+to] + sAcc[0][192+to]);
        sX[1][to] = siluf(b_p1[to] + sAcc[1][to] + sAcc[1][64+to] + sAcc[1][128+to] + sAcc[1][192+to]);
    }
    __syncthreads();
    // p2: 64 -> 64
    {
        float a0 = 0.f, a1 = 0.f;
        int k0 = ko*16;
        #pragma unroll
        for (int k = 0; k < 16; k++){
            float w = W_p2[(k0+k)*HIDN + to];
            a0 = fmaf(sX[0][k0+k], w, a0);
            a1 = fmaf(sX[1][k0+k], w, a1);
        }
        sAcc[0][t] = a0; sAcc[1][t] = a1;
    }
    __syncthreads();
    if (ko == 0){
        sIn[0][320 + to] = siluf(b_p2[to] + sAcc[0][to] + sAcc[0][64+to] + sAcc[0][128+to] + sAcc[0][192+to]);
        sIn[1][320 + to] = siluf(b_p2[to] + sAcc[1][to] + sAcc[1][64+to] + sAcc[1][128+to] + sAcc[1][192+to]);
    }
    __syncthreads();
    // n1: 384 -> 64
    {
        float a0 = 0.f, a1 = 0.f;
        int k0 = ko*96;
        #pragma unroll 8
        for (int k = 0; k < 96; k++){
            float w = W_n1[(k0+k)*HIDN + to];
            a0 = fmaf(sIn[0][k0+k], w, a0);
            a1 = fmaf(sIn[1][k0+k], w, a1);
        }
        sAcc[0][t] = a0; sAcc[1][t] = a1;
    }
    __syncthreads();
    if (ko == 0){
        sX[0][to] = siluf(b_n1[to] + sAcc[0][to] + sAcc[0][64+to] + sAcc[0][128+to] + sAcc[0][192+to]);
        sX[1][to] = siluf(b_n1[to] + sAcc[1][to] + sAcc[1][64+to] + sAcc[1][128+to] + sAcc[1][192+to]);
    }
    __syncthreads();
    // n2: 64 -> 64, residual
    {
        float a0 = 0.f, a1 = 0.f;
        int k0 = ko*16;
        #pragma unroll
        for (int k = 0; k < 16; k++){
            float w = W_n2[(k0+k)*HIDN + to];
            a0 = fmaf(sX[0][k0+k], w, a0);
            a1 = fmaf(sX[1][k0+k], w, a1);
        }
        sAcc[0][t] = a0; sAcc[1][t] = a1;
    }
    __syncthreads();
    if (ko == 0){
        float hn0 = sIn[0][to] + siluf(b_n2[to] + sAcc[0][to] + sAcc[0][64+to] + sAcc[0][128+to] + sAcc[0][192+to]);
        float hn1 = sIn[1][to] + siluf(b_n2[to] + sAcc[1][to] + sAcc[1][64+to] + sAcc[1][128+to] + sAcc[1][192+to]);
        sY[0][to] = hn0; sY[1][to] = hn1;
        out[node0*FF + to] = hn0;
        out[node1*FF + to] = hn1;
    }
    __syncthreads();
    // v1: 64 -> 64
    {
        float a0 = 0.f, a1 = 0.f;
        int k0 = ko*16;
        #pragma unroll
        for (int k = 0; k < 16; k++){
            float w = W_v1[(k0+k)*HIDN + to];
            a0 = fmaf(sY[0][k0+k], w, a0);
            a1 = fmaf(sY[1][k0+k], w, a1);
        }
        sAcc[0][t] = a0; sAcc[1][t] = a1;
    }
    __syncthreads();
    if (ko == 0){
        float w2 = W_v2[to];
        sX[0][to] = siluf(b_v1[to] + sAcc[0][to] + sAcc[0][64+to] + sAcc[0][128+to] + sAcc[0][192+to]) * w2;
        sX[1][to] = siluf(b_v1[to] + sAcc[1][to] + sAcc[1][64+to] + sAcc[1][128+to] + sAcc[1][192+to]) * w2;
    }
    __syncthreads();
    if (t < 64){
        int n = t >> 5, l = t & 31;
        float s = sX[n][l] + sX[n][l+32];
        #pragma unroll
        for (int o2 = 16; o2; o2 >>= 1)
            s += __shfl_xor_sync(0xFFFFFFFFu, s, o2);
        if (l == 0) sFin[n] = s;
    }
    __syncthreads();
    if (t < 3){
        float vs = 2.0f/(1.0f + expf(-sFin[0]));
        float vn = g_dvp[node0*8 + t] + g_dvp[node0*8 + 4 + t] + vs * v[node0*3 + t];
        out[NODES*FF + node0*3 + t]            = x[node0*3 + t] + vn;
        out[NODES*FF + NODES*3 + node0*3 + t]  = vn;
    } else if (t >= 16 && t < 19){
        int q = t - 16;
        float vs = 2.0f/(1.0f + expf(-sFin[1]));
        float vn = g_dvp[node1*8 + q] + g_dvp[node1*8 + 4 + q] + vs * v[node1*3 + q];
        out[NODES*FF + node1*3 + q]            = x[node1*3 + q] + vn;
        out[NODES*FF + NODES*3 + node1*3 + q]  = vn;
    }
}

extern "C" void kernel_launch(void* const* d_in, const int* in_sizes, int n_in,
                              void* d_out, int out_size)
{
    const float* h      = (const float*)d_in[0];
    const float* x      = (const float*)d_in[1];
    const float* v      = (const float*)d_in[2];
    const float* W_in   = (const float*)d_in[3];
    const float* b_in   = (const float*)d_in[4];
    const float* means  = (const float*)d_in[5];
    const float* betas  = (const float*)d_in[6];
    const float* W_o1   = (const float*)d_in[7];
    const float* b_o1   = (const float*)d_in[8];
    const float* W_o2   = (const float*)d_in[9];
    const float* b_o2   = (const float*)d_in[10];
    const float* W_sem  = (const float*)d_in[11];
    const float* b_sem  = (const float*)d_in[12];
    const float* W_xmix = (const float*)d_in[13];
    const float* W_p1   = (const float*)d_in[14];
    const float* b_p1   = (const float*)d_in[15];
    const float* W_p2   = (const float*)d_in[16];
    const float* b_p2   = (const float*)d_in[17];
    const float* W_n1   = (const float*)d_in[18];
    const float* b_n1   = (const float*)d_in[19];
    const float* W_n2   = (const float*)d_in[20];
    const float* b_n2   = (const float*)d_in[21];
    const float* W_v1   = (const float*)d_in[22];
    const float* b_v1   = (const float*)d_in[23];
    const float* W_v2   = (const float*)d_in[24];
    const float* W_vmix = (const float*)d_in[25];
    float* out = (float*)d_out;

    static int smem_set = 0;
    if (!smem_set){
        cudaFuncSetAttribute(k3_attn, cudaFuncAttributeMaxDynamicSharedMemorySize, K3_SMEM);
        cudaFuncSetAttribute(k2_edge, cudaFuncAttributeMaxDynamicSharedMemorySize, K2_SMEM);
        smem_set = 1;
    }

    k_prep<<<NODES + 48, 256>>>(h, W_in, W_o1, W_o2, W_xmix);
    dim3 g2(NN/16, NN/8, BB);
    k2_edge<<<g2, 256, K2_SMEM>>>(x, b_o1, b_in, means, betas, W_sem, b_sem);
    k3_attn<<<NODES*2, 256, K3_SMEM>>>(W_vmix);
    k4_node<<<NODES/2, 256>>>(h, x, v, W_p1, b_p1, W_p2, b_p2,
                              W_n1, b_n1, W_n2, b_n2, W_v1, b_v1, W_v2, out);
}